// round 1
// baseline (speedup 1.0000x reference)
#include <cuda_runtime.h>
#include <cuda_bf16.h>
#include <math.h>

#define S_TOT 3900
#define DIM   1536
#define NH    12
#define HD    128
#define CC    64          // HD/2 complex pairs per head

// ---------------- scratch (no allocation allowed) ----------------
__device__ float g_q [S_TOT * DIM];
__device__ float g_k [S_TOT * DIM];
__device__ float g_v [S_TOT * DIM];
__device__ float g_ao[S_TOT * DIM];

// ---------------- tiled fp32 GEMM: C = A[MxK] * B[KxN] + bias ----------------
#define TBM 64
#define TBN 64
#define TBK 16

__global__ __launch_bounds__(256)
void gemm_bias_kernel(const float* __restrict__ A, const float* __restrict__ B,
                      const float* __restrict__ bias, float* __restrict__ C,
                      int M, int N, int K) {
    __shared__ float As[TBM][TBK + 1];
    __shared__ float Bs[TBK][TBN + 1];

    const int tx = threadIdx.x & 15;
    const int ty = threadIdx.x >> 4;
    const int row0 = blockIdx.y * TBM;
    const int col0 = blockIdx.x * TBN;

    float acc[4][4] = {};

    for (int k0 = 0; k0 < K; k0 += TBK) {
        // load A tile (64x16)
        for (int i = threadIdx.x; i < TBM * TBK; i += 256) {
            int r = i / TBK, c = i % TBK;
            int gr = row0 + r;
            As[r][c] = (gr < M) ? A[(size_t)gr * K + k0 + c] : 0.f;
        }
        // load B tile (16x64); N,K are multiples of tile dims
        for (int i = threadIdx.x; i < TBK * TBN; i += 256) {
            int r = i / TBN, c = i % TBN;
            Bs[r][c] = B[(size_t)(k0 + r) * N + col0 + c];
        }
        __syncthreads();

        #pragma unroll
        for (int kk = 0; kk < TBK; kk++) {
            float a[4], b[4];
            #pragma unroll
            for (int i = 0; i < 4; i++) a[i] = As[ty * 4 + i][kk];
            #pragma unroll
            for (int j = 0; j < 4; j++) b[j] = Bs[kk][tx * 4 + j];
            #pragma unroll
            for (int i = 0; i < 4; i++)
                #pragma unroll
                for (int j = 0; j < 4; j++)
                    acc[i][j] = fmaf(a[i], b[j], acc[i][j]);
        }
        __syncthreads();
    }

    #pragma unroll
    for (int i = 0; i < 4; i++) {
        int gr = row0 + ty * 4 + i;
        if (gr < M) {
            #pragma unroll
            for (int j = 0; j < 4; j++) {
                int gc = col0 + tx * 4 + j;
                C[(size_t)gr * N + gc] = acc[i][j] + bias[gc];
            }
        }
    }
}

// ---------------- fused RMSNorm (over full DIM row) + 3D RoPE ----------------
__global__ __launch_bounds__(256)
void rmsnorm_rope_kernel(float* __restrict__ t, const float* __restrict__ g,
                         const float* __restrict__ freqs,
                         const int* __restrict__ grid_sizes) {
    const int s = blockIdx.x;
    const int tid = threadIdx.x;
    float* row = t + (size_t)s * DIM;

    // sum of squares over 1536
    float ss = 0.f;
    for (int i = tid; i < DIM; i += 256) {
        float v = row[i];
        ss += v * v;
    }
    #pragma unroll
    for (int off = 16; off; off >>= 1) ss += __shfl_xor_sync(0xffffffffu, ss, off);

    __shared__ float red[8];
    if ((tid & 31) == 0) red[tid >> 5] = ss;
    __syncthreads();
    if (tid == 0) {
        float tot = 0.f;
        #pragma unroll
        for (int i = 0; i < 8; i++) tot += red[i];
        red[0] = tot;
    }
    __syncthreads();
    const float inv = rsqrtf(red[0] * (1.f / DIM) + 1e-6f);

    // position decomposition
    const int F = grid_sizes[0], H = grid_sizes[1], W = grid_sizes[2];
    (void)F;
    const int fi = s / (H * W);
    const int rem = s % (H * W);
    const int hi = rem / W;
    const int wi = rem % W;

    const int c3 = CC / 3;          // 21
    const int c0 = CC - 2 * c3;     // 22

    // 768 complex pairs
    for (int p = tid; p < NH * CC; p += 256) {
        int j = p % CC;             // freq column (global)
        int head = p / CC;
        int idx = head * HD + 2 * j;
        float a = row[idx]     * inv * g[idx];
        float b = row[idx + 1] * inv * g[idx + 1];
        int pos = (j < c0) ? fi : ((j < c0 + c3) ? hi : wi);
        float cs = freqs[(pos * CC + j) * 2 + 0];
        float sn = freqs[(pos * CC + j) * 2 + 1];
        row[idx]     = a * cs - b * sn;
        row[idx + 1] = a * sn + b * cs;
    }
}

// ---------------- flash-style attention, fp32, online softmax ----------------
#define BQ  64
#define BKV 64
#define QK_STRIDE 132     // 128 + 4 pad, keeps float4 alignment
#define V_STRIDE  128
#define SC_STRIDE 65

// smem float offsets
#define OFF_Q  0
#define OFF_K  (BQ * QK_STRIDE)                 // 8448
#define OFF_V  (OFF_K + BKV * QK_STRIDE)        // 16896
#define OFF_S  (OFF_V + BKV * V_STRIDE)         // 25088
#define OFF_M  (OFF_S + BQ * SC_STRIDE)         // 29248
#define OFF_L  (OFF_M + BQ)                     // 29312
#define OFF_A  (OFF_L + BQ)                     // 29376
#define FLASH_SMEM_FLOATS (OFF_A + BQ)          // 29440
#define FLASH_SMEM_BYTES  (FLASH_SMEM_FLOATS * 4)

__global__ __launch_bounds__(256)
void flash_kernel(const float* __restrict__ Q, const float* __restrict__ K,
                  const float* __restrict__ V, float* __restrict__ O,
                  const int* __restrict__ seq_lens) {
    extern __shared__ float sm[];
    float* Qs = sm + OFF_Q;
    float* Ks = sm + OFF_K;
    float* Vs = sm + OFF_V;
    float* Sc = sm + OFF_S;
    float* rm = sm + OFF_M;
    float* rl = sm + OFF_L;
    float* ra = sm + OFF_A;

    const int h  = blockIdx.y;
    const int q0 = blockIdx.x * BQ;
    const int tid = threadIdx.x;
    const int seqlen = seq_lens[0];

    // load Q tile [64 x 128] (float4)
    for (int i = tid; i < BQ * (HD / 4); i += 256) {
        int r = i >> 5;
        int c = (i & 31) * 4;
        int qr = q0 + r;
        float4 val = make_float4(0.f, 0.f, 0.f, 0.f);
        if (qr < S_TOT)
            val = *(const float4*)(Q + (size_t)qr * DIM + h * HD + c);
        *(float4*)&Qs[r * QK_STRIDE + c] = val;
    }
    if (tid < BQ) { rm[tid] = -1e30f; rl[tid] = 0.f; }

    float o[32];
    #pragma unroll
    for (int i = 0; i < 32; i++) o[i] = 0.f;

    const int tx = tid & 15, ty = tid >> 4;        // for QK^T microtiles
    const int prow = tid >> 2, pg = tid & 3;       // for PV: row, 32-col group
    const float scale = 0.08838834764831845f;      // 1/sqrt(128)

    for (int k0 = 0; k0 < S_TOT; k0 += BKV) {
        __syncthreads();   // protect Ks/Vs/Sc from previous iteration's consumers

        // load K,V tiles (float4)
        for (int i = tid; i < BKV * (HD / 4); i += 256) {
            int r = i >> 5;
            int c = (i & 31) * 4;
            int kr = k0 + r;
            float4 kv = make_float4(0.f, 0.f, 0.f, 0.f);
            float4 vv = make_float4(0.f, 0.f, 0.f, 0.f);
            if (kr < S_TOT) {
                kv = *(const float4*)(K + (size_t)kr * DIM + h * HD + c);
                vv = *(const float4*)(V + (size_t)kr * DIM + h * HD + c);
            }
            *(float4*)&Ks[r * QK_STRIDE + c] = kv;
            *(float4*)&Vs[r * V_STRIDE + c]  = vv;
        }
        __syncthreads();

        // S = Q K^T (each thread: 4x4 of the 64x64 tile)
        float acc[4][4] = {};
        #pragma unroll 8
        for (int d = 0; d < HD; d += 4) {
            float4 a[4], b[4];
            #pragma unroll
            for (int i = 0; i < 4; i++) a[i] = *(float4*)&Qs[(ty * 4 + i) * QK_STRIDE + d];
            #pragma unroll
            for (int j = 0; j < 4; j++) b[j] = *(float4*)&Ks[(tx * 4 + j) * QK_STRIDE + d];
            #pragma unroll
            for (int i = 0; i < 4; i++)
                #pragma unroll
                for (int j = 0; j < 4; j++) {
                    acc[i][j] = fmaf(a[i].x, b[j].x, acc[i][j]);
                    acc[i][j] = fmaf(a[i].y, b[j].y, acc[i][j]);
                    acc[i][j] = fmaf(a[i].z, b[j].z, acc[i][j]);
                    acc[i][j] = fmaf(a[i].w, b[j].w, acc[i][j]);
                }
        }
        #pragma unroll
        for (int i = 0; i < 4; i++)
            #pragma unroll
            for (int j = 0; j < 4; j++) {
                int kc = k0 + tx * 4 + j;
                Sc[(ty * 4 + i) * SC_STRIDE + tx * 4 + j] =
                    (kc < seqlen) ? acc[i][j] * scale : -1e30f;
            }
        __syncthreads();

        // online softmax (one thread per query row)
        if (tid < BQ) {
            float mold = rm[tid];
            float mnew = mold;
            float* srow = Sc + tid * SC_STRIDE;
            #pragma unroll 8
            for (int j = 0; j < BKV; j++) mnew = fmaxf(mnew, srow[j]);
            float alpha = __expf(mold - mnew);
            float lsum = 0.f;
            #pragma unroll 8
            for (int j = 0; j < BKV; j++) {
                float pexp = __expf(srow[j] - mnew);
                srow[j] = pexp;
                lsum += pexp;
            }
            rm[tid] = mnew;
            rl[tid] = rl[tid] * alpha + lsum;
            ra[tid] = alpha;
        }
        __syncthreads();

        // O = O*alpha + P @ V   (thread owns row prow, cols [pg*32, pg*32+32))
        float alpha = ra[prow];
        #pragma unroll
        for (int j = 0; j < 32; j++) o[j] *= alpha;
        for (int kk = 0; kk < BKV; kk++) {
            float pval = Sc[prow * SC_STRIDE + kk];
            const float* vr = &Vs[kk * V_STRIDE + pg * 32];
            #pragma unroll
            for (int j4 = 0; j4 < 8; j4++) {
                float4 vv = *(const float4*)(vr + j4 * 4);
                o[j4 * 4 + 0] = fmaf(pval, vv.x, o[j4 * 4 + 0]);
                o[j4 * 4 + 1] = fmaf(pval, vv.y, o[j4 * 4 + 1]);
                o[j4 * 4 + 2] = fmaf(pval, vv.z, o[j4 * 4 + 2]);
                o[j4 * 4 + 3] = fmaf(pval, vv.w, o[j4 * 4 + 3]);
            }
        }
    }

    // write normalized output
    int qr = q0 + prow;
    if (qr < S_TOT) {
        float invl = 1.f / rl[prow];
        float* dst = O + (size_t)qr * DIM + h * HD + pg * 32;
        #pragma unroll
        for (int j4 = 0; j4 < 8; j4++) {
            float4 val = make_float4(o[j4 * 4 + 0] * invl, o[j4 * 4 + 1] * invl,
                                     o[j4 * 4 + 2] * invl, o[j4 * 4 + 3] * invl);
            *(float4*)(dst + j4 * 4) = val;
        }
    }
}

// ---------------- launch ----------------
extern "C" void kernel_launch(void* const* d_in, const int* in_sizes, int n_in,
                              void* d_out, int out_size) {
    const float* x         = (const float*)d_in[0];
    const int*   seq_lens  = (const int*)  d_in[1];
    const int*   grid_sz   = (const int*)  d_in[2];
    const float* freqs     = (const float*)d_in[3];
    const float* Wq        = (const float*)d_in[4];
    const float* bq        = (const float*)d_in[5];
    const float* Wk        = (const float*)d_in[6];
    const float* bk        = (const float*)d_in[7];
    const float* Wv        = (const float*)d_in[8];
    const float* bv        = (const float*)d_in[9];
    const float* Wo        = (const float*)d_in[10];
    const float* bo        = (const float*)d_in[11];
    const float* gq        = (const float*)d_in[12];
    const float* gk        = (const float*)d_in[13];
    float* out = (float*)d_out;

    float *q, *k, *v, *ao;
    cudaGetSymbolAddress((void**)&q,  g_q);
    cudaGetSymbolAddress((void**)&k,  g_k);
    cudaGetSymbolAddress((void**)&v,  g_v);
    cudaGetSymbolAddress((void**)&ao, g_ao);

    dim3 gb(DIM / TBN, (S_TOT + TBM - 1) / TBM);   // (24, 61)

    gemm_bias_kernel<<<gb, 256>>>(x, Wq, bq, q, S_TOT, DIM, DIM);
    gemm_bias_kernel<<<gb, 256>>>(x, Wk, bk, k, S_TOT, DIM, DIM);
    gemm_bias_kernel<<<gb, 256>>>(x, Wv, bv, v, S_TOT, DIM, DIM);

    rmsnorm_rope_kernel<<<S_TOT, 256>>>(q, gq, freqs, grid_sz);
    rmsnorm_rope_kernel<<<S_TOT, 256>>>(k, gk, freqs, grid_sz);

    cudaFuncSetAttribute(flash_kernel, cudaFuncAttributeMaxDynamicSharedMemorySize,
                         FLASH_SMEM_BYTES);
    dim3 ga((S_TOT + BQ - 1) / BQ, NH);            // (61, 12)
    flash_kernel<<<ga, 256, FLASH_SMEM_BYTES>>>(q, k, v, ao, seq_lens);

    gemm_bias_kernel<<<gb, 256>>>(ao, Wo, bo, out, S_TOT, DIM, DIM);
}

// round 2
// speedup vs baseline: 6.0615x; 6.0615x over previous
#include <cuda_runtime.h>
#include <cuda_bf16.h>
#include <math.h>

#define S_TOT 3900
#define DIM   1536
#define NH    12
#define HD    128
#define CC    64

// ---------------- scratch ----------------
__device__ float g_q [S_TOT * DIM];
__device__ float g_k [S_TOT * DIM];
__device__ float g_v [S_TOT * DIM];
__device__ float g_ao[S_TOT * DIM];

// ---------------- f32x2 helpers ----------------
typedef unsigned long long u64t;

__device__ __forceinline__ void ffma2(u64t& c, u64t a, u64t b) {
    asm("fma.rn.f32x2 %0, %1, %2, %3;" : "=l"(c) : "l"(a), "l"(b), "l"(c));
}
__device__ __forceinline__ u64t dup2(float x) {
    u64t d;
    asm("mov.b64 %0, {%1, %1};" : "=l"(d) : "r"(__float_as_uint(x)));
    return d;
}
__device__ __forceinline__ u64t mul2(u64t a, u64t b) {
    u64t r;
    asm("mul.rn.f32x2 %0, %1, %2;" : "=l"(r) : "l"(a), "l"(b));
    return r;
}
__device__ __forceinline__ void unpack2(u64t v, float& lo, float& hi) {
    asm("mov.b64 {%0, %1}, %2;" : "=f"(lo), "=f"(hi) : "l"(v));
}

// ================= SGEMM: C[M x 1536] = A[M x 1536] * B + bias =================
#define GK 1536
#define GN 1536

__global__ __launch_bounds__(256)
void sgemm128(const float* __restrict__ A, const float* __restrict__ B,
              const float* __restrict__ bias, float* __restrict__ C, int M) {
    __shared__ float As[2][8][128];   // As[kk][m] (transposed)
    __shared__ float Bs[2][8][128];   // Bs[kk][n]

    const int t = threadIdx.x;
    const int m_ld  = t & 127;           // lane spans m -> conflict-free transpose STS
    const int k4_ld = (t >> 7) << 2;     // 0 or 4
    const int brow  = t >> 5;            // 0..7
    const int bcol4 = (t & 31) << 2;
    const int row0 = blockIdx.y * 128;
    const int col0 = blockIdx.x * 128;
    const int ty4 = (t >> 4) << 2;       // rows ty4..+3 and 64+ty4..+3
    const int tx4 = (t & 15) << 2;       // cols tx4..+3 and 64+tx4..+3

    float4 aR, bR;
    {
        int gr = row0 + m_ld;
        aR = (gr < M) ? *(const float4*)&A[(size_t)gr * GK + k4_ld]
                      : make_float4(0.f, 0.f, 0.f, 0.f);
        bR = *(const float4*)&B[(size_t)brow * GN + col0 + bcol4];
    }
    As[0][k4_ld + 0][m_ld] = aR.x;
    As[0][k4_ld + 1][m_ld] = aR.y;
    As[0][k4_ld + 2][m_ld] = aR.z;
    As[0][k4_ld + 3][m_ld] = aR.w;
    *(float4*)&Bs[0][brow][bcol4] = bR;
    __syncthreads();

    u64t acc[8][4];
    #pragma unroll
    for (int i = 0; i < 8; i++)
        #pragma unroll
        for (int j = 0; j < 4; j++) acc[i][j] = 0ull;

    int buf = 0;
    for (int kt = 1; kt <= GK / 8; kt++) {
        if (kt < GK / 8) {
            int k0 = kt * 8;
            int gr = row0 + m_ld;
            aR = (gr < M) ? *(const float4*)&A[(size_t)gr * GK + k0 + k4_ld]
                          : make_float4(0.f, 0.f, 0.f, 0.f);
            bR = *(const float4*)&B[(size_t)(k0 + brow) * GN + col0 + bcol4];
        }
        #pragma unroll
        for (int kk = 0; kk < 8; kk++) {
            float4 a0 = *(const float4*)&As[buf][kk][ty4];
            float4 a1 = *(const float4*)&As[buf][kk][64 + ty4];
            ulonglong2 b0 = *(const ulonglong2*)&Bs[buf][kk][tx4];
            ulonglong2 b1 = *(const ulonglong2*)&Bs[buf][kk][64 + tx4];
            u64t ad[8];
            ad[0] = dup2(a0.x); ad[1] = dup2(a0.y); ad[2] = dup2(a0.z); ad[3] = dup2(a0.w);
            ad[4] = dup2(a1.x); ad[5] = dup2(a1.y); ad[6] = dup2(a1.z); ad[7] = dup2(a1.w);
            #pragma unroll
            for (int i = 0; i < 8; i++) {
                ffma2(acc[i][0], ad[i], b0.x);
                ffma2(acc[i][1], ad[i], b0.y);
                ffma2(acc[i][2], ad[i], b1.x);
                ffma2(acc[i][3], ad[i], b1.y);
            }
        }
        if (kt < GK / 8) {
            int nb = buf ^ 1;
            As[nb][k4_ld + 0][m_ld] = aR.x;
            As[nb][k4_ld + 1][m_ld] = aR.y;
            As[nb][k4_ld + 2][m_ld] = aR.z;
            As[nb][k4_ld + 3][m_ld] = aR.w;
            *(float4*)&Bs[nb][brow][bcol4] = bR;
            __syncthreads();
            buf = nb;
        }
    }

    // epilogue
    #pragma unroll
    for (int i = 0; i < 8; i++) {
        int gr = row0 + ((i < 4) ? (ty4 + i) : (64 + ty4 + i - 4));
        if (gr >= M) continue;
        float c[8];
        unpack2(acc[i][0], c[0], c[1]);
        unpack2(acc[i][1], c[2], c[3]);
        unpack2(acc[i][2], c[4], c[5]);
        unpack2(acc[i][3], c[6], c[7]);
        int gc0 = col0 + tx4;
        float4 o0 = make_float4(c[0] + bias[gc0 + 0], c[1] + bias[gc0 + 1],
                                c[2] + bias[gc0 + 2], c[3] + bias[gc0 + 3]);
        int gc1 = col0 + 64 + tx4;
        float4 o1 = make_float4(c[4] + bias[gc1 + 0], c[5] + bias[gc1 + 1],
                                c[6] + bias[gc1 + 2], c[7] + bias[gc1 + 3]);
        *(float4*)&C[(size_t)gr * GN + gc0] = o0;
        *(float4*)&C[(size_t)gr * GN + gc1] = o1;
    }
}

// ---------------- RMSNorm + 3D RoPE (unchanged) ----------------
__global__ __launch_bounds__(256)
void rmsnorm_rope_kernel(float* __restrict__ t, const float* __restrict__ g,
                         const float* __restrict__ freqs,
                         const int* __restrict__ grid_sizes) {
    const int s = blockIdx.x;
    const int tid = threadIdx.x;
    float* row = t + (size_t)s * DIM;

    float ss = 0.f;
    for (int i = tid; i < DIM; i += 256) { float v = row[i]; ss += v * v; }
    #pragma unroll
    for (int off = 16; off; off >>= 1) ss += __shfl_xor_sync(0xffffffffu, ss, off);

    __shared__ float red[8];
    if ((tid & 31) == 0) red[tid >> 5] = ss;
    __syncthreads();
    if (tid == 0) {
        float tot = 0.f;
        #pragma unroll
        for (int i = 0; i < 8; i++) tot += red[i];
        red[0] = tot;
    }
    __syncthreads();
    const float inv = rsqrtf(red[0] * (1.f / DIM) + 1e-6f);

    const int H = grid_sizes[1], W = grid_sizes[2];
    const int fi = s / (H * W);
    const int rem = s % (H * W);
    const int hi = rem / W;
    const int wi = rem % W;

    const int c3 = CC / 3;
    const int c0 = CC - 2 * c3;

    for (int p = tid; p < NH * CC; p += 256) {
        int j = p % CC;
        int head = p / CC;
        int idx = head * HD + 2 * j;
        float a = row[idx]     * inv * g[idx];
        float b = row[idx + 1] * inv * g[idx + 1];
        int pos = (j < c0) ? fi : ((j < c0 + c3) ? hi : wi);
        float cs = freqs[(pos * CC + j) * 2 + 0];
        float sn = freqs[(pos * CC + j) * 2 + 1];
        row[idx]     = a * cs - b * sn;
        row[idx + 1] = a * sn + b * cs;
    }
}

// ================= flash attention: 128q x 64k tiles, 512 threads =================
#define BQ 128
#define BK 64
#define QS_STR 132   // Qs[d][q], d=128 rows
#define KS_STR 68    // Ks[d][k]
#define VS_STR 128   // Vs[k][d]
#define PS_STR 132   // Ps[k][q]

#define OFF_Q 0
#define OFF_K (OFF_Q + HD * QS_STR)          // 16896
#define OFF_V (OFF_K + HD * KS_STR)          // 25600
#define OFF_P (OFF_V + BK * VS_STR)          // 33792
#define FL_SMEM_FLOATS (OFF_P + BK * PS_STR) // 42240
#define FL_SMEM_BYTES (FL_SMEM_FLOATS * 4)   // 168960

__global__ __launch_bounds__(512, 1)
void flash_kernel(const float* __restrict__ Q, const float* __restrict__ K,
                  const float* __restrict__ V, float* __restrict__ O,
                  const int* __restrict__ seq_lens) {
    extern __shared__ float sm[];
    float* Qs = sm + OFF_Q;
    float* Ks = sm + OFF_K;
    float* Vs = sm + OFF_V;
    float* Ps = sm + OFF_P;

    const int h   = blockIdx.y;
    const int q0  = blockIdx.x * BQ;
    const int tid = threadIdx.x;
    const int tx  = tid & 15;   // cols
    const int ty  = tid >> 4;   // 0..31, rows ty*4..+3
    const int seqlen = seq_lens[0];
    const float scale = 0.08838834764831845f;   // 1/sqrt(128)

    // load Q tile [128q x 128d] transposed -> Qs[d][q]; lanes span q (conflict-free STS)
    #pragma unroll
    for (int i = 0; i < 8; i++) {
        int chunk = tid + i * 512;            // 0..4095
        int q  = chunk & 127;
        int d4 = (chunk >> 7) << 2;
        float4 v = make_float4(0.f, 0.f, 0.f, 0.f);
        if (q0 + q < S_TOT)
            v = *(const float4*)&Q[(size_t)(q0 + q) * DIM + h * HD + d4];
        Qs[(d4 + 0) * QS_STR + q] = v.x;
        Qs[(d4 + 1) * QS_STR + q] = v.y;
        Qs[(d4 + 2) * QS_STR + q] = v.z;
        Qs[(d4 + 3) * QS_STR + q] = v.w;
    }

    float m_i[4], l_i[4];
    #pragma unroll
    for (int i = 0; i < 4; i++) { m_i[i] = -1e30f; l_i[i] = 0.f; }
    u64t o2[4][4];
    #pragma unroll
    for (int i = 0; i < 4; i++)
        #pragma unroll
        for (int j = 0; j < 4; j++) o2[i][j] = 0ull;

    for (int k0 = 0; k0 < S_TOT; k0 += BK) {
        __syncthreads();
        // K tile [64k x 128d] transposed -> Ks[d][k]; lanes span k
        #pragma unroll
        for (int i = 0; i < 4; i++) {
            int chunk = tid + i * 512;        // 0..2047
            int k  = chunk & 63;
            int d4 = (chunk >> 6) << 2;
            float4 v = make_float4(0.f, 0.f, 0.f, 0.f);
            if (k0 + k < S_TOT)
                v = *(const float4*)&K[(size_t)(k0 + k) * DIM + h * HD + d4];
            Ks[(d4 + 0) * KS_STR + k] = v.x;
            Ks[(d4 + 1) * KS_STR + k] = v.y;
            Ks[(d4 + 2) * KS_STR + k] = v.z;
            Ks[(d4 + 3) * KS_STR + k] = v.w;
        }
        // V tile [64k x 128d] natural
        #pragma unroll
        for (int i = 0; i < 4; i++) {
            int chunk = tid + i * 512;
            int vr = chunk >> 5;
            int d4 = (chunk & 31) << 2;
            float4 v = make_float4(0.f, 0.f, 0.f, 0.f);
            if (k0 + vr < S_TOT)
                v = *(const float4*)&V[(size_t)(k0 + vr) * DIM + h * HD + d4];
            *(float4*)&Vs[vr * VS_STR + d4] = v;
        }
        __syncthreads();

        // S = Q K^T : thread owns rows ty*4..+3, cols tx*4..+3
        u64t s2[4][2];
        #pragma unroll
        for (int i = 0; i < 4; i++) { s2[i][0] = 0ull; s2[i][1] = 0ull; }
        #pragma unroll 8
        for (int kk = 0; kk < HD; kk++) {
            float4 a = *(const float4*)&Qs[kk * QS_STR + ty * 4];
            ulonglong2 b = *(const ulonglong2*)&Ks[kk * KS_STR + tx * 4];
            u64t a0 = dup2(a.x), a1 = dup2(a.y), a2 = dup2(a.z), a3 = dup2(a.w);
            ffma2(s2[0][0], a0, b.x); ffma2(s2[0][1], a0, b.y);
            ffma2(s2[1][0], a1, b.x); ffma2(s2[1][1], a1, b.y);
            ffma2(s2[2][0], a2, b.x); ffma2(s2[2][1], a2, b.y);
            ffma2(s2[3][0], a3, b.x); ffma2(s2[3][1], a3, b.y);
        }

        float sc[4][4];
        #pragma unroll
        for (int i = 0; i < 4; i++) {
            unpack2(s2[i][0], sc[i][0], sc[i][1]);
            unpack2(s2[i][1], sc[i][2], sc[i][3]);
        }
        #pragma unroll
        for (int i = 0; i < 4; i++)
            #pragma unroll
            for (int j = 0; j < 4; j++) {
                int kc = k0 + tx * 4 + j;
                float v = sc[i][j] * scale;
                sc[i][j] = (kc < seqlen) ? v : -1e30f;
            }

        // online softmax, in registers, reduced across the 16 tx lanes
        float alpha[4];
        #pragma unroll
        for (int i = 0; i < 4; i++) {
            float r = fmaxf(fmaxf(sc[i][0], sc[i][1]), fmaxf(sc[i][2], sc[i][3]));
            r = fmaxf(r, __shfl_xor_sync(0xffffffffu, r, 1));
            r = fmaxf(r, __shfl_xor_sync(0xffffffffu, r, 2));
            r = fmaxf(r, __shfl_xor_sync(0xffffffffu, r, 4));
            r = fmaxf(r, __shfl_xor_sync(0xffffffffu, r, 8));
            float mnew = fmaxf(m_i[i], r);
            alpha[i] = __expf(m_i[i] - mnew);
            m_i[i] = mnew;
            float rs = 0.f;
            #pragma unroll
            for (int j = 0; j < 4; j++) {
                float p = __expf(sc[i][j] - mnew);
                sc[i][j] = p;
                rs += p;
            }
            rs += __shfl_xor_sync(0xffffffffu, rs, 1);
            rs += __shfl_xor_sync(0xffffffffu, rs, 2);
            rs += __shfl_xor_sync(0xffffffffu, rs, 4);
            rs += __shfl_xor_sync(0xffffffffu, rs, 8);
            l_i[i] = l_i[i] * alpha[i] + rs;
        }

        // rescale O accumulators
        #pragma unroll
        for (int i = 0; i < 4; i++) {
            u64t ad = dup2(alpha[i]);
            #pragma unroll
            for (int j = 0; j < 4; j++) o2[i][j] = mul2(o2[i][j], ad);
        }

        // write P transposed: Ps[k][q]
        #pragma unroll
        for (int j = 0; j < 4; j++) {
            float4 pv = make_float4(sc[0][j], sc[1][j], sc[2][j], sc[3][j]);
            *(float4*)&Ps[(tx * 4 + j) * PS_STR + ty * 4] = pv;
        }
        __syncthreads();

        // O += P V : thread owns rows ty*4..+3, cols tx*4..+3 and 64+tx*4..+3
        #pragma unroll 8
        for (int kk = 0; kk < BK; kk++) {
            float4 pa = *(const float4*)&Ps[kk * PS_STR + ty * 4];
            ulonglong2 v0 = *(const ulonglong2*)&Vs[kk * VS_STR + tx * 4];
            ulonglong2 v1 = *(const ulonglong2*)&Vs[kk * VS_STR + 64 + tx * 4];
            u64t p0 = dup2(pa.x), p1 = dup2(pa.y), p2 = dup2(pa.z), p3 = dup2(pa.w);
            ffma2(o2[0][0], p0, v0.x); ffma2(o2[0][1], p0, v0.y);
            ffma2(o2[0][2], p0, v1.x); ffma2(o2[0][3], p0, v1.y);
            ffma2(o2[1][0], p1, v0.x); ffma2(o2[1][1], p1, v0.y);
            ffma2(o2[1][2], p1, v1.x); ffma2(o2[1][3], p1, v1.y);
            ffma2(o2[2][0], p2, v0.x); ffma2(o2[2][1], p2, v0.y);
            ffma2(o2[2][2], p2, v1.x); ffma2(o2[2][3], p2, v1.y);
            ffma2(o2[3][0], p3, v0.x); ffma2(o2[3][1], p3, v0.y);
            ffma2(o2[3][2], p3, v1.x); ffma2(o2[3][3], p3, v1.y);
        }
    }

    // write O
    #pragma unroll
    for (int i = 0; i < 4; i++) {
        int qr = q0 + ty * 4 + i;
        if (qr >= S_TOT) continue;
        float invl = 1.f / l_i[i];
        float c[8];
        unpack2(o2[i][0], c[0], c[1]);
        unpack2(o2[i][1], c[2], c[3]);
        unpack2(o2[i][2], c[4], c[5]);
        unpack2(o2[i][3], c[6], c[7]);
        float4 w0 = make_float4(c[0] * invl, c[1] * invl, c[2] * invl, c[3] * invl);
        float4 w1 = make_float4(c[4] * invl, c[5] * invl, c[6] * invl, c[7] * invl);
        *(float4*)&O[(size_t)qr * DIM + h * HD + tx * 4] = w0;
        *(float4*)&O[(size_t)qr * DIM + h * HD + 64 + tx * 4] = w1;
    }
}

// ---------------- launch ----------------
extern "C" void kernel_launch(void* const* d_in, const int* in_sizes, int n_in,
                              void* d_out, int out_size) {
    const float* x        = (const float*)d_in[0];
    const int*   seq_lens = (const int*)  d_in[1];
    const int*   grid_sz  = (const int*)  d_in[2];
    const float* freqs    = (const float*)d_in[3];
    const float* Wq       = (const float*)d_in[4];
    const float* bq       = (const float*)d_in[5];
    const float* Wk       = (const float*)d_in[6];
    const float* bk       = (const float*)d_in[7];
    const float* Wv       = (const float*)d_in[8];
    const float* bv       = (const float*)d_in[9];
    const float* Wo       = (const float*)d_in[10];
    const float* bo       = (const float*)d_in[11];
    const float* gq       = (const float*)d_in[12];
    const float* gk       = (const float*)d_in[13];
    float* out = (float*)d_out;

    float *q, *k, *v, *ao;
    cudaGetSymbolAddress((void**)&q,  g_q);
    cudaGetSymbolAddress((void**)&k,  g_k);
    cudaGetSymbolAddress((void**)&v,  g_v);
    cudaGetSymbolAddress((void**)&ao, g_ao);

    dim3 gb(GN / 128, (S_TOT + 127) / 128);   // (12, 31)

    sgemm128<<<gb, 256>>>(x, Wq, bq, q, S_TOT);
    sgemm128<<<gb, 256>>>(x, Wk, bk, k, S_TOT);
    sgemm128<<<gb, 256>>>(x, Wv, bv, v, S_TOT);

    rmsnorm_rope_kernel<<<S_TOT, 256>>>(q, gq, freqs, grid_sz);
    rmsnorm_rope_kernel<<<S_TOT, 256>>>(k, gk, freqs, grid_sz);

    cudaFuncSetAttribute(flash_kernel, cudaFuncAttributeMaxDynamicSharedMemorySize,
                         FL_SMEM_BYTES);
    dim3 ga((S_TOT + BQ - 1) / BQ, NH);       // (31, 12)
    flash_kernel<<<ga, 512, FL_SMEM_BYTES>>>(q, k, v, ao, seq_lens);

    sgemm128<<<gb, 256>>>(ao, Wo, bo, out, S_TOT);
}

// round 6
// speedup vs baseline: 13.1227x; 2.1649x over previous
#include <cuda_runtime.h>
#include <cuda_bf16.h>
#include <math.h>
#include <stdint.h>

#define S_TOT 3900
#define SP    3904        // padded seq (61*64)
#define DIM   1536
#define NH    12
#define HD    128
#define CC    64

// ---------------- scratch ----------------
__device__ float g_q [S_TOT * DIM];
__device__ float g_k [S_TOT * DIM];
__device__ float g_v [S_TOT * DIM];

__device__ __nv_bfloat16 g_xh [S_TOT * DIM];
__device__ __nv_bfloat16 g_xl [S_TOT * DIM];
__device__ __nv_bfloat16 g_qh [S_TOT * DIM];
__device__ __nv_bfloat16 g_ql [S_TOT * DIM];
__device__ __nv_bfloat16 g_kh [S_TOT * DIM];
__device__ __nv_bfloat16 g_kl [S_TOT * DIM];
__device__ __nv_bfloat16 g_aoh[S_TOT * DIM];
__device__ __nv_bfloat16 g_aol[S_TOT * DIM];
__device__ __nv_bfloat16 g_vth[DIM * SP];
__device__ __nv_bfloat16 g_vtl[DIM * SP];

__device__ __nv_bfloat16 g_wthq[DIM * DIM];
__device__ __nv_bfloat16 g_wtlq[DIM * DIM];
__device__ __nv_bfloat16 g_wthk[DIM * DIM];
__device__ __nv_bfloat16 g_wtlk[DIM * DIM];
__device__ __nv_bfloat16 g_wthv[DIM * DIM];
__device__ __nv_bfloat16 g_wtlv[DIM * DIM];
__device__ __nv_bfloat16 g_wtho[DIM * DIM];
__device__ __nv_bfloat16 g_wtlo[DIM * DIM];

// ================= helpers =================
__device__ __forceinline__ uint32_t smem_u32(const void* p) {
    uint32_t a;
    asm("{ .reg .u64 t; cvta.to.shared.u64 t, %1; cvt.u32.u64 %0, t; }" : "=r"(a) : "l"(p));
    return a;
}
__device__ __forceinline__ void ldsm4(uint32_t& r0, uint32_t& r1, uint32_t& r2, uint32_t& r3,
                                      uint32_t addr) {
    asm volatile("ldmatrix.sync.aligned.m8n8.x4.shared.b16 {%0,%1,%2,%3}, [%4];"
                 : "=r"(r0), "=r"(r1), "=r"(r2), "=r"(r3) : "r"(addr));
}
__device__ __forceinline__ void mma16816(float* c, const uint32_t* a, const uint32_t* b) {
    asm volatile(
        "mma.sync.aligned.m16n8k16.row.col.f32.bf16.bf16.f32 "
        "{%0,%1,%2,%3}, {%4,%5,%6,%7}, {%8,%9}, {%0,%1,%2,%3};"
        : "+f"(c[0]), "+f"(c[1]), "+f"(c[2]), "+f"(c[3])
        : "r"(a[0]), "r"(a[1]), "r"(a[2]), "r"(a[3]), "r"(b[0]), "r"(b[1]));
}
__device__ __forceinline__ uint32_t pack_bf(float lo, float hi) {
    __nv_bfloat162 t = __floats2bfloat162_rn(lo, hi);
    return *(uint32_t*)&t;
}
__device__ __forceinline__ void split2(float x, float y, uint32_t& hw, uint32_t& lw) {
    __nv_bfloat16 bx = __float2bfloat16(x), by = __float2bfloat16(y);
    __nv_bfloat162 hp; hp.x = bx; hp.y = by;
    hw = *(uint32_t*)&hp;
    lw = pack_bf(x - __bfloat162float(bx), y - __bfloat162float(by));
}
__device__ __forceinline__ void hilo(float x, unsigned short& h, unsigned short& l) {
    __nv_bfloat16 hb = __float2bfloat16(x);
    h = __bfloat16_as_ushort(hb);
    l = __bfloat16_as_ushort(__float2bfloat16(x - __bfloat162float(hb)));
}

// ================= prep kernels =================
__global__ __launch_bounds__(256)
void convert_x_kernel(const float* __restrict__ x,
                      __nv_bfloat16* __restrict__ xh, __nv_bfloat16* __restrict__ xl) {
    int i = blockIdx.x * 256 + threadIdx.x;
    const int tot4 = S_TOT * DIM / 4;
    if (i >= tot4) return;
    float4 v = ((const float4*)x)[i];
    unsigned short h0,l0,h1,l1,h2,l2,h3,l3;
    hilo(v.x,h0,l0); hilo(v.y,h1,l1); hilo(v.z,h2,l2); hilo(v.w,h3,l3);
    ((uint2*)xh)[i] = make_uint2((uint32_t)h0 | ((uint32_t)h1 << 16), (uint32_t)h2 | ((uint32_t)h3 << 16));
    ((uint2*)xl)[i] = make_uint2((uint32_t)l0 | ((uint32_t)l1 << 16), (uint32_t)l2 | ((uint32_t)l3 << 16));
}

// W[K][N] fp32 -> Wt[N][K] bf16 hi/lo
__global__ __launch_bounds__(256)
void transw_kernel(const float* __restrict__ W,
                   __nv_bfloat16* __restrict__ Th, __nv_bfloat16* __restrict__ Tl) {
    __shared__ float t[32][33];
    const int n0 = blockIdx.x * 32, k0 = blockIdx.y * 32;
    const int tx = threadIdx.x, ty = threadIdx.y;
    #pragma unroll
    for (int i = 0; i < 4; i++)
        t[ty + i * 8][tx] = W[(size_t)(k0 + ty + i * 8) * DIM + n0 + tx];
    __syncthreads();
    #pragma unroll
    for (int i = 0; i < 4; i++) {
        float v = t[tx][ty + i * 8];
        unsigned short h, l; hilo(v, h, l);
        size_t o = (size_t)(n0 + ty + i * 8) * DIM + k0 + tx;
        Th[o] = __ushort_as_bfloat16(h);
        Tl[o] = __ushort_as_bfloat16(l);
    }
}

// V[S][DIM] fp32 -> Vt[DIM][SP] bf16 hi/lo (zero-pad s >= S_TOT)
__global__ __launch_bounds__(256)
void transv_kernel(const float* __restrict__ V,
                   __nv_bfloat16* __restrict__ Th, __nv_bfloat16* __restrict__ Tl) {
    __shared__ float t[32][33];
    const int s0 = blockIdx.x * 32, d0 = blockIdx.y * 32;
    const int tx = threadIdx.x, ty = threadIdx.y;
    #pragma unroll
    for (int i = 0; i < 4; i++) {
        int s = s0 + ty + i * 8;
        t[ty + i * 8][tx] = (s < S_TOT) ? V[(size_t)s * DIM + d0 + tx] : 0.f;
    }
    __syncthreads();
    #pragma unroll
    for (int i = 0; i < 4; i++) {
        float v = t[tx][ty + i * 8];
        unsigned short h, l; hilo(v, h, l);
        size_t o = (size_t)(d0 + ty + i * 8) * SP + s0 + tx;
        Th[o] = __ushort_as_bfloat16(h);
        Tl[o] = __ushort_as_bfloat16(l);
    }
}

// RMSNorm + RoPE: fp32 in -> bf16 hi/lo out
__global__ __launch_bounds__(256)
void rmsnorm_rope_conv(const float* __restrict__ t, const float* __restrict__ g,
                       const float* __restrict__ freqs, const int* __restrict__ grid_sizes,
                       __nv_bfloat16* __restrict__ oh, __nv_bfloat16* __restrict__ ol) {
    const int s = blockIdx.x;
    const int tid = threadIdx.x;
    const float* row = t + (size_t)s * DIM;

    float ss = 0.f;
    for (int i = tid; i < DIM; i += 256) { float v = row[i]; ss += v * v; }
    #pragma unroll
    for (int off = 16; off; off >>= 1) ss += __shfl_xor_sync(0xffffffffu, ss, off);
    __shared__ float red[8];
    if ((tid & 31) == 0) red[tid >> 5] = ss;
    __syncthreads();
    if (tid == 0) {
        float tot = 0.f;
        #pragma unroll
        for (int i = 0; i < 8; i++) tot += red[i];
        red[0] = tot;
    }
    __syncthreads();
    const float inv = rsqrtf(red[0] * (1.f / DIM) + 1e-6f);

    const int H = grid_sizes[1], W = grid_sizes[2];
    const int fi = s / (H * W);
    const int rem = s % (H * W);
    const int hi = rem / W;
    const int wi = rem % W;
    const int c3 = CC / 3, c0 = CC - 2 * c3;

    for (int p = tid; p < NH * CC; p += 256) {
        int j = p % CC;
        int head = p / CC;
        int idx = head * HD + 2 * j;
        float a = row[idx]     * inv * g[idx];
        float b = row[idx + 1] * inv * g[idx + 1];
        int pos = (j < c0) ? fi : ((j < c0 + c3) ? hi : wi);
        float cs = freqs[(pos * CC + j) * 2 + 0];
        float sn = freqs[(pos * CC + j) * 2 + 1];
        float ra = a * cs - b * sn;
        float rb = a * sn + b * cs;
        uint32_t hw, lw;
        split2(ra, rb, hw, lw);
        *(uint32_t*)(oh + (size_t)s * DIM + idx) = hw;
        *(uint32_t*)(ol + (size_t)s * DIM + idx) = lw;
    }
}

// ================= HMMA GEMM: C[M x 1536] = (Ah+Al)(Wt_h+Wt_l)^T + bias =================
#define G_ST   40
#define G_BUFB 10240
#define G_ASH  0
#define G_ASL  20480
#define G_BSH  40960
#define G_BSL  61440
#define G_SMEM 81920

__global__ __launch_bounds__(256)
void gemm_mma(const __nv_bfloat16* __restrict__ Ah, const __nv_bfloat16* __restrict__ Al,
              const __nv_bfloat16* __restrict__ Bh, const __nv_bfloat16* __restrict__ Bl,
              const float* __restrict__ bias, float* __restrict__ C, int M) {
    extern __shared__ char smc[];
    const uint32_t sb = smem_u32(smc);
    const int tid = threadIdx.x;
    const int lane = tid & 31;
    const int wid = tid >> 5;
    const int wm = wid & 1;       // 0..1 -> 64 rows
    const int wn = wid >> 1;      // 0..3 -> 32 cols
    const int m0 = blockIdx.y * 128;
    const int n0 = blockIdx.x * 128;

    float c[4][4][4];
    #pragma unroll
    for (int i = 0; i < 4; i++)
        #pragma unroll
        for (int j = 0; j < 4; j++)
            #pragma unroll
            for (int q = 0; q < 4; q++) c[i][j][q] = 0.f;

    auto load_stage = [&](int kt, int buf) {
        const int k0 = kt * 32;
        const int bo = buf * G_BUFB;
        #pragma unroll
        for (int cix = 0; cix < 2; cix++) {
            int ch = tid + cix * 256;           // 0..511
            int row = ch >> 2, cc = (ch & 3) * 8;
            uint32_t so = (uint32_t)(row * G_ST + cc) * 2 + bo;
            uint4 vh = make_uint4(0,0,0,0), vl = make_uint4(0,0,0,0);
            if (m0 + row < M) {
                size_t gA = (size_t)(m0 + row) * DIM + k0 + cc;
                vh = *(const uint4*)(Ah + gA);
                vl = *(const uint4*)(Al + gA);
            }
            *(uint4*)(smc + G_ASH + so) = vh;
            *(uint4*)(smc + G_ASL + so) = vl;
            size_t gB = (size_t)(n0 + row) * DIM + k0 + cc;
            *(uint4*)(smc + G_BSH + so) = *(const uint4*)(Bh + gB);
            *(uint4*)(smc + G_BSL + so) = *(const uint4*)(Bl + gB);
        }
    };

    load_stage(0, 0);
    __syncthreads();

    const int a_row = (lane & 15);
    const int a_col = ((lane >> 1) & 8);
    const int b_row = (lane & 7) + ((lane & 16) >> 1);
    const int b_col = (lane & 8);

    for (int kt = 0; kt < 48; kt++) {
        if (kt < 47) load_stage(kt + 1, (kt + 1) & 1);
        const int bo = (kt & 1) * G_BUFB;
        #pragma unroll
        for (int kc = 0; kc < 32; kc += 16) {
            uint32_t af[4][4], bfh[4][2], bfl[4][2];
            #pragma unroll
            for (int mt = 0; mt < 4; mt++)
                ldsm4(af[mt][0], af[mt][1], af[mt][2], af[mt][3],
                      sb + G_ASH + bo + (uint32_t)((wm * 64 + mt * 16 + a_row) * G_ST + kc + a_col) * 2);
            #pragma unroll
            for (int np = 0; np < 2; np++) {
                uint32_t r0, r1, r2, r3;
                uint32_t ad = sb + G_BSH + bo +
                    (uint32_t)((wn * 32 + np * 16 + b_row) * G_ST + kc + b_col) * 2;
                ldsm4(r0, r1, r2, r3, ad);
                bfh[np*2][0] = r0; bfh[np*2][1] = r1; bfh[np*2+1][0] = r2; bfh[np*2+1][1] = r3;
                ad = sb + G_BSL + bo +
                    (uint32_t)((wn * 32 + np * 16 + b_row) * G_ST + kc + b_col) * 2;
                ldsm4(r0, r1, r2, r3, ad);
                bfl[np*2][0] = r0; bfl[np*2][1] = r1; bfl[np*2+1][0] = r2; bfl[np*2+1][1] = r3;
            }
            #pragma unroll
            for (int mt = 0; mt < 4; mt++)
                #pragma unroll
                for (int nt = 0; nt < 4; nt++) {
                    mma16816(c[mt][nt], af[mt], bfh[nt]);
                    mma16816(c[mt][nt], af[mt], bfl[nt]);
                }
            #pragma unroll
            for (int mt = 0; mt < 4; mt++)
                ldsm4(af[mt][0], af[mt][1], af[mt][2], af[mt][3],
                      sb + G_ASL + bo + (uint32_t)((wm * 64 + mt * 16 + a_row) * G_ST + kc + a_col) * 2);
            #pragma unroll
            for (int mt = 0; mt < 4; mt++)
                #pragma unroll
                for (int nt = 0; nt < 4; nt++)
                    mma16816(c[mt][nt], af[mt], bfh[nt]);
        }
        __syncthreads();
    }

    // epilogue
    #pragma unroll
    for (int mt = 0; mt < 4; mt++) {
        #pragma unroll
        for (int nt = 0; nt < 4; nt++) {
            int row = m0 + wm * 64 + mt * 16 + (lane >> 2);
            int col = n0 + wn * 32 + nt * 8 + (lane & 3) * 2;
            float b0 = bias[col], b1 = bias[col + 1];
            if (row < M)
                *(float2*)&C[(size_t)row * DIM + col] =
                    make_float2(c[mt][nt][0] + b0, c[mt][nt][1] + b1);
            if (row + 8 < M)
                *(float2*)&C[(size_t)(row + 8) * DIM + col] =
                    make_float2(c[mt][nt][2] + b0, c[mt][nt][3] + b1);
        }
    }
}

// ================= HMMA flash attention =================
#define F_QST 136
#define F_VST 72
#define F_QH  0
#define F_QL  34816
#define F_KH  69632
#define F_KL  87040
#define F_VTH 104448
#define F_VTL 122880
#define F_SMEM 141312

__global__ __launch_bounds__(256, 1)
void flash_mma(const __nv_bfloat16* __restrict__ Qh, const __nv_bfloat16* __restrict__ Ql,
               const __nv_bfloat16* __restrict__ Kh, const __nv_bfloat16* __restrict__ Kl,
               const __nv_bfloat16* __restrict__ Vh, const __nv_bfloat16* __restrict__ Vl,
               __nv_bfloat16* __restrict__ AOh, __nv_bfloat16* __restrict__ AOl,
               const int* __restrict__ seq_lens) {
    extern __shared__ char smc[];
    const uint32_t sb = smem_u32(smc);
    const int tid = threadIdx.x;
    const int lane = tid & 31;
    const int wid = tid >> 5;
    const int r0w = wid * 16;               // this warp's q rows (within tile)
    const int h = blockIdx.y;
    const int q0 = blockIdx.x * 128;
    const int seqlen = seq_lens[0];
    const float scale = 0.08838834764831845f;

    // ---- load Q tile [128 x 128] hi/lo : 2048 uint4 chunks ----
    #pragma unroll
    for (int cix = 0; cix < 8; cix++) {
        int ch = tid + cix * 256;            // 0..2047
        int row = ch >> 4, cc = (ch & 15) * 8;
        uint32_t so = (uint32_t)(row * F_QST + cc) * 2;
        uint4 vh = make_uint4(0,0,0,0), vl = make_uint4(0,0,0,0);
        if (q0 + row < S_TOT) {
            size_t gq = (size_t)(q0 + row) * DIM + h * HD + cc;
            vh = *(const uint4*)(Qh + gq);
            vl = *(const uint4*)(Ql + gq);
        }
        *(uint4*)(smc + F_QH + so) = vh;
        *(uint4*)(smc + F_QL + so) = vl;
    }

    float m0s = -1e30f, m1s = -1e30f, l0s = 0.f, l1s = 0.f;
    float o[16][4];
    #pragma unroll
    for (int i = 0; i < 16; i++)
        #pragma unroll
        for (int j = 0; j < 4; j++) o[i][j] = 0.f;

    const int a_row = (lane & 15);
    const int a_col = ((lane >> 1) & 8);
    const int b_row = (lane & 7) + ((lane & 16) >> 1);
    const int b_col = (lane & 8);

    for (int t = 0; t < SP / 64; t++) {
        const int k0 = t * 64;
        __syncthreads();
        // ---- load K [64 x 128] (1024 chunks) + Vt [128 x 64] (1024 chunks) ----
        #pragma unroll
        for (int cix = 0; cix < 4; cix++) {
            int ch = tid + cix * 256;        // 0..1023
            {
                int row = ch >> 4, cc = (ch & 15) * 8;
                uint32_t so = (uint32_t)(row * F_QST + cc) * 2;
                uint4 vh = make_uint4(0,0,0,0), vl = make_uint4(0,0,0,0);
                if (k0 + row < S_TOT) {
                    size_t gk = (size_t)(k0 + row) * DIM + h * HD + cc;
                    vh = *(const uint4*)(Kh + gk);
                    vl = *(const uint4*)(Kl + gk);
                }
                *(uint4*)(smc + F_KH + so) = vh;
                *(uint4*)(smc + F_KL + so) = vl;
            }
            {
                int row = ch >> 3, cc = (ch & 7) * 8;
                uint32_t so = (uint32_t)(row * F_VST + cc) * 2;
                size_t gv = (size_t)(h * HD + row) * SP + k0 + cc;
                *(uint4*)(smc + F_VTH + so) = *(const uint4*)(Vh + gv);
                *(uint4*)(smc + F_VTL + so) = *(const uint4*)(Vl + gv);
            }
        }
        __syncthreads();

        // ---- S = Q K^T : c[8 kv-tiles][4] ----
        float c[8][4];
        #pragma unroll
        for (int nt = 0; nt < 8; nt++)
            #pragma unroll
            for (int j = 0; j < 4; j++) c[nt][j] = 0.f;

        #pragma unroll
        for (int kc8 = 0; kc8 < 8; kc8++) {
            const int kc = kc8 * 16;
            uint32_t aq[4], bkh[8][2], bkl[8][2];
            ldsm4(aq[0], aq[1], aq[2], aq[3],
                  sb + F_QH + (uint32_t)((r0w + a_row) * F_QST + kc + a_col) * 2);
            #pragma unroll
            for (int np = 0; np < 4; np++) {
                uint32_t r0, r1, r2, r3;
                ldsm4(r0, r1, r2, r3,
                      sb + F_KH + (uint32_t)((np * 16 + b_row) * F_QST + kc + b_col) * 2);
                bkh[np*2][0] = r0; bkh[np*2][1] = r1; bkh[np*2+1][0] = r2; bkh[np*2+1][1] = r3;
                ldsm4(r0, r1, r2, r3,
                      sb + F_KL + (uint32_t)((np * 16 + b_row) * F_QST + kc + b_col) * 2);
                bkl[np*2][0] = r0; bkl[np*2][1] = r1; bkl[np*2+1][0] = r2; bkl[np*2+1][1] = r3;
            }
            #pragma unroll
            for (int nt = 0; nt < 8; nt++) {
                mma16816(c[nt], aq, bkh[nt]);
                mma16816(c[nt], aq, bkl[nt]);
            }
            ldsm4(aq[0], aq[1], aq[2], aq[3],
                  sb + F_QL + (uint32_t)((r0w + a_row) * F_QST + kc + a_col) * 2);
            #pragma unroll
            for (int nt = 0; nt < 8; nt++)
                mma16816(c[nt], aq, bkh[nt]);
        }

        // ---- scale + mask ----
        #pragma unroll
        for (int nt = 0; nt < 8; nt++) {
            int colb = k0 + nt * 8 + (lane & 3) * 2;
            #pragma unroll
            for (int j = 0; j < 4; j++) {
                float v = c[nt][j] * scale;
                c[nt][j] = (colb + (j & 1) < seqlen) ? v : -1e30f;
            }
        }

        // ---- online softmax (rows lane>>2 and +8) ----
        float mx0 = -1e30f, mx1 = -1e30f;
        #pragma unroll
        for (int nt = 0; nt < 8; nt++) {
            mx0 = fmaxf(mx0, fmaxf(c[nt][0], c[nt][1]));
            mx1 = fmaxf(mx1, fmaxf(c[nt][2], c[nt][3]));
        }
        mx0 = fmaxf(mx0, __shfl_xor_sync(0xffffffffu, mx0, 1));
        mx0 = fmaxf(mx0, __shfl_xor_sync(0xffffffffu, mx0, 2));
        mx1 = fmaxf(mx1, __shfl_xor_sync(0xffffffffu, mx1, 1));
        mx1 = fmaxf(mx1, __shfl_xor_sync(0xffffffffu, mx1, 2));
        float mn0 = fmaxf(m0s, mx0), mn1 = fmaxf(m1s, mx1);
        float al0 = __expf(m0s - mn0), al1 = __expf(m1s - mn1);
        m0s = mn0; m1s = mn1;
        float ls0 = 0.f, ls1 = 0.f;
        #pragma unroll
        for (int nt = 0; nt < 8; nt++) {
            c[nt][0] = __expf(c[nt][0] - mn0); ls0 += c[nt][0];
            c[nt][1] = __expf(c[nt][1] - mn0); ls0 += c[nt][1];
            c[nt][2] = __expf(c[nt][2] - mn1); ls1 += c[nt][2];
            c[nt][3] = __expf(c[nt][3] - mn1); ls1 += c[nt][3];
        }
        ls0 += __shfl_xor_sync(0xffffffffu, ls0, 1);
        ls0 += __shfl_xor_sync(0xffffffffu, ls0, 2);
        ls1 += __shfl_xor_sync(0xffffffffu, ls1, 1);
        ls1 += __shfl_xor_sync(0xffffffffu, ls1, 2);
        l0s = l0s * al0 + ls0;
        l1s = l1s * al1 + ls1;

        // ---- pack P into A fragments (hi/lo) ----
        uint32_t ph[4][4], pl[4][4];
        #pragma unroll
        for (int kc2 = 0; kc2 < 4; kc2++) {
            split2(c[2*kc2][0],   c[2*kc2][1],   ph[kc2][0], pl[kc2][0]);
            split2(c[2*kc2][2],   c[2*kc2][3],   ph[kc2][1], pl[kc2][1]);
            split2(c[2*kc2+1][0], c[2*kc2+1][1], ph[kc2][2], pl[kc2][2]);
            split2(c[2*kc2+1][2], c[2*kc2+1][3], ph[kc2][3], pl[kc2][3]);
        }

        // ---- rescale O ----
        #pragma unroll
        for (int nt = 0; nt < 16; nt++) {
            o[nt][0] *= al0; o[nt][1] *= al0;
            o[nt][2] *= al1; o[nt][3] *= al1;
        }

        // ---- O += P V ----
        #pragma unroll
        for (int kc2 = 0; kc2 < 4; kc2++) {
            #pragma unroll
            for (int np = 0; np < 8; np++) {
                uint32_t vh0, vh1, vh2, vh3, vl0, vl1, vl2, vl3;
                uint32_t ad = sb + F_VTH +
                    (uint32_t)((np * 16 + b_row) * F_VST + kc2 * 16 + b_col) * 2;
                ldsm4(vh0, vh1, vh2, vh3, ad);
                ad = sb + F_VTL +
                    (uint32_t)((np * 16 + b_row) * F_VST + kc2 * 16 + b_col) * 2;
                ldsm4(vl0, vl1, vl2, vl3, ad);
                uint32_t bh0[2] = {vh0, vh1}, bh1[2] = {vh2, vh3};
                uint32_t bl0[2] = {vl0, vl1}, bl1[2] = {vl2, vl3};
                mma16816(o[2*np],   ph[kc2], bh0);
                mma16816(o[2*np+1], ph[kc2], bh1);
                mma16816(o[2*np],   ph[kc2], bl0);
                mma16816(o[2*np+1], ph[kc2], bl1);
                mma16816(o[2*np],   pl[kc2], bh0);
                mma16816(o[2*np+1], pl[kc2], bh1);
            }
        }
    }

    // ---- normalize + write ----
    const float il0 = 1.f / l0s, il1 = 1.f / l1s;
    const int rA = q0 + r0w + (lane >> 2);
    const int rB = rA + 8;
    #pragma unroll
    for (int nt = 0; nt < 16; nt++) {
        int col = h * HD + nt * 8 + (lane & 3) * 2;
        if (rA < S_TOT) {
            uint32_t hw, lw;
            split2(o[nt][0] * il0, o[nt][1] * il0, hw, lw);
            *(uint32_t*)(AOh + (size_t)rA * DIM + col) = hw;
            *(uint32_t*)(AOl + (size_t)rA * DIM + col) = lw;
        }
        if (rB < S_TOT) {
            uint32_t hw, lw;
            split2(o[nt][2] * il1, o[nt][3] * il1, hw, lw);
            *(uint32_t*)(AOh + (size_t)rB * DIM + col) = hw;
            *(uint32_t*)(AOl + (size_t)rB * DIM + col) = lw;
        }
    }
}

// ---------------- launch ----------------
extern "C" void kernel_launch(void* const* d_in, const int* in_sizes, int n_in,
                              void* d_out, int out_size) {
    const float* x        = (const float*)d_in[0];
    const int*   seq_lens = (const int*)  d_in[1];
    const int*   grid_sz  = (const int*)  d_in[2];
    const float* freqs    = (const float*)d_in[3];
    const float* Wq       = (const float*)d_in[4];
    const float* bq       = (const float*)d_in[5];
    const float* Wk       = (const float*)d_in[6];
    const float* bk       = (const float*)d_in[7];
    const float* Wv       = (const float*)d_in[8];
    const float* bv       = (const float*)d_in[9];
    const float* Wo       = (const float*)d_in[10];
    const float* bo       = (const float*)d_in[11];
    const float* gq       = (const float*)d_in[12];
    const float* gk       = (const float*)d_in[13];
    float* out = (float*)d_out;

    float *q, *k, *v;
    __nv_bfloat16 *xh, *xl, *qh, *ql, *kh, *kl, *aoh, *aol, *vth, *vtl;
    __nv_bfloat16 *wthq, *wtlq, *wthk, *wtlk, *wthv, *wtlv, *wtho, *wtlo;
    cudaGetSymbolAddress((void**)&q, g_q);
    cudaGetSymbolAddress((void**)&k, g_k);
    cudaGetSymbolAddress((void**)&v, g_v);
    cudaGetSymbolAddress((void**)&xh, g_xh);   cudaGetSymbolAddress((void**)&xl, g_xl);
    cudaGetSymbolAddress((void**)&qh, g_qh);   cudaGetSymbolAddress((void**)&ql, g_ql);
    cudaGetSymbolAddress((void**)&kh, g_kh);   cudaGetSymbolAddress((void**)&kl, g_kl);
    cudaGetSymbolAddress((void**)&aoh, g_aoh); cudaGetSymbolAddress((void**)&aol, g_aol);
    cudaGetSymbolAddress((void**)&vth, g_vth); cudaGetSymbolAddress((void**)&vtl, g_vtl);
    cudaGetSymbolAddress((void**)&wthq, g_wthq); cudaGetSymbolAddress((void**)&wtlq, g_wtlq);
    cudaGetSymbolAddress((void**)&wthk, g_wthk); cudaGetSymbolAddress((void**)&wtlk, g_wtlk);
    cudaGetSymbolAddress((void**)&wthv, g_wthv); cudaGetSymbolAddress((void**)&wtlv, g_wtlv);
    cudaGetSymbolAddress((void**)&wtho, g_wtho); cudaGetSymbolAddress((void**)&wtlo, g_wtlo);

    cudaFuncSetAttribute(gemm_mma, cudaFuncAttributeMaxDynamicSharedMemorySize, G_SMEM);
    cudaFuncSetAttribute(flash_mma, cudaFuncAttributeMaxDynamicSharedMemorySize, F_SMEM);

    // prep
    convert_x_kernel<<<S_TOT * DIM / 4 / 256, 256>>>(x, xh, xl);
    dim3 tw(48, 48), twb(32, 8);
    transw_kernel<<<tw, twb>>>(Wq, wthq, wtlq);
    transw_kernel<<<tw, twb>>>(Wk, wthk, wtlk);
    transw_kernel<<<tw, twb>>>(Wv, wthv, wtlv);
    transw_kernel<<<tw, twb>>>(Wo, wtho, wtlo);

    dim3 gg(12, 31);
    gemm_mma<<<gg, 256, G_SMEM>>>(xh, xl, wthq, wtlq, bq, q, S_TOT);
    gemm_mma<<<gg, 256, G_SMEM>>>(xh, xl, wthk, wtlk, bk, k, S_TOT);
    gemm_mma<<<gg, 256, G_SMEM>>>(xh, xl, wthv, wtlv, bv, v, S_TOT);

    rmsnorm_rope_conv<<<S_TOT, 256>>>(q, gq, freqs, grid_sz, qh, ql);
    rmsnorm_rope_conv<<<S_TOT, 256>>>(k, gk, freqs, grid_sz, kh, kl);
    transv_kernel<<<dim3(SP / 32, DIM / 32), twb>>>(v, vth, vtl);

    dim3 fg(31, NH);
    flash_mma<<<fg, 256, F_SMEM>>>(qh, ql, kh, kl, vth, vtl, aoh, aol, seq_lens);

    gemm_mma<<<gg, 256, G_SMEM>>>(aoh, aol, wtho, wtlo, bo, out, S_TOT);
}

// round 7
// speedup vs baseline: 16.5309x; 1.2597x over previous
#include <cuda_runtime.h>
#include <cuda_bf16.h>
#include <math.h>
#include <stdint.h>

#define S_TOT 3900
#define SP    3904        // padded seq (61*64)
#define DIM   1536
#define NH    12
#define HD    128
#define CC    64

// ---------------- scratch ----------------
__device__ float g_q [S_TOT * DIM];
__device__ float g_k [S_TOT * DIM];
__device__ float g_v [S_TOT * DIM];

__device__ __nv_bfloat16 g_xh [S_TOT * DIM];
__device__ __nv_bfloat16 g_xl [S_TOT * DIM];
__device__ __nv_bfloat16 g_qh [S_TOT * DIM];
__device__ __nv_bfloat16 g_ql [S_TOT * DIM];
__device__ __nv_bfloat16 g_kh [S_TOT * DIM];
__device__ __nv_bfloat16 g_kl [S_TOT * DIM];
__device__ __nv_bfloat16 g_aoh[S_TOT * DIM];
__device__ __nv_bfloat16 g_aol[S_TOT * DIM];
__device__ __nv_bfloat16 g_vth[DIM * SP];
__device__ __nv_bfloat16 g_vtl[DIM * SP];

__device__ __nv_bfloat16 g_wthq[DIM * DIM];
__device__ __nv_bfloat16 g_wtlq[DIM * DIM];
__device__ __nv_bfloat16 g_wthk[DIM * DIM];
__device__ __nv_bfloat16 g_wtlk[DIM * DIM];
__device__ __nv_bfloat16 g_wthv[DIM * DIM];
__device__ __nv_bfloat16 g_wtlv[DIM * DIM];
__device__ __nv_bfloat16 g_wtho[DIM * DIM];
__device__ __nv_bfloat16 g_wtlo[DIM * DIM];

// ================= helpers =================
__device__ __forceinline__ uint32_t smem_u32(const void* p) {
    uint32_t a;
    asm("{ .reg .u64 t; cvta.to.shared.u64 t, %1; cvt.u32.u64 %0, t; }" : "=r"(a) : "l"(p));
    return a;
}
__device__ __forceinline__ void ldsm4(uint32_t& r0, uint32_t& r1, uint32_t& r2, uint32_t& r3,
                                      uint32_t addr) {
    asm volatile("ldmatrix.sync.aligned.m8n8.x4.shared.b16 {%0,%1,%2,%3}, [%4];"
                 : "=r"(r0), "=r"(r1), "=r"(r2), "=r"(r3) : "r"(addr));
}
__device__ __forceinline__ void mma16816(float* c, const uint32_t* a, const uint32_t* b) {
    asm volatile(
        "mma.sync.aligned.m16n8k16.row.col.f32.bf16.bf16.f32 "
        "{%0,%1,%2,%3}, {%4,%5,%6,%7}, {%8,%9}, {%0,%1,%2,%3};"
        : "+f"(c[0]), "+f"(c[1]), "+f"(c[2]), "+f"(c[3])
        : "r"(a[0]), "r"(a[1]), "r"(a[2]), "r"(a[3]), "r"(b[0]), "r"(b[1]));
}
#define CP16(dst, src, sz) \
    asm volatile("cp.async.cg.shared.global [%0], [%1], 16, %2;" \
        :: "r"(dst), "l"(src), "r"(sz) : "memory")
#define CP_COMMIT() asm volatile("cp.async.commit_group;" ::: "memory")
#define CP_WAIT0()  asm volatile("cp.async.wait_group 0;" ::: "memory")

__device__ __forceinline__ uint32_t pack_bf(float lo, float hi) {
    __nv_bfloat162 t = __floats2bfloat162_rn(lo, hi);
    return *(uint32_t*)&t;
}
__device__ __forceinline__ void split2(float x, float y, uint32_t& hw, uint32_t& lw) {
    __nv_bfloat16 bx = __float2bfloat16(x), by = __float2bfloat16(y);
    __nv_bfloat162 hp; hp.x = bx; hp.y = by;
    hw = *(uint32_t*)&hp;
    lw = pack_bf(x - __bfloat162float(bx), y - __bfloat162float(by));
}
__device__ __forceinline__ void hilo(float x, unsigned short& h, unsigned short& l) {
    __nv_bfloat16 hb = __float2bfloat16(x);
    h = __bfloat16_as_ushort(hb);
    l = __bfloat16_as_ushort(__float2bfloat16(x - __bfloat162float(hb)));
}

// ================= prep kernels =================
__global__ __launch_bounds__(256)
void convert_x_kernel(const float* __restrict__ x,
                      __nv_bfloat16* __restrict__ xh, __nv_bfloat16* __restrict__ xl) {
    int i = blockIdx.x * 256 + threadIdx.x;
    const int tot4 = S_TOT * DIM / 4;
    if (i >= tot4) return;
    float4 v = ((const float4*)x)[i];
    unsigned short h0,l0,h1,l1,h2,l2,h3,l3;
    hilo(v.x,h0,l0); hilo(v.y,h1,l1); hilo(v.z,h2,l2); hilo(v.w,h3,l3);
    ((uint2*)xh)[i] = make_uint2((uint32_t)h0 | ((uint32_t)h1 << 16), (uint32_t)h2 | ((uint32_t)h3 << 16));
    ((uint2*)xl)[i] = make_uint2((uint32_t)l0 | ((uint32_t)l1 << 16), (uint32_t)l2 | ((uint32_t)l3 << 16));
}

// W[K][N] fp32 -> Wt[N][K] bf16 hi/lo ; 4 weights in one launch (blockIdx.z)
struct WPtrs { const float* w[4]; __nv_bfloat16* th[4]; __nv_bfloat16* tl[4]; };

__global__ __launch_bounds__(256)
void transw_kernel(WPtrs p) {
    __shared__ float t[32][33];
    const float* W = p.w[blockIdx.z];
    __nv_bfloat16* Th = p.th[blockIdx.z];
    __nv_bfloat16* Tl = p.tl[blockIdx.z];
    const int n0 = blockIdx.x * 32, k0 = blockIdx.y * 32;
    const int tx = threadIdx.x, ty = threadIdx.y;
    #pragma unroll
    for (int i = 0; i < 4; i++)
        t[ty + i * 8][tx] = W[(size_t)(k0 + ty + i * 8) * DIM + n0 + tx];
    __syncthreads();
    #pragma unroll
    for (int i = 0; i < 4; i++) {
        float v = t[tx][ty + i * 8];
        unsigned short h, l; hilo(v, h, l);
        size_t o = (size_t)(n0 + ty + i * 8) * DIM + k0 + tx;
        Th[o] = __ushort_as_bfloat16(h);
        Tl[o] = __ushort_as_bfloat16(l);
    }
}

// V[S][DIM] fp32 -> Vt[DIM][SP] bf16 hi/lo (zero-pad s >= S_TOT)
__global__ __launch_bounds__(256)
void transv_kernel(const float* __restrict__ V,
                   __nv_bfloat16* __restrict__ Th, __nv_bfloat16* __restrict__ Tl) {
    __shared__ float t[32][33];
    const int s0 = blockIdx.x * 32, d0 = blockIdx.y * 32;
    const int tx = threadIdx.x, ty = threadIdx.y;
    #pragma unroll
    for (int i = 0; i < 4; i++) {
        int s = s0 + ty + i * 8;
        t[ty + i * 8][tx] = (s < S_TOT) ? V[(size_t)s * DIM + d0 + tx] : 0.f;
    }
    __syncthreads();
    #pragma unroll
    for (int i = 0; i < 4; i++) {
        float v = t[tx][ty + i * 8];
        unsigned short h, l; hilo(v, h, l);
        size_t o = (size_t)(d0 + ty + i * 8) * SP + s0 + tx;
        Th[o] = __ushort_as_bfloat16(h);
        Tl[o] = __ushort_as_bfloat16(l);
    }
}

// RMSNorm + RoPE for q and k in one launch (blockIdx.y)
__global__ __launch_bounds__(256)
void rmsnorm_rope_conv(const float* __restrict__ tq, const float* __restrict__ gq,
                       __nv_bfloat16* __restrict__ qoh, __nv_bfloat16* __restrict__ qol,
                       const float* __restrict__ tk, const float* __restrict__ gk,
                       __nv_bfloat16* __restrict__ koh, __nv_bfloat16* __restrict__ kol,
                       const float* __restrict__ freqs, const int* __restrict__ grid_sizes) {
    const int s = blockIdx.x;
    const int tid = threadIdx.x;
    const float* t  = (blockIdx.y == 0) ? tq : tk;
    const float* g  = (blockIdx.y == 0) ? gq : gk;
    __nv_bfloat16* oh = (blockIdx.y == 0) ? qoh : koh;
    __nv_bfloat16* ol = (blockIdx.y == 0) ? qol : kol;
    const float* row = t + (size_t)s * DIM;

    float ss = 0.f;
    for (int i = tid; i < DIM; i += 256) { float v = row[i]; ss += v * v; }
    #pragma unroll
    for (int off = 16; off; off >>= 1) ss += __shfl_xor_sync(0xffffffffu, ss, off);
    __shared__ float red[8];
    if ((tid & 31) == 0) red[tid >> 5] = ss;
    __syncthreads();
    if (tid == 0) {
        float tot = 0.f;
        #pragma unroll
        for (int i = 0; i < 8; i++) tot += red[i];
        red[0] = tot;
    }
    __syncthreads();
    const float inv = rsqrtf(red[0] * (1.f / DIM) + 1e-6f);

    const int H = grid_sizes[1], W = grid_sizes[2];
    const int fi = s / (H * W);
    const int rem = s % (H * W);
    const int hi = rem / W;
    const int wi = rem % W;
    const int c3 = CC / 3, c0 = CC - 2 * c3;

    for (int p = tid; p < NH * CC; p += 256) {
        int j = p % CC;
        int head = p / CC;
        int idx = head * HD + 2 * j;
        float a = row[idx]     * inv * g[idx];
        float b = row[idx + 1] * inv * g[idx + 1];
        int pos = (j < c0) ? fi : ((j < c0 + c3) ? hi : wi);
        float cs = freqs[(pos * CC + j) * 2 + 0];
        float sn = freqs[(pos * CC + j) * 2 + 1];
        float ra = a * cs - b * sn;
        float rb = a * sn + b * cs;
        uint32_t hw, lw;
        split2(ra, rb, hw, lw);
        *(uint32_t*)(oh + (size_t)s * DIM + idx) = hw;
        *(uint32_t*)(ol + (size_t)s * DIM + idx) = lw;
    }
}

// ================= HMMA GEMM (cp.async double-buffered, multi-weight) =================
#define G_ST   40
#define G_BUFB 10240
#define G_ASH  0
#define G_ASL  20480
#define G_BSH  40960
#define G_BSL  61440
#define G_SMEM 81920

struct QKVArgs {
    const __nv_bfloat16* bh[3];
    const __nv_bfloat16* bl[3];
    const float* bias[3];
    float* c[3];
};

__global__ __launch_bounds__(256)
void gemm_mma(const __nv_bfloat16* __restrict__ Ah, const __nv_bfloat16* __restrict__ Al,
              QKVArgs args, int M) {
    extern __shared__ char smc[];
    const uint32_t sb = smem_u32(smc);
    const int tid = threadIdx.x;
    const int lane = tid & 31;
    const int wid = tid >> 5;
    const int wm = wid & 1;
    const int wn = wid >> 1;
    const int mat = blockIdx.x / 12;
    const int n0 = (blockIdx.x % 12) * 128;
    const int m0 = blockIdx.y * 128;
    const __nv_bfloat16* Bh = args.bh[mat];
    const __nv_bfloat16* Bl = args.bl[mat];
    const float* bias = args.bias[mat];
    float* C = args.c[mat];

    float c[4][4][4];
    #pragma unroll
    for (int i = 0; i < 4; i++)
        #pragma unroll
        for (int j = 0; j < 4; j++)
            #pragma unroll
            for (int q = 0; q < 4; q++) c[i][j][q] = 0.f;

    auto stage = [&](int kt, int buf) {
        const int k0 = kt * 32;
        #pragma unroll
        for (int cix = 0; cix < 2; cix++) {
            int ch = tid + cix * 256;           // 0..511
            int row = ch >> 2, cc = (ch & 3) * 8;
            uint32_t so = (uint32_t)(row * G_ST + cc) * 2 + (uint32_t)buf * G_BUFB;
            int szA = (m0 + row < M) ? 16 : 0;
            const __nv_bfloat16* pah = Ah + (size_t)(m0 + row) * DIM + k0 + cc;
            const __nv_bfloat16* pal = Al + (size_t)(m0 + row) * DIM + k0 + cc;
            const __nv_bfloat16* pbh = Bh + (size_t)(n0 + row) * DIM + k0 + cc;
            const __nv_bfloat16* pbl = Bl + (size_t)(n0 + row) * DIM + k0 + cc;
            CP16(sb + G_ASH + so, pah, szA);
            CP16(sb + G_ASL + so, pal, szA);
            CP16(sb + G_BSH + so, pbh, 16);
            CP16(sb + G_BSL + so, pbl, 16);
        }
        CP_COMMIT();
    };

    stage(0, 0);

    const int a_row = (lane & 15);
    const int a_col = ((lane >> 1) & 8);
    const int b_row = (lane & 7) + ((lane & 16) >> 1);
    const int b_col = (lane & 8);

    for (int kt = 0; kt < 48; kt++) {
        CP_WAIT0();
        __syncthreads();
        if (kt < 47) stage(kt + 1, (kt + 1) & 1);
        const int bo = (kt & 1) * G_BUFB;
        #pragma unroll
        for (int kc = 0; kc < 32; kc += 16) {
            uint32_t af[4][4], bfh[4][2], bfl[4][2];
            #pragma unroll
            for (int mt = 0; mt < 4; mt++)
                ldsm4(af[mt][0], af[mt][1], af[mt][2], af[mt][3],
                      sb + G_ASH + bo + (uint32_t)((wm * 64 + mt * 16 + a_row) * G_ST + kc + a_col) * 2);
            #pragma unroll
            for (int np = 0; np < 2; np++) {
                uint32_t r0, r1, r2, r3;
                uint32_t ad = sb + G_BSH + bo +
                    (uint32_t)((wn * 32 + np * 16 + b_row) * G_ST + kc + b_col) * 2;
                ldsm4(r0, r1, r2, r3, ad);
                bfh[np*2][0] = r0; bfh[np*2][1] = r1; bfh[np*2+1][0] = r2; bfh[np*2+1][1] = r3;
                ad = sb + G_BSL + bo +
                    (uint32_t)((wn * 32 + np * 16 + b_row) * G_ST + kc + b_col) * 2;
                ldsm4(r0, r1, r2, r3, ad);
                bfl[np*2][0] = r0; bfl[np*2][1] = r1; bfl[np*2+1][0] = r2; bfl[np*2+1][1] = r3;
            }
            #pragma unroll
            for (int mt = 0; mt < 4; mt++)
                #pragma unroll
                for (int nt = 0; nt < 4; nt++) {
                    mma16816(c[mt][nt], af[mt], bfh[nt]);
                    mma16816(c[mt][nt], af[mt], bfl[nt]);
                }
            #pragma unroll
            for (int mt = 0; mt < 4; mt++)
                ldsm4(af[mt][0], af[mt][1], af[mt][2], af[mt][3],
                      sb + G_ASL + bo + (uint32_t)((wm * 64 + mt * 16 + a_row) * G_ST + kc + a_col) * 2);
            #pragma unroll
            for (int mt = 0; mt < 4; mt++)
                #pragma unroll
                for (int nt = 0; nt < 4; nt++)
                    mma16816(c[mt][nt], af[mt], bfh[nt]);
        }
        __syncthreads();
    }

    // epilogue
    #pragma unroll
    for (int mt = 0; mt < 4; mt++) {
        #pragma unroll
        for (int nt = 0; nt < 4; nt++) {
            int row = m0 + wm * 64 + mt * 16 + (lane >> 2);
            int col = n0 + wn * 32 + nt * 8 + (lane & 3) * 2;
            float b0 = bias[col], b1 = bias[col + 1];
            if (row < M)
                *(float2*)&C[(size_t)row * DIM + col] =
                    make_float2(c[mt][nt][0] + b0, c[mt][nt][1] + b1);
            if (row + 8 < M)
                *(float2*)&C[(size_t)(row + 8) * DIM + col] =
                    make_float2(c[mt][nt][2] + b0, c[mt][nt][3] + b1);
        }
    }
}

// ================= HMMA flash attention (double-buffered K/V) =================
#define F_QST 136
#define F_VST 72
#define F_QH   0
#define F_QL   34816
#define F_STG  69632
#define F_STGB 71680          // KH 17408 | KL 17408 | VTH 18432 | VTL 18432
#define F_SMEM (F_STG + 2 * F_STGB)   // 212992

__global__ __launch_bounds__(256, 1)
void flash_mma(const __nv_bfloat16* __restrict__ Qh, const __nv_bfloat16* __restrict__ Ql,
               const __nv_bfloat16* __restrict__ Kh, const __nv_bfloat16* __restrict__ Kl,
               const __nv_bfloat16* __restrict__ Vh, const __nv_bfloat16* __restrict__ Vl,
               __nv_bfloat16* __restrict__ AOh, __nv_bfloat16* __restrict__ AOl,
               const int* __restrict__ seq_lens) {
    extern __shared__ char smc[];
    const uint32_t sb = smem_u32(smc);
    const int tid = threadIdx.x;
    const int lane = tid & 31;
    const int wid = tid >> 5;
    const int r0w = wid * 16;
    const int h = blockIdx.y;
    const int q0 = blockIdx.x * 128;
    const int seqlen = seq_lens[0];
    const float scale = 0.08838834764831845f;

    // ---- load Q tile [128 x 128] hi/lo : 2048 uint4 chunks ----
    #pragma unroll
    for (int cix = 0; cix < 8; cix++) {
        int ch = tid + cix * 256;
        int row = ch >> 4, cc = (ch & 15) * 8;
        uint32_t so = (uint32_t)(row * F_QST + cc) * 2;
        uint4 vh = make_uint4(0,0,0,0), vl = make_uint4(0,0,0,0);
        if (q0 + row < S_TOT) {
            size_t gq = (size_t)(q0 + row) * DIM + h * HD + cc;
            vh = *(const uint4*)(Qh + gq);
            vl = *(const uint4*)(Ql + gq);
        }
        *(uint4*)(smc + F_QH + so) = vh;
        *(uint4*)(smc + F_QL + so) = vl;
    }

    auto kv_stage = [&](int t, int buf) {
        const int k0 = t * 64;
        const uint32_t base = sb + F_STG + (uint32_t)buf * F_STGB;
        #pragma unroll
        for (int cix = 0; cix < 4; cix++) {
            int ch = tid + cix * 256;            // 0..1023
            {
                int row = ch >> 4, cc = (ch & 15) * 8;
                uint32_t so = (uint32_t)(row * F_QST + cc) * 2;
                int sz = (k0 + row < S_TOT) ? 16 : 0;
                const __nv_bfloat16* gh = Kh + (size_t)(k0 + row) * DIM + h * HD + cc;
                const __nv_bfloat16* gl = Kl + (size_t)(k0 + row) * DIM + h * HD + cc;
                CP16(base + so, gh, sz);
                CP16(base + 17408 + so, gl, sz);
            }
            {
                int row = ch >> 3, cc = (ch & 7) * 8;
                uint32_t so = (uint32_t)(row * F_VST + cc) * 2;
                const __nv_bfloat16* gvh = Vh + (size_t)(h * HD + row) * SP + k0 + cc;
                const __nv_bfloat16* gvl = Vl + (size_t)(h * HD + row) * SP + k0 + cc;
                CP16(base + 34816 + so, gvh, 16);
                CP16(base + 53248 + so, gvl, 16);
            }
        }
        CP_COMMIT();
    };

    kv_stage(0, 0);

    float m0s = -1e30f, m1s = -1e30f, l0s = 0.f, l1s = 0.f;
    float o[16][4];
    #pragma unroll
    for (int i = 0; i < 16; i++)
        #pragma unroll
        for (int j = 0; j < 4; j++) o[i][j] = 0.f;

    const int a_row = (lane & 15);
    const int a_col = ((lane >> 1) & 8);
    const int b_row = (lane & 7) + ((lane & 16) >> 1);
    const int b_col = (lane & 8);

    const int NT = SP / 64;
    for (int t = 0; t < NT; t++) {
        const int k0 = t * 64;
        CP_WAIT0();
        __syncthreads();
        if (t + 1 < NT) kv_stage(t + 1, (t + 1) & 1);

        const uint32_t kb = sb + F_STG + (uint32_t)(t & 1) * F_STGB;
        const uint32_t kbh = kb, kbl = kb + 17408;
        const uint32_t vbh = kb + 34816, vbl = kb + 53248;

        // ---- S = Q K^T ----
        float c[8][4];
        #pragma unroll
        for (int nt = 0; nt < 8; nt++)
            #pragma unroll
            for (int j = 0; j < 4; j++) c[nt][j] = 0.f;

        #pragma unroll
        for (int kc8 = 0; kc8 < 8; kc8++) {
            const int kc = kc8 * 16;
            uint32_t aq[4], bkh[8][2], bkl[8][2];
            ldsm4(aq[0], aq[1], aq[2], aq[3],
                  sb + F_QH + (uint32_t)((r0w + a_row) * F_QST + kc + a_col) * 2);
            #pragma unroll
            for (int np = 0; np < 4; np++) {
                uint32_t r0, r1, r2, r3;
                ldsm4(r0, r1, r2, r3,
                      kbh + (uint32_t)((np * 16 + b_row) * F_QST + kc + b_col) * 2);
                bkh[np*2][0] = r0; bkh[np*2][1] = r1; bkh[np*2+1][0] = r2; bkh[np*2+1][1] = r3;
                ldsm4(r0, r1, r2, r3,
                      kbl + (uint32_t)((np * 16 + b_row) * F_QST + kc + b_col) * 2);
                bkl[np*2][0] = r0; bkl[np*2][1] = r1; bkl[np*2+1][0] = r2; bkl[np*2+1][1] = r3;
            }
            #pragma unroll
            for (int nt = 0; nt < 8; nt++) {
                mma16816(c[nt], aq, bkh[nt]);
                mma16816(c[nt], aq, bkl[nt]);
            }
            ldsm4(aq[0], aq[1], aq[2], aq[3],
                  sb + F_QL + (uint32_t)((r0w + a_row) * F_QST + kc + a_col) * 2);
            #pragma unroll
            for (int nt = 0; nt < 8; nt++)
                mma16816(c[nt], aq, bkh[nt]);
        }

        // ---- scale + mask ----
        #pragma unroll
        for (int nt = 0; nt < 8; nt++) {
            int colb = k0 + nt * 8 + (lane & 3) * 2;
            #pragma unroll
            for (int j = 0; j < 4; j++) {
                float v = c[nt][j] * scale;
                c[nt][j] = (colb + (j & 1) < seqlen) ? v : -1e30f;
            }
        }

        // ---- online softmax ----
        float mx0 = -1e30f, mx1 = -1e30f;
        #pragma unroll
        for (int nt = 0; nt < 8; nt++) {
            mx0 = fmaxf(mx0, fmaxf(c[nt][0], c[nt][1]));
            mx1 = fmaxf(mx1, fmaxf(c[nt][2], c[nt][3]));
        }
        mx0 = fmaxf(mx0, __shfl_xor_sync(0xffffffffu, mx0, 1));
        mx0 = fmaxf(mx0, __shfl_xor_sync(0xffffffffu, mx0, 2));
        mx1 = fmaxf(mx1, __shfl_xor_sync(0xffffffffu, mx1, 1));
        mx1 = fmaxf(mx1, __shfl_xor_sync(0xffffffffu, mx1, 2));
        float mn0 = fmaxf(m0s, mx0), mn1 = fmaxf(m1s, mx1);
        float al0 = __expf(m0s - mn0), al1 = __expf(m1s - mn1);
        m0s = mn0; m1s = mn1;
        float ls0 = 0.f, ls1 = 0.f;
        #pragma unroll
        for (int nt = 0; nt < 8; nt++) {
            c[nt][0] = __expf(c[nt][0] - mn0); ls0 += c[nt][0];
            c[nt][1] = __expf(c[nt][1] - mn0); ls0 += c[nt][1];
            c[nt][2] = __expf(c[nt][2] - mn1); ls1 += c[nt][2];
            c[nt][3] = __expf(c[nt][3] - mn1); ls1 += c[nt][3];
        }
        ls0 += __shfl_xor_sync(0xffffffffu, ls0, 1);
        ls0 += __shfl_xor_sync(0xffffffffu, ls0, 2);
        ls1 += __shfl_xor_sync(0xffffffffu, ls1, 1);
        ls1 += __shfl_xor_sync(0xffffffffu, ls1, 2);
        l0s = l0s * al0 + ls0;
        l1s = l1s * al1 + ls1;

        // ---- pack P into A fragments (hi/lo) ----
        uint32_t ph[4][4], pl[4][4];
        #pragma unroll
        for (int kc2 = 0; kc2 < 4; kc2++) {
            split2(c[2*kc2][0],   c[2*kc2][1],   ph[kc2][0], pl[kc2][0]);
            split2(c[2*kc2][2],   c[2*kc2][3],   ph[kc2][1], pl[kc2][1]);
            split2(c[2*kc2+1][0], c[2*kc2+1][1], ph[kc2][2], pl[kc2][2]);
            split2(c[2*kc2+1][2], c[2*kc2+1][3], ph[kc2][3], pl[kc2][3]);
        }

        // ---- rescale O ----
        #pragma unroll
        for (int nt = 0; nt < 16; nt++) {
            o[nt][0] *= al0; o[nt][1] *= al0;
            o[nt][2] *= al1; o[nt][3] *= al1;
        }

        // ---- O += P V ----
        #pragma unroll
        for (int kc2 = 0; kc2 < 4; kc2++) {
            #pragma unroll
            for (int np = 0; np < 8; np++) {
                uint32_t vh0, vh1, vh2, vh3, vl0, vl1, vl2, vl3;
                uint32_t ad = vbh + (uint32_t)((np * 16 + b_row) * F_VST + kc2 * 16 + b_col) * 2;
                ldsm4(vh0, vh1, vh2, vh3, ad);
                ad = vbl + (uint32_t)((np * 16 + b_row) * F_VST + kc2 * 16 + b_col) * 2;
                ldsm4(vl0, vl1, vl2, vl3, ad);
                uint32_t bh0[2] = {vh0, vh1}, bh1[2] = {vh2, vh3};
                uint32_t bl0[2] = {vl0, vl1}, bl1[2] = {vl2, vl3};
                mma16816(o[2*np],   ph[kc2], bh0);
                mma16816(o[2*np+1], ph[kc2], bh1);
                mma16816(o[2*np],   ph[kc2], bl0);
                mma16816(o[2*np+1], ph[kc2], bl1);
                mma16816(o[2*np],   pl[kc2], bh0);
                mma16816(o[2*np+1], pl[kc2], bh1);
            }
        }
    }

    // ---- normalize + write ----
    const float il0 = 1.f / l0s, il1 = 1.f / l1s;
    const int rA = q0 + r0w + (lane >> 2);
    const int rB = rA + 8;
    #pragma unroll
    for (int nt = 0; nt < 16; nt++) {
        int col = h * HD + nt * 8 + (lane & 3) * 2;
        if (rA < S_TOT) {
            uint32_t hw, lw;
            split2(o[nt][0] * il0, o[nt][1] * il0, hw, lw);
            *(uint32_t*)(AOh + (size_t)rA * DIM + col) = hw;
            *(uint32_t*)(AOl + (size_t)rA * DIM + col) = lw;
        }
        if (rB < S_TOT) {
            uint32_t hw, lw;
            split2(o[nt][2] * il1, o[nt][3] * il1, hw, lw);
            *(uint32_t*)(AOh + (size_t)rB * DIM + col) = hw;
            *(uint32_t*)(AOl + (size_t)rB * DIM + col) = lw;
        }
    }
}

// ---------------- launch ----------------
extern "C" void kernel_launch(void* const* d_in, const int* in_sizes, int n_in,
                              void* d_out, int out_size) {
    const float* x        = (const float*)d_in[0];
    const int*   seq_lens = (const int*)  d_in[1];
    const int*   grid_sz  = (const int*)  d_in[2];
    const float* freqs    = (const float*)d_in[3];
    const float* Wq       = (const float*)d_in[4];
    const float* bq       = (const float*)d_in[5];
    const float* Wk       = (const float*)d_in[6];
    const float* bk       = (const float*)d_in[7];
    const float* Wv       = (const float*)d_in[8];
    const float* bv       = (const float*)d_in[9];
    const float* Wo       = (const float*)d_in[10];
    const float* bo       = (const float*)d_in[11];
    const float* gq       = (const float*)d_in[12];
    const float* gk       = (const float*)d_in[13];
    float* out = (float*)d_out;

    float *q, *k, *v;
    __nv_bfloat16 *xh, *xl, *qh, *ql, *kh, *kl, *aoh, *aol, *vth, *vtl;
    __nv_bfloat16 *wthq, *wtlq, *wthk, *wtlk, *wthv, *wtlv, *wtho, *wtlo;
    cudaGetSymbolAddress((void**)&q, g_q);
    cudaGetSymbolAddress((void**)&k, g_k);
    cudaGetSymbolAddress((void**)&v, g_v);
    cudaGetSymbolAddress((void**)&xh, g_xh);   cudaGetSymbolAddress((void**)&xl, g_xl);
    cudaGetSymbolAddress((void**)&qh, g_qh);   cudaGetSymbolAddress((void**)&ql, g_ql);
    cudaGetSymbolAddress((void**)&kh, g_kh);   cudaGetSymbolAddress((void**)&kl, g_kl);
    cudaGetSymbolAddress((void**)&aoh, g_aoh); cudaGetSymbolAddress((void**)&aol, g_aol);
    cudaGetSymbolAddress((void**)&vth, g_vth); cudaGetSymbolAddress((void**)&vtl, g_vtl);
    cudaGetSymbolAddress((void**)&wthq, g_wthq); cudaGetSymbolAddress((void**)&wtlq, g_wtlq);
    cudaGetSymbolAddress((void**)&wthk, g_wthk); cudaGetSymbolAddress((void**)&wtlk, g_wtlk);
    cudaGetSymbolAddress((void**)&wthv, g_wthv); cudaGetSymbolAddress((void**)&wtlv, g_wtlv);
    cudaGetSymbolAddress((void**)&wtho, g_wtho); cudaGetSymbolAddress((void**)&wtlo, g_wtlo);

    cudaFuncSetAttribute(gemm_mma, cudaFuncAttributeMaxDynamicSharedMemorySize, G_SMEM);
    cudaFuncSetAttribute(flash_mma, cudaFuncAttributeMaxDynamicSharedMemorySize, F_SMEM);

    // prep
    convert_x_kernel<<<S_TOT * DIM / 4 / 256, 256>>>(x, xh, xl);
    WPtrs wp;
    wp.w[0] = Wq; wp.th[0] = wthq; wp.tl[0] = wtlq;
    wp.w[1] = Wk; wp.th[1] = wthk; wp.tl[1] = wtlk;
    wp.w[2] = Wv; wp.th[2] = wthv; wp.tl[2] = wtlv;
    wp.w[3] = Wo; wp.th[3] = wtho; wp.tl[3] = wtlo;
    transw_kernel<<<dim3(48, 48, 4), dim3(32, 8)>>>(wp);

    // fused QKV projection
    QKVArgs aqkv;
    aqkv.bh[0] = wthq; aqkv.bl[0] = wtlq; aqkv.bias[0] = bq; aqkv.c[0] = q;
    aqkv.bh[1] = wthk; aqkv.bl[1] = wtlk; aqkv.bias[1] = bk; aqkv.c[1] = k;
    aqkv.bh[2] = wthv; aqkv.bl[2] = wtlv; aqkv.bias[2] = bv; aqkv.c[2] = v;
    gemm_mma<<<dim3(36, 31), 256, G_SMEM>>>(xh, xl, aqkv, S_TOT);

    rmsnorm_rope_conv<<<dim3(S_TOT, 2), 256>>>(q, gq, qh, ql, k, gk, kh, kl, freqs, grid_sz);
    transv_kernel<<<dim3(SP / 32, DIM / 32), dim3(32, 8)>>>(v, vth, vtl);

    dim3 fg(31, NH);
    flash_mma<<<fg, 256, F_SMEM>>>(qh, ql, kh, kl, vth, vtl, aoh, aol, seq_lens);

    // O projection
    QKVArgs aop;
    aop.bh[0] = wtho; aop.bl[0] = wtlo; aop.bias[0] = bo; aop.c[0] = out;
    aop.bh[1] = wtho; aop.bl[1] = wtlo; aop.bias[1] = bo; aop.c[1] = out;
    aop.bh[2] = wtho; aop.bl[2] = wtlo; aop.bias[2] = bo; aop.c[2] = out;
    gemm_mma<<<dim3(12, 31), 256, G_SMEM>>>(aoh, aol, aop, S_TOT);
}

// round 9
// speedup vs baseline: 17.4809x; 1.0575x over previous
#include <cuda_runtime.h>
#include <cuda_bf16.h>
#include <math.h>
#include <stdint.h>

#define S_TOT 3900
#define SP    3904        // padded seq (61*64)
#define DIM   1536
#define NH    12
#define HD    128
#define CC    64
#define NTILES 61         // SP/64

// ---------------- scratch ----------------
__device__ float g_q [S_TOT * DIM];   // q fp32, then flash partial half0
__device__ float g_k [S_TOT * DIM];   // k fp32, then flash partial half1
__device__ float g_stat[2 * NH * 2 * 4096];

__device__ __nv_bfloat16 g_xh [S_TOT * DIM];
__device__ __nv_bfloat16 g_xl [S_TOT * DIM];
__device__ __nv_bfloat16 g_qh [S_TOT * DIM];
__device__ __nv_bfloat16 g_ql [S_TOT * DIM];
__device__ __nv_bfloat16 g_kh [S_TOT * DIM];
__device__ __nv_bfloat16 g_kl [S_TOT * DIM];
__device__ __nv_bfloat16 g_aoh[S_TOT * DIM];
__device__ __nv_bfloat16 g_aol[S_TOT * DIM];
__device__ __nv_bfloat16 g_vth[DIM * SP];
__device__ __nv_bfloat16 g_vtl[DIM * SP];

__device__ __nv_bfloat16 g_wthq[DIM * DIM];
__device__ __nv_bfloat16 g_wtlq[DIM * DIM];
__device__ __nv_bfloat16 g_wthk[DIM * DIM];
__device__ __nv_bfloat16 g_wtlk[DIM * DIM];
__device__ __nv_bfloat16 g_wthv[DIM * DIM];
__device__ __nv_bfloat16 g_wtlv[DIM * DIM];
__device__ __nv_bfloat16 g_wtho[DIM * DIM];
__device__ __nv_bfloat16 g_wtlo[DIM * DIM];

// ================= helpers =================
__device__ __forceinline__ uint32_t smem_u32(const void* p) {
    uint32_t a;
    asm("{ .reg .u64 t; cvta.to.shared.u64 t, %1; cvt.u32.u64 %0, t; }" : "=r"(a) : "l"(p));
    return a;
}
__device__ __forceinline__ void ldsm4(uint32_t& r0, uint32_t& r1, uint32_t& r2, uint32_t& r3,
                                      uint32_t addr) {
    asm volatile("ldmatrix.sync.aligned.m8n8.x4.shared.b16 {%0,%1,%2,%3}, [%4];"
                 : "=r"(r0), "=r"(r1), "=r"(r2), "=r"(r3) : "r"(addr));
}
__device__ __forceinline__ void mma16816(float* c, const uint32_t* a, const uint32_t* b) {
    asm volatile(
        "mma.sync.aligned.m16n8k16.row.col.f32.bf16.bf16.f32 "
        "{%0,%1,%2,%3}, {%4,%5,%6,%7}, {%8,%9}, {%0,%1,%2,%3};"
        : "+f"(c[0]), "+f"(c[1]), "+f"(c[2]), "+f"(c[3])
        : "r"(a[0]), "r"(a[1]), "r"(a[2]), "r"(a[3]), "r"(b[0]), "r"(b[1]));
}
#define CP16(dst, src, sz) \
    asm volatile("cp.async.cg.shared.global [%0], [%1], 16, %2;" \
        :: "r"(dst), "l"(src), "r"(sz) : "memory")
#define CP_COMMIT() asm volatile("cp.async.commit_group;" ::: "memory")
#define CP_WAIT0()  asm volatile("cp.async.wait_group 0;" ::: "memory")

__device__ __forceinline__ uint32_t pack_bf(float lo, float hi) {
    __nv_bfloat162 t = __floats2bfloat162_rn(lo, hi);
    return *(uint32_t*)&t;
}
__device__ __forceinline__ void split2(float x, float y, uint32_t& hw, uint32_t& lw) {
    __nv_bfloat16 bx = __float2bfloat16(x), by = __float2bfloat16(y);
    __nv_bfloat162 hp; hp.x = bx; hp.y = by;
    hw = *(uint32_t*)&hp;
    lw = pack_bf(x - __bfloat162float(bx), y - __bfloat162float(by));
}
__device__ __forceinline__ void hilo(float x, unsigned short& h, unsigned short& l) {
    __nv_bfloat16 hb = __float2bfloat16(x);
    h = __bfloat16_as_ushort(hb);
    l = __bfloat16_as_ushort(__float2bfloat16(x - __bfloat162float(hb)));
}
#define STATIDX(half, hh, ml, s) ((((half) * NH + (hh)) * 2 + (ml)) * 4096 + (s))

// ================= prep kernels =================
__global__ __launch_bounds__(256)
void convert_x_kernel(const float* __restrict__ x,
                      __nv_bfloat16* __restrict__ xh, __nv_bfloat16* __restrict__ xl) {
    int i = blockIdx.x * 256 + threadIdx.x;
    const int tot4 = S_TOT * DIM / 4;
    if (i >= tot4) return;
    float4 v = ((const float4*)x)[i];
    unsigned short h0,l0,h1,l1,h2,l2,h3,l3;
    hilo(v.x,h0,l0); hilo(v.y,h1,l1); hilo(v.z,h2,l2); hilo(v.w,h3,l3);
    ((uint2*)xh)[i] = make_uint2((uint32_t)h0 | ((uint32_t)h1 << 16), (uint32_t)h2 | ((uint32_t)h3 << 16));
    ((uint2*)xl)[i] = make_uint2((uint32_t)l0 | ((uint32_t)l1 << 16), (uint32_t)l2 | ((uint32_t)l3 << 16));
}

// W[K][N] fp32 -> Wt[N][K] bf16 hi/lo ; 4 weights in one launch (blockIdx.z)
struct WPtrs { const float* w[4]; __nv_bfloat16* th[4]; __nv_bfloat16* tl[4]; };

__global__ __launch_bounds__(256)
void transw_kernel(WPtrs p) {
    __shared__ float t[32][33];
    const float* W = p.w[blockIdx.z];
    __nv_bfloat16* Th = p.th[blockIdx.z];
    __nv_bfloat16* Tl = p.tl[blockIdx.z];
    const int n0 = blockIdx.x * 32, k0 = blockIdx.y * 32;
    const int tx = threadIdx.x, ty = threadIdx.y;
    #pragma unroll
    for (int i = 0; i < 4; i++)
        t[ty + i * 8][tx] = W[(size_t)(k0 + ty + i * 8) * DIM + n0 + tx];
    __syncthreads();
    #pragma unroll
    for (int i = 0; i < 4; i++) {
        float v = t[tx][ty + i * 8];
        unsigned short h, l; hilo(v, h, l);
        size_t o = (size_t)(n0 + ty + i * 8) * DIM + k0 + tx;
        Th[o] = __ushort_as_bfloat16(h);
        Tl[o] = __ushort_as_bfloat16(l);
    }
}

// RMSNorm + RoPE for q and k in one launch (blockIdx.y)
__global__ __launch_bounds__(256)
void rmsnorm_rope_conv(const float* __restrict__ tq, const float* __restrict__ gq,
                       __nv_bfloat16* __restrict__ qoh, __nv_bfloat16* __restrict__ qol,
                       const float* __restrict__ tk, const float* __restrict__ gk,
                       __nv_bfloat16* __restrict__ koh, __nv_bfloat16* __restrict__ kol,
                       const float* __restrict__ freqs, const int* __restrict__ grid_sizes) {
    const int s = blockIdx.x;
    const int tid = threadIdx.x;
    const float* t  = (blockIdx.y == 0) ? tq : tk;
    const float* g  = (blockIdx.y == 0) ? gq : gk;
    __nv_bfloat16* oh = (blockIdx.y == 0) ? qoh : koh;
    __nv_bfloat16* ol = (blockIdx.y == 0) ? qol : kol;
    const float* row = t + (size_t)s * DIM;

    float ss = 0.f;
    for (int i = tid; i < DIM; i += 256) { float v = row[i]; ss += v * v; }
    #pragma unroll
    for (int off = 16; off; off >>= 1) ss += __shfl_xor_sync(0xffffffffu, ss, off);
    __shared__ float red[8];
    if ((tid & 31) == 0) red[tid >> 5] = ss;
    __syncthreads();
    if (tid == 0) {
        float tot = 0.f;
        #pragma unroll
        for (int i = 0; i < 8; i++) tot += red[i];
        red[0] = tot;
    }
    __syncthreads();
    const float inv = rsqrtf(red[0] * (1.f / DIM) + 1e-6f);

    const int H = grid_sizes[1], W = grid_sizes[2];
    const int fi = s / (H * W);
    const int rem = s % (H * W);
    const int hi = rem / W;
    const int wi = rem % W;
    const int c3 = CC / 3, c0 = CC - 2 * c3;

    for (int p = tid; p < NH * CC; p += 256) {
        int j = p % CC;
        int head = p / CC;
        int idx = head * HD + 2 * j;
        float a = row[idx]     * inv * g[idx];
        float b = row[idx + 1] * inv * g[idx + 1];
        int pos = (j < c0) ? fi : ((j < c0 + c3) ? hi : wi);
        float cs = freqs[(pos * CC + j) * 2 + 0];
        float sn = freqs[(pos * CC + j) * 2 + 1];
        float ra = a * cs - b * sn;
        float rb = a * sn + b * cs;
        uint32_t hw, lw;
        split2(ra, rb, hw, lw);
        *(uint32_t*)(oh + (size_t)s * DIM + idx) = hw;
        *(uint32_t*)(ol + (size_t)s * DIM + idx) = lw;
    }
}

// ================= HMMA GEMM (cp.async double-buffered, multi-weight) =================
#define G_ST   40
#define G_BUFB 10240
#define G_ASH  0
#define G_ASL  20480
#define G_BSH  40960
#define G_BSL  61440
#define G_SMEM 81920
#define VT_ST  136          // transposed V staging stride (bf16 elems)

struct QKVArgs {
    const __nv_bfloat16* bh[3];
    const __nv_bfloat16* bl[3];
    const float* bias[3];
    float* c[3];
    __nv_bfloat16* vth;     // if non-null: mat==2 writes transposed bf16 hi/lo
    __nv_bfloat16* vtl;
};

__global__ __launch_bounds__(256)
void gemm_mma(const __nv_bfloat16* __restrict__ Ah, const __nv_bfloat16* __restrict__ Al,
              QKVArgs args, int M) {
    extern __shared__ char smc[];
    const uint32_t sb = smem_u32(smc);
    const int tid = threadIdx.x;
    const int lane = tid & 31;
    const int wid = tid >> 5;
    const int wm = wid & 1;
    const int wn = wid >> 1;
    const int mat = blockIdx.x / 12;
    const int n0 = (blockIdx.x % 12) * 128;
    const int m0 = blockIdx.y * 128;
    const __nv_bfloat16* Bh = args.bh[mat];
    const __nv_bfloat16* Bl = args.bl[mat];
    const float* bias = args.bias[mat];
    float* C = args.c[mat];

    float c[4][4][4];
    #pragma unroll
    for (int i = 0; i < 4; i++)
        #pragma unroll
        for (int j = 0; j < 4; j++)
            #pragma unroll
            for (int q = 0; q < 4; q++) c[i][j][q] = 0.f;

    auto stage = [&](int kt, int buf) {
        const int k0 = kt * 32;
        #pragma unroll
        for (int cix = 0; cix < 2; cix++) {
            int ch = tid + cix * 256;           // 0..511
            int row = ch >> 2, cc = (ch & 3) * 8;
            uint32_t so = (uint32_t)(row * G_ST + cc) * 2 + (uint32_t)buf * G_BUFB;
            int szA = (m0 + row < M) ? 16 : 0;
            const __nv_bfloat16* pah = Ah + (size_t)(m0 + row) * DIM + k0 + cc;
            const __nv_bfloat16* pal = Al + (size_t)(m0 + row) * DIM + k0 + cc;
            const __nv_bfloat16* pbh = Bh + (size_t)(n0 + row) * DIM + k0 + cc;
            const __nv_bfloat16* pbl = Bl + (size_t)(n0 + row) * DIM + k0 + cc;
            CP16(sb + G_ASH + so, pah, szA);
            CP16(sb + G_ASL + so, pal, szA);
            CP16(sb + G_BSH + so, pbh, 16);
            CP16(sb + G_BSL + so, pbl, 16);
        }
        CP_COMMIT();
    };

    stage(0, 0);

    const int a_row = (lane & 15);
    const int a_col = ((lane >> 1) & 8);
    const int b_row = (lane & 7) + ((lane & 16) >> 1);
    const int b_col = (lane & 8);

    for (int kt = 0; kt < 48; kt++) {
        CP_WAIT0();
        __syncthreads();
        if (kt < 47) stage(kt + 1, (kt + 1) & 1);
        const int bo = (kt & 1) * G_BUFB;
        #pragma unroll
        for (int kc = 0; kc < 32; kc += 16) {
            uint32_t af[4][4], bfh[4][2], bfl[4][2];
            #pragma unroll
            for (int mt = 0; mt < 4; mt++)
                ldsm4(af[mt][0], af[mt][1], af[mt][2], af[mt][3],
                      sb + G_ASH + bo + (uint32_t)((wm * 64 + mt * 16 + a_row) * G_ST + kc + a_col) * 2);
            #pragma unroll
            for (int np = 0; np < 2; np++) {
                uint32_t r0, r1, r2, r3;
                uint32_t ad = sb + G_BSH + bo +
                    (uint32_t)((wn * 32 + np * 16 + b_row) * G_ST + kc + b_col) * 2;
                ldsm4(r0, r1, r2, r3, ad);
                bfh[np*2][0] = r0; bfh[np*2][1] = r1; bfh[np*2+1][0] = r2; bfh[np*2+1][1] = r3;
                ad = sb + G_BSL + bo +
                    (uint32_t)((wn * 32 + np * 16 + b_row) * G_ST + kc + b_col) * 2;
                ldsm4(r0, r1, r2, r3, ad);
                bfl[np*2][0] = r0; bfl[np*2][1] = r1; bfl[np*2+1][0] = r2; bfl[np*2+1][1] = r3;
            }
            #pragma unroll
            for (int mt = 0; mt < 4; mt++)
                #pragma unroll
                for (int nt = 0; nt < 4; nt++) {
                    mma16816(c[mt][nt], af[mt], bfh[nt]);
                    mma16816(c[mt][nt], af[mt], bfl[nt]);
                }
            #pragma unroll
            for (int mt = 0; mt < 4; mt++)
                ldsm4(af[mt][0], af[mt][1], af[mt][2], af[mt][3],
                      sb + G_ASL + bo + (uint32_t)((wm * 64 + mt * 16 + a_row) * G_ST + kc + a_col) * 2);
            #pragma unroll
            for (int mt = 0; mt < 4; mt++)
                #pragma unroll
                for (int nt = 0; nt < 4; nt++)
                    mma16816(c[mt][nt], af[mt], bfh[nt]);
        }
        __syncthreads();
    }

    if (args.vth != nullptr && mat == 2) {
        // ---- V epilogue: transposed bf16 hi/lo via smem staging ----
        #pragma unroll
        for (int mt = 0; mt < 4; mt++) {
            #pragma unroll
            for (int nt = 0; nt < 4; nt++) {
                int row0 = wm * 64 + mt * 16 + (lane >> 2);
                int coll = wn * 32 + nt * 8 + (lane & 3) * 2;
                float b0 = bias[n0 + coll], b1 = bias[n0 + coll + 1];
                float v00 = c[mt][nt][0] + b0, v01 = c[mt][nt][1] + b1;
                float v10 = c[mt][nt][2] + b0, v11 = c[mt][nt][3] + b1;
                unsigned short hh, ll;
                __nv_bfloat16* TH = (__nv_bfloat16*)smc;
                __nv_bfloat16* TL = (__nv_bfloat16*)(smc + 34816);
                hilo(v00, hh, ll);
                TH[coll * VT_ST + row0] = __ushort_as_bfloat16(hh);
                TL[coll * VT_ST + row0] = __ushort_as_bfloat16(ll);
                hilo(v01, hh, ll);
                TH[(coll + 1) * VT_ST + row0] = __ushort_as_bfloat16(hh);
                TL[(coll + 1) * VT_ST + row0] = __ushort_as_bfloat16(ll);
                hilo(v10, hh, ll);
                TH[coll * VT_ST + row0 + 8] = __ushort_as_bfloat16(hh);
                TL[coll * VT_ST + row0 + 8] = __ushort_as_bfloat16(ll);
                hilo(v11, hh, ll);
                TH[(coll + 1) * VT_ST + row0 + 8] = __ushort_as_bfloat16(hh);
                TL[(coll + 1) * VT_ST + row0 + 8] = __ushort_as_bfloat16(ll);
            }
        }
        __syncthreads();
        #pragma unroll
        for (int it = 0; it < 8; it++) {
            int ch = tid + it * 256;         // 0..2047
            int drow = ch >> 4;
            int c8 = (ch & 15) * 8;
            if (m0 + c8 + 8 <= SP) {         // guard: last M-block overhangs SP
                uint4 vh = *(uint4*)(smc + (uint32_t)(drow * VT_ST + c8) * 2);
                uint4 vl = *(uint4*)(smc + 34816 + (uint32_t)(drow * VT_ST + c8) * 2);
                *(uint4*)(args.vth + (size_t)(n0 + drow) * SP + m0 + c8) = vh;
                *(uint4*)(args.vtl + (size_t)(n0 + drow) * SP + m0 + c8) = vl;
            }
        }
    } else {
        #pragma unroll
        for (int mt = 0; mt < 4; mt++) {
            #pragma unroll
            for (int nt = 0; nt < 4; nt++) {
                int row = m0 + wm * 64 + mt * 16 + (lane >> 2);
                int col = n0 + wn * 32 + nt * 8 + (lane & 3) * 2;
                float b0 = bias[col], b1 = bias[col + 1];
                if (row < M)
                    *(float2*)&C[(size_t)row * DIM + col] =
                        make_float2(c[mt][nt][0] + b0, c[mt][nt][1] + b1);
                if (row + 8 < M)
                    *(float2*)&C[(size_t)(row + 8) * DIM + col] =
                        make_float2(c[mt][nt][2] + b0, c[mt][nt][3] + b1);
            }
        }
    }
}

// ================= HMMA flash attention (split-KV, double-buffered K/V) =================
#define F_QST 136
#define F_VST 72
#define F_QH   0
#define F_QL   34816
#define F_STG  69632
#define F_STGB 71680          // KH 17408 | KL 17408 | VTH 18432 | VTL 18432
#define F_SMEM (F_STG + 2 * F_STGB)   // 212992

__global__ __launch_bounds__(256, 1)
void flash_mma(const __nv_bfloat16* __restrict__ Qh, const __nv_bfloat16* __restrict__ Ql,
               const __nv_bfloat16* __restrict__ Kh, const __nv_bfloat16* __restrict__ Kl,
               const __nv_bfloat16* __restrict__ Vh, const __nv_bfloat16* __restrict__ Vl,
               float* __restrict__ O0, float* __restrict__ O1,
               float* __restrict__ stat, const int* __restrict__ seq_lens) {
    extern __shared__ char smc[];
    const uint32_t sb = smem_u32(smc);
    const int tid = threadIdx.x;
    const int lane = tid & 31;
    const int wid = tid >> 5;
    const int r0w = wid * 16;
    const int h = blockIdx.y;
    const int q0 = blockIdx.x * 128;
    const int half = blockIdx.z;
    const int t_begin = half * 31;
    const int t_cnt = half ? (NTILES - 31) : 31;
    const int seqlen = seq_lens[0];
    const float scale2 = 0.08838834764831845f * 1.4426950408889634f;  // /sqrt(128)*log2(e)

    // ---- load Q tile [128 x 128] hi/lo ----
    #pragma unroll
    for (int cix = 0; cix < 8; cix++) {
        int ch = tid + cix * 256;
        int row = ch >> 4, cc = (ch & 15) * 8;
        uint32_t so = (uint32_t)(row * F_QST + cc) * 2;
        uint4 vh = make_uint4(0,0,0,0), vl = make_uint4(0,0,0,0);
        if (q0 + row < S_TOT) {
            size_t gq = (size_t)(q0 + row) * DIM + h * HD + cc;
            vh = *(const uint4*)(Qh + gq);
            vl = *(const uint4*)(Ql + gq);
        }
        *(uint4*)(smc + F_QH + so) = vh;
        *(uint4*)(smc + F_QL + so) = vl;
    }

    auto kv_stage = [&](int gt, int buf) {
        const int k0 = gt * 64;
        const uint32_t base = sb + F_STG + (uint32_t)buf * F_STGB;
        #pragma unroll
        for (int cix = 0; cix < 4; cix++) {
            int ch = tid + cix * 256;            // 0..1023
            {
                int row = ch >> 4, cc = (ch & 15) * 8;
                uint32_t so = (uint32_t)(row * F_QST + cc) * 2;
                int sz = (k0 + row < S_TOT) ? 16 : 0;
                const __nv_bfloat16* gh = Kh + (size_t)(k0 + row) * DIM + h * HD + cc;
                const __nv_bfloat16* gl = Kl + (size_t)(k0 + row) * DIM + h * HD + cc;
                CP16(base + so, gh, sz);
                CP16(base + 17408 + so, gl, sz);
            }
            {
                int row = ch >> 3, cc = (ch & 7) * 8;
                uint32_t so = (uint32_t)(row * F_VST + cc) * 2;
                const __nv_bfloat16* gvh = Vh + (size_t)(h * HD + row) * SP + k0 + cc;
                const __nv_bfloat16* gvl = Vl + (size_t)(h * HD + row) * SP + k0 + cc;
                CP16(base + 34816 + so, gvh, 16);
                CP16(base + 53248 + so, gvl, 16);
            }
        }
        CP_COMMIT();
    };

    kv_stage(t_begin, 0);

    float m0s = -1e30f, m1s = -1e30f, l0s = 0.f, l1s = 0.f;
    float o[16][4];
    #pragma unroll
    for (int i = 0; i < 16; i++)
        #pragma unroll
        for (int j = 0; j < 4; j++) o[i][j] = 0.f;

    const int a_row = (lane & 15);
    const int a_col = ((lane >> 1) & 8);
    const int b_row = (lane & 7) + ((lane & 16) >> 1);
    const int b_col = (lane & 8);

    for (int lt = 0; lt < t_cnt; lt++) {
        const int gt = t_begin + lt;
        const int k0 = gt * 64;
        CP_WAIT0();
        __syncthreads();
        if (lt + 1 < t_cnt) kv_stage(gt + 1, (lt + 1) & 1);

        const uint32_t kb = sb + F_STG + (uint32_t)(lt & 1) * F_STGB;
        const uint32_t kbh = kb, kbl = kb + 17408;
        const uint32_t vbh = kb + 34816, vbl = kb + 53248;

        // ---- S = Q K^T ----
        float c[8][4];
        #pragma unroll
        for (int nt = 0; nt < 8; nt++)
            #pragma unroll
            for (int j = 0; j < 4; j++) c[nt][j] = 0.f;

        #pragma unroll
        for (int kc8 = 0; kc8 < 8; kc8++) {
            const int kc = kc8 * 16;
            uint32_t aq[4], bkh[8][2], bkl[8][2];
            ldsm4(aq[0], aq[1], aq[2], aq[3],
                  sb + F_QH + (uint32_t)((r0w + a_row) * F_QST + kc + a_col) * 2);
            #pragma unroll
            for (int np = 0; np < 4; np++) {
                uint32_t r0, r1, r2, r3;
                ldsm4(r0, r1, r2, r3,
                      kbh + (uint32_t)((np * 16 + b_row) * F_QST + kc + b_col) * 2);
                bkh[np*2][0] = r0; bkh[np*2][1] = r1; bkh[np*2+1][0] = r2; bkh[np*2+1][1] = r3;
                ldsm4(r0, r1, r2, r3,
                      kbl + (uint32_t)((np * 16 + b_row) * F_QST + kc + b_col) * 2);
                bkl[np*2][0] = r0; bkl[np*2][1] = r1; bkl[np*2+1][0] = r2; bkl[np*2+1][1] = r3;
            }
            #pragma unroll
            for (int nt = 0; nt < 8; nt++) {
                mma16816(c[nt], aq, bkh[nt]);
                mma16816(c[nt], aq, bkl[nt]);
            }
            ldsm4(aq[0], aq[1], aq[2], aq[3],
                  sb + F_QL + (uint32_t)((r0w + a_row) * F_QST + kc + a_col) * 2);
            #pragma unroll
            for (int nt = 0; nt < 8; nt++)
                mma16816(c[nt], aq, bkh[nt]);
        }

        // ---- scale (log2 domain) + mask ----
        #pragma unroll
        for (int nt = 0; nt < 8; nt++) {
            int colb = k0 + nt * 8 + (lane & 3) * 2;
            #pragma unroll
            for (int j = 0; j < 4; j++) {
                float v = c[nt][j] * scale2;
                c[nt][j] = (colb + (j & 1) < seqlen) ? v : -1e30f;
            }
        }

        // ---- online softmax (exp2) ----
        float mx0 = -1e30f, mx1 = -1e30f;
        #pragma unroll
        for (int nt = 0; nt < 8; nt++) {
            mx0 = fmaxf(mx0, fmaxf(c[nt][0], c[nt][1]));
            mx1 = fmaxf(mx1, fmaxf(c[nt][2], c[nt][3]));
        }
        mx0 = fmaxf(mx0, __shfl_xor_sync(0xffffffffu, mx0, 1));
        mx0 = fmaxf(mx0, __shfl_xor_sync(0xffffffffu, mx0, 2));
        mx1 = fmaxf(mx1, __shfl_xor_sync(0xffffffffu, mx1, 1));
        mx1 = fmaxf(mx1, __shfl_xor_sync(0xffffffffu, mx1, 2));
        float mn0 = fmaxf(m0s, mx0), mn1 = fmaxf(m1s, mx1);
        float al0 = exp2f(m0s - mn0), al1 = exp2f(m1s - mn1);
        m0s = mn0; m1s = mn1;
        float ls0 = 0.f, ls1 = 0.f;
        #pragma unroll
        for (int nt = 0; nt < 8; nt++) {
            c[nt][0] = exp2f(c[nt][0] - mn0); ls0 += c[nt][0];
            c[nt][1] = exp2f(c[nt][1] - mn0); ls0 += c[nt][1];
            c[nt][2] = exp2f(c[nt][2] - mn1); ls1 += c[nt][2];
            c[nt][3] = exp2f(c[nt][3] - mn1); ls1 += c[nt][3];
        }
        ls0 += __shfl_xor_sync(0xffffffffu, ls0, 1);
        ls0 += __shfl_xor_sync(0xffffffffu, ls0, 2);
        ls1 += __shfl_xor_sync(0xffffffffu, ls1, 1);
        ls1 += __shfl_xor_sync(0xffffffffu, ls1, 2);
        l0s = l0s * al0 + ls0;
        l1s = l1s * al1 + ls1;

        // ---- pack P into A fragments (hi/lo) ----
        uint32_t ph[4][4], pl[4][4];
        #pragma unroll
        for (int kc2 = 0; kc2 < 4; kc2++) {
            split2(c[2*kc2][0],   c[2*kc2][1],   ph[kc2][0], pl[kc2][0]);
            split2(c[2*kc2][2],   c[2*kc2][3],   ph[kc2][1], pl[kc2][1]);
            split2(c[2*kc2+1][0], c[2*kc2+1][1], ph[kc2][2], pl[kc2][2]);
            split2(c[2*kc2+1][2], c[2*kc2+1][3], ph[kc2][3], pl[kc2][3]);
        }

        // ---- rescale O ----
        #pragma unroll
        for (int nt = 0; nt < 16; nt++) {
            o[nt][0] *= al0; o[nt][1] *= al0;
            o[nt][2] *= al1; o[nt][3] *= al1;
        }

        // ---- O += P V ----
        #pragma unroll
        for (int kc2 = 0; kc2 < 4; kc2++) {
            #pragma unroll
            for (int np = 0; np < 8; np++) {
                uint32_t vh0, vh1, vh2, vh3, vl0, vl1, vl2, vl3;
                uint32_t ad = vbh + (uint32_t)((np * 16 + b_row) * F_VST + kc2 * 16 + b_col) * 2;
                ldsm4(vh0, vh1, vh2, vh3, ad);
                ad = vbl + (uint32_t)((np * 16 + b_row) * F_VST + kc2 * 16 + b_col) * 2;
                ldsm4(vl0, vl1, vl2, vl3, ad);
                uint32_t bh0[2] = {vh0, vh1}, bh1[2] = {vh2, vh3};
                uint32_t bl0[2] = {vl0, vl1}, bl1[2] = {vl2, vl3};
                mma16816(o[2*np],   ph[kc2], bh0);
                mma16816(o[2*np+1], ph[kc2], bh1);
                mma16816(o[2*np],   ph[kc2], bl0);
                mma16816(o[2*np+1], ph[kc2], bl1);
                mma16816(o[2*np],   pl[kc2], bh0);
                mma16816(o[2*np+1], pl[kc2], bh1);
            }
        }
    }

    // ---- write UNNORMALIZED partial + stats ----
    float* Op = half ? O1 : O0;
    const int rA = q0 + r0w + (lane >> 2);
    const int rB = rA + 8;
    #pragma unroll
    for (int nt = 0; nt < 16; nt++) {
        int col = h * HD + nt * 8 + (lane & 3) * 2;
        if (rA < S_TOT)
            *(float2*)&Op[(size_t)rA * DIM + col] = make_float2(o[nt][0], o[nt][1]);
        if (rB < S_TOT)
            *(float2*)&Op[(size_t)rB * DIM + col] = make_float2(o[nt][2], o[nt][3]);
    }
    if ((lane & 3) == 0) {
        if (rA < S_TOT) {
            stat[STATIDX(half, h, 0, rA)] = m0s;
            stat[STATIDX(half, h, 1, rA)] = l0s;
        }
        if (rB < S_TOT) {
            stat[STATIDX(half, h, 0, rB)] = m1s;
            stat[STATIDX(half, h, 1, rB)] = l1s;
        }
    }
}

// ================= combine split-KV partials =================
__global__ __launch_bounds__(128)
void combine_kernel(const float* __restrict__ O0, const float* __restrict__ O1,
                    const float* __restrict__ stat,
                    __nv_bfloat16* __restrict__ AOh, __nv_bfloat16* __restrict__ AOl) {
    const int s = blockIdx.x;
    const int h = blockIdx.y;
    const int c = threadIdx.x;
    float mA = stat[STATIDX(0, h, 0, s)], lA = stat[STATIDX(0, h, 1, s)];
    float mB = stat[STATIDX(1, h, 0, s)], lB = stat[STATIDX(1, h, 1, s)];
    float m = fmaxf(mA, mB);
    float aA = exp2f(mA - m), aB = exp2f(mB - m);
    float inv = 1.f / (lA * aA + lB * aB);
    size_t idx = (size_t)s * DIM + h * HD + c;
    float o = (O0[idx] * aA + O1[idx] * aB) * inv;
    unsigned short hh, ll;
    hilo(o, hh, ll);
    AOh[idx] = __ushort_as_bfloat16(hh);
    AOl[idx] = __ushort_as_bfloat16(ll);
}

// ---------------- launch ----------------
extern "C" void kernel_launch(void* const* d_in, const int* in_sizes, int n_in,
                              void* d_out, int out_size) {
    const float* x        = (const float*)d_in[0];
    const int*   seq_lens = (const int*)  d_in[1];
    const int*   grid_sz  = (const int*)  d_in[2];
    const float* freqs    = (const float*)d_in[3];
    const float* Wq       = (const float*)d_in[4];
    const float* bq       = (const float*)d_in[5];
    const float* Wk       = (const float*)d_in[6];
    const float* bk       = (const float*)d_in[7];
    const float* Wv       = (const float*)d_in[8];
    const float* bv       = (const float*)d_in[9];
    const float* Wo       = (const float*)d_in[10];
    const float* bo       = (const float*)d_in[11];
    const float* gq       = (const float*)d_in[12];
    const float* gk       = (const float*)d_in[13];
    float* out = (float*)d_out;

    float *q, *k, *stat;
    __nv_bfloat16 *xh, *xl, *qh, *ql, *kh, *kl, *aoh, *aol, *vth, *vtl;
    __nv_bfloat16 *wthq, *wtlq, *wthk, *wtlk, *wthv, *wtlv, *wtho, *wtlo;
    cudaGetSymbolAddress((void**)&q, g_q);
    cudaGetSymbolAddress((void**)&k, g_k);
    cudaGetSymbolAddress((void**)&stat, g_stat);
    cudaGetSymbolAddress((void**)&xh, g_xh);   cudaGetSymbolAddress((void**)&xl, g_xl);
    cudaGetSymbolAddress((void**)&qh, g_qh);   cudaGetSymbolAddress((void**)&ql, g_ql);
    cudaGetSymbolAddress((void**)&kh, g_kh);   cudaGetSymbolAddress((void**)&kl, g_kl);
    cudaGetSymbolAddress((void**)&aoh, g_aoh); cudaGetSymbolAddress((void**)&aol, g_aol);
    cudaGetSymbolAddress((void**)&vth, g_vth); cudaGetSymbolAddress((void**)&vtl, g_vtl);
    cudaGetSymbolAddress((void**)&wthq, g_wthq); cudaGetSymbolAddress((void**)&wtlq, g_wtlq);
    cudaGetSymbolAddress((void**)&wthk, g_wthk); cudaGetSymbolAddress((void**)&wtlk, g_wtlk);
    cudaGetSymbolAddress((void**)&wthv, g_wthv); cudaGetSymbolAddress((void**)&wtlv, g_wtlv);
    cudaGetSymbolAddress((void**)&wtho, g_wtho); cudaGetSymbolAddress((void**)&wtlo, g_wtlo);

    cudaFuncSetAttribute(gemm_mma, cudaFuncAttributeMaxDynamicSharedMemorySize, G_SMEM);
    cudaFuncSetAttribute(flash_mma, cudaFuncAttributeMaxDynamicSharedMemorySize, F_SMEM);

    // prep
    convert_x_kernel<<<S_TOT * DIM / 4 / 256, 256>>>(x, xh, xl);
    WPtrs wp;
    wp.w[0] = Wq; wp.th[0] = wthq; wp.tl[0] = wtlq;
    wp.w[1] = Wk; wp.th[1] = wthk; wp.tl[1] = wtlk;
    wp.w[2] = Wv; wp.th[2] = wthv; wp.tl[2] = wtlv;
    wp.w[3] = Wo; wp.th[3] = wtho; wp.tl[3] = wtlo;
    transw_kernel<<<dim3(48, 48, 4), dim3(32, 8)>>>(wp);

    // fused QKV projection; V written directly as transposed bf16 hi/lo
    QKVArgs aqkv;
    aqkv.bh[0] = wthq; aqkv.bl[0] = wtlq; aqkv.bias[0] = bq; aqkv.c[0] = q;
    aqkv.bh[1] = wthk; aqkv.bl[1] = wtlk; aqkv.bias[1] = bk; aqkv.c[1] = k;
    aqkv.bh[2] = wthv; aqkv.bl[2] = wtlv; aqkv.bias[2] = bv; aqkv.c[2] = nullptr;
    aqkv.vth = vth; aqkv.vtl = vtl;
    gemm_mma<<<dim3(36, 31), 256, G_SMEM>>>(xh, xl, aqkv, S_TOT);

    rmsnorm_rope_conv<<<dim3(S_TOT, 2), 256>>>(q, gq, qh, ql, k, gk, kh, kl, freqs, grid_sz);

    // split-KV flash: half 0 -> g_q, half 1 -> g_k (both free now)
    dim3 fg(31, NH, 2);
    flash_mma<<<fg, 256, F_SMEM>>>(qh, ql, kh, kl, vth, vtl, q, k, stat, seq_lens);
    combine_kernel<<<dim3(S_TOT, NH), 128>>>(q, k, stat, aoh, aol);

    // O projection
    QKVArgs aop;
    aop.bh[0] = wtho; aop.bl[0] = wtlo; aop.bias[0] = bo; aop.c[0] = out;
    aop.bh[1] = wtho; aop.bl[1] = wtlo; aop.bias[1] = bo; aop.c[1] = out;
    aop.bh[2] = wtho; aop.bl[2] = wtlo; aop.bias[2] = bo; aop.c[2] = out;
    aop.vth = nullptr; aop.vtl = nullptr;
    gemm_mma<<<dim3(12, 31), 256, G_SMEM>>>(aoh, aol, aop, S_TOT);
}

// round 10
// speedup vs baseline: 18.7280x; 1.0713x over previous
#include <cuda_runtime.h>
#include <cuda_bf16.h>
#include <math.h>
#include <stdint.h>

#define S_TOT 3900
#define SP    3904        // padded seq (61*64)
#define DIM   1536
#define NH    12
#define HD    128
#define CC    64
#define NTILES 61         // SP/64
#define NSPLIT 3          // flash KV splits

// ---------------- scratch ----------------
__device__ float g_q [S_TOT * DIM];   // q fp32 -> flash partial 0 -> O-proj split-K partial 0
__device__ float g_k [S_TOT * DIM];   // k fp32 -> flash partial 1 -> O-proj split-K partial 1
__device__ float g_o2[S_TOT * DIM];   // v fp32 unused; flash partial 2
__device__ float g_stat[NSPLIT * NH * 2 * 4096];

__device__ __nv_bfloat16 g_xh [S_TOT * DIM];
__device__ __nv_bfloat16 g_xl [S_TOT * DIM];
__device__ __nv_bfloat16 g_qh [S_TOT * DIM];
__device__ __nv_bfloat16 g_ql [S_TOT * DIM];
__device__ __nv_bfloat16 g_kh [S_TOT * DIM];
__device__ __nv_bfloat16 g_kl [S_TOT * DIM];
__device__ __nv_bfloat16 g_aoh[S_TOT * DIM];
__device__ __nv_bfloat16 g_aol[S_TOT * DIM];
__device__ __nv_bfloat16 g_vth[DIM * SP];
__device__ __nv_bfloat16 g_vtl[DIM * SP];

__device__ __nv_bfloat16 g_wthq[DIM * DIM];
__device__ __nv_bfloat16 g_wtlq[DIM * DIM];
__device__ __nv_bfloat16 g_wthk[DIM * DIM];
__device__ __nv_bfloat16 g_wtlk[DIM * DIM];
__device__ __nv_bfloat16 g_wthv[DIM * DIM];
__device__ __nv_bfloat16 g_wtlv[DIM * DIM];
__device__ __nv_bfloat16 g_wtho[DIM * DIM];
__device__ __nv_bfloat16 g_wtlo[DIM * DIM];

// ================= helpers =================
__device__ __forceinline__ uint32_t smem_u32(const void* p) {
    uint32_t a;
    asm("{ .reg .u64 t; cvta.to.shared.u64 t, %1; cvt.u32.u64 %0, t; }" : "=r"(a) : "l"(p));
    return a;
}
__device__ __forceinline__ void ldsm4(uint32_t& r0, uint32_t& r1, uint32_t& r2, uint32_t& r3,
                                      uint32_t addr) {
    asm volatile("ldmatrix.sync.aligned.m8n8.x4.shared.b16 {%0,%1,%2,%3}, [%4];"
                 : "=r"(r0), "=r"(r1), "=r"(r2), "=r"(r3) : "r"(addr));
}
__device__ __forceinline__ void mma16816(float* c, const uint32_t* a, const uint32_t* b) {
    asm volatile(
        "mma.sync.aligned.m16n8k16.row.col.f32.bf16.bf16.f32 "
        "{%0,%1,%2,%3}, {%4,%5,%6,%7}, {%8,%9}, {%0,%1,%2,%3};"
        : "+f"(c[0]), "+f"(c[1]), "+f"(c[2]), "+f"(c[3])
        : "r"(a[0]), "r"(a[1]), "r"(a[2]), "r"(a[3]), "r"(b[0]), "r"(b[1]));
}
#define CP16(dst, src, sz) \
    asm volatile("cp.async.cg.shared.global [%0], [%1], 16, %2;" \
        :: "r"(dst), "l"(src), "r"(sz) : "memory")
#define CP_COMMIT() asm volatile("cp.async.commit_group;" ::: "memory")
#define CP_WAIT0()  asm volatile("cp.async.wait_group 0;" ::: "memory")

__device__ __forceinline__ uint32_t pack_bf(float lo, float hi) {
    __nv_bfloat162 t = __floats2bfloat162_rn(lo, hi);
    return *(uint32_t*)&t;
}
__device__ __forceinline__ void split2(float x, float y, uint32_t& hw, uint32_t& lw) {
    __nv_bfloat16 bx = __float2bfloat16(x), by = __float2bfloat16(y);
    __nv_bfloat162 hp; hp.x = bx; hp.y = by;
    hw = *(uint32_t*)&hp;
    lw = pack_bf(x - __bfloat162float(bx), y - __bfloat162float(by));
}
__device__ __forceinline__ void hilo(float x, unsigned short& h, unsigned short& l) {
    __nv_bfloat16 hb = __float2bfloat16(x);
    h = __bfloat16_as_ushort(hb);
    l = __bfloat16_as_ushort(__float2bfloat16(x - __bfloat162float(hb)));
}
#define STATIDX(sp, hh, ml, s) ((((sp) * NH + (hh)) * 2 + (ml)) * 4096 + (s))

// ================= prep kernels =================
__global__ __launch_bounds__(256)
void convert_x_kernel(const float* __restrict__ x,
                      __nv_bfloat16* __restrict__ xh, __nv_bfloat16* __restrict__ xl) {
    int i = blockIdx.x * 256 + threadIdx.x;
    const int tot4 = S_TOT * DIM / 4;
    if (i >= tot4) return;
    float4 v = ((const float4*)x)[i];
    unsigned short h0,l0,h1,l1,h2,l2,h3,l3;
    hilo(v.x,h0,l0); hilo(v.y,h1,l1); hilo(v.z,h2,l2); hilo(v.w,h3,l3);
    ((uint2*)xh)[i] = make_uint2((uint32_t)h0 | ((uint32_t)h1 << 16), (uint32_t)h2 | ((uint32_t)h3 << 16));
    ((uint2*)xl)[i] = make_uint2((uint32_t)l0 | ((uint32_t)l1 << 16), (uint32_t)l2 | ((uint32_t)l3 << 16));
}

// W[K][N] fp32 -> Wt[N][K] bf16 hi/lo ; 4 weights in one launch (blockIdx.z)
struct WPtrs { const float* w[4]; __nv_bfloat16* th[4]; __nv_bfloat16* tl[4]; };

__global__ __launch_bounds__(256)
void transw_kernel(WPtrs p) {
    __shared__ float t[32][33];
    const float* W = p.w[blockIdx.z];
    __nv_bfloat16* Th = p.th[blockIdx.z];
    __nv_bfloat16* Tl = p.tl[blockIdx.z];
    const int n0 = blockIdx.x * 32, k0 = blockIdx.y * 32;
    const int tx = threadIdx.x, ty = threadIdx.y;
    #pragma unroll
    for (int i = 0; i < 4; i++)
        t[ty + i * 8][tx] = W[(size_t)(k0 + ty + i * 8) * DIM + n0 + tx];
    __syncthreads();
    #pragma unroll
    for (int i = 0; i < 4; i++) {
        float v = t[tx][ty + i * 8];
        unsigned short h, l; hilo(v, h, l);
        size_t o = (size_t)(n0 + ty + i * 8) * DIM + k0 + tx;
        Th[o] = __ushort_as_bfloat16(h);
        Tl[o] = __ushort_as_bfloat16(l);
    }
}

// RMSNorm + RoPE for q and k in one launch (blockIdx.y)
__global__ __launch_bounds__(256)
void rmsnorm_rope_conv(const float* __restrict__ tq, const float* __restrict__ gq,
                       __nv_bfloat16* __restrict__ qoh, __nv_bfloat16* __restrict__ qol,
                       const float* __restrict__ tk, const float* __restrict__ gk,
                       __nv_bfloat16* __restrict__ koh, __nv_bfloat16* __restrict__ kol,
                       const float* __restrict__ freqs, const int* __restrict__ grid_sizes) {
    const int s = blockIdx.x;
    const int tid = threadIdx.x;
    const float* t  = (blockIdx.y == 0) ? tq : tk;
    const float* g  = (blockIdx.y == 0) ? gq : gk;
    __nv_bfloat16* oh = (blockIdx.y == 0) ? qoh : koh;
    __nv_bfloat16* ol = (blockIdx.y == 0) ? qol : kol;
    const float* row = t + (size_t)s * DIM;

    float ss = 0.f;
    for (int i = tid; i < DIM / 4; i += 256) {
        float4 v = ((const float4*)row)[i];
        ss += v.x * v.x + v.y * v.y + v.z * v.z + v.w * v.w;
    }
    #pragma unroll
    for (int off = 16; off; off >>= 1) ss += __shfl_xor_sync(0xffffffffu, ss, off);
    __shared__ float red[8];
    if ((tid & 31) == 0) red[tid >> 5] = ss;
    __syncthreads();
    if (tid == 0) {
        float tot = 0.f;
        #pragma unroll
        for (int i = 0; i < 8; i++) tot += red[i];
        red[0] = tot;
    }
    __syncthreads();
    const float inv = rsqrtf(red[0] * (1.f / DIM) + 1e-6f);

    const int H = grid_sizes[1], W = grid_sizes[2];
    const int fi = s / (H * W);
    const int rem = s % (H * W);
    const int hi = rem / W;
    const int wi = rem % W;
    const int c3 = CC / 3, c0 = CC - 2 * c3;

    for (int p = tid; p < NH * CC; p += 256) {
        int j = p % CC;
        int head = p / CC;
        int idx = head * HD + 2 * j;
        float a = row[idx]     * inv * g[idx];
        float b = row[idx + 1] * inv * g[idx + 1];
        int pos = (j < c0) ? fi : ((j < c0 + c3) ? hi : wi);
        float cs = freqs[(pos * CC + j) * 2 + 0];
        float sn = freqs[(pos * CC + j) * 2 + 1];
        float ra = a * cs - b * sn;
        float rb = a * sn + b * cs;
        uint32_t hw, lw;
        split2(ra, rb, hw, lw);
        *(uint32_t*)(oh + (size_t)s * DIM + idx) = hw;
        *(uint32_t*)(ol + (size_t)s * DIM + idx) = lw;
    }
}

// ================= HMMA GEMM (cp.async double-buffered, multi-weight, opt split-K) ======
#define G_ST   40
#define G_BUFB 10240
#define G_ASH  0
#define G_ASL  20480
#define G_BSH  40960
#define G_BSL  61440
#define G_SMEM 81920
#define VT_ST  136          // transposed V staging stride (bf16 elems)

struct QKVArgs {
    const __nv_bfloat16* bh[3];
    const __nv_bfloat16* bl[3];
    const float* bias[3];
    float* c[3];
    __nv_bfloat16* vth;     // if non-null: mat==2 writes transposed bf16 hi/lo
    __nv_bfloat16* vtl;
};

__global__ __launch_bounds__(256)
void gemm_mma(const __nv_bfloat16* __restrict__ Ah, const __nv_bfloat16* __restrict__ Al,
              QKVArgs args, int M, int splitk) {
    extern __shared__ char smc[];
    const uint32_t sb = smem_u32(smc);
    const int tid = threadIdx.x;
    const int lane = tid & 31;
    const int wid = tid >> 5;
    const int wm = wid & 1;
    const int wn = wid >> 1;
    int mat = blockIdx.x / 12;
    const int n0 = (blockIdx.x % 12) * 128;
    const int m0 = blockIdx.y * 128;
    int kt0 = 0, ktn = 48;
    if (splitk) { kt0 = blockIdx.z * 24; ktn = 24; mat = blockIdx.z; }
    const __nv_bfloat16* Bh = args.bh[splitk ? 0 : mat];
    const __nv_bfloat16* Bl = args.bl[splitk ? 0 : mat];
    const float* bias = args.bias[mat];
    float* C = args.c[mat];

    float c[4][4][4];
    #pragma unroll
    for (int i = 0; i < 4; i++)
        #pragma unroll
        for (int j = 0; j < 4; j++)
            #pragma unroll
            for (int q = 0; q < 4; q++) c[i][j][q] = 0.f;

    auto stage = [&](int kt, int buf) {
        const int k0 = kt * 32;
        #pragma unroll
        for (int cix = 0; cix < 2; cix++) {
            int ch = tid + cix * 256;           // 0..511
            int row = ch >> 2, cc = (ch & 3) * 8;
            uint32_t so = (uint32_t)(row * G_ST + cc) * 2 + (uint32_t)buf * G_BUFB;
            int szA = (m0 + row < M) ? 16 : 0;
            const __nv_bfloat16* pah = Ah + (size_t)(m0 + row) * DIM + k0 + cc;
            const __nv_bfloat16* pal = Al + (size_t)(m0 + row) * DIM + k0 + cc;
            const __nv_bfloat16* pbh = Bh + (size_t)(n0 + row) * DIM + k0 + cc;
            const __nv_bfloat16* pbl = Bl + (size_t)(n0 + row) * DIM + k0 + cc;
            CP16(sb + G_ASH + so, pah, szA);
            CP16(sb + G_ASL + so, pal, szA);
            CP16(sb + G_BSH + so, pbh, 16);
            CP16(sb + G_BSL + so, pbl, 16);
        }
        CP_COMMIT();
    };

    stage(kt0, 0);

    const int a_row = (lane & 15);
    const int a_col = ((lane >> 1) & 8);
    const int b_row = (lane & 7) + ((lane & 16) >> 1);
    const int b_col = (lane & 8);

    for (int kti = 0; kti < ktn; kti++) {
        CP_WAIT0();
        __syncthreads();
        if (kti < ktn - 1) stage(kt0 + kti + 1, (kti + 1) & 1);
        const int bo = (kti & 1) * G_BUFB;
        #pragma unroll
        for (int kc = 0; kc < 32; kc += 16) {
            uint32_t af[4][4], bfh[4][2], bfl[4][2];
            #pragma unroll
            for (int mt = 0; mt < 4; mt++)
                ldsm4(af[mt][0], af[mt][1], af[mt][2], af[mt][3],
                      sb + G_ASH + bo + (uint32_t)((wm * 64 + mt * 16 + a_row) * G_ST + kc + a_col) * 2);
            #pragma unroll
            for (int np = 0; np < 2; np++) {
                uint32_t r0, r1, r2, r3;
                uint32_t ad = sb + G_BSH + bo +
                    (uint32_t)((wn * 32 + np * 16 + b_row) * G_ST + kc + b_col) * 2;
                ldsm4(r0, r1, r2, r3, ad);
                bfh[np*2][0] = r0; bfh[np*2][1] = r1; bfh[np*2+1][0] = r2; bfh[np*2+1][1] = r3;
                ad = sb + G_BSL + bo +
                    (uint32_t)((wn * 32 + np * 16 + b_row) * G_ST + kc + b_col) * 2;
                ldsm4(r0, r1, r2, r3, ad);
                bfl[np*2][0] = r0; bfl[np*2][1] = r1; bfl[np*2+1][0] = r2; bfl[np*2+1][1] = r3;
            }
            #pragma unroll
            for (int mt = 0; mt < 4; mt++)
                #pragma unroll
                for (int nt = 0; nt < 4; nt++) {
                    mma16816(c[mt][nt], af[mt], bfh[nt]);
                    mma16816(c[mt][nt], af[mt], bfl[nt]);
                }
            #pragma unroll
            for (int mt = 0; mt < 4; mt++)
                ldsm4(af[mt][0], af[mt][1], af[mt][2], af[mt][3],
                      sb + G_ASL + bo + (uint32_t)((wm * 64 + mt * 16 + a_row) * G_ST + kc + a_col) * 2);
            #pragma unroll
            for (int mt = 0; mt < 4; mt++)
                #pragma unroll
                for (int nt = 0; nt < 4; nt++)
                    mma16816(c[mt][nt], af[mt], bfh[nt]);
        }
        __syncthreads();
    }

    if (args.vth != nullptr && mat == 2) {
        // ---- V epilogue: transposed bf16 hi/lo via smem staging ----
        #pragma unroll
        for (int mt = 0; mt < 4; mt++) {
            #pragma unroll
            for (int nt = 0; nt < 4; nt++) {
                int row0 = wm * 64 + mt * 16 + (lane >> 2);
                int coll = wn * 32 + nt * 8 + (lane & 3) * 2;
                float b0 = bias[n0 + coll], b1 = bias[n0 + coll + 1];
                float v00 = c[mt][nt][0] + b0, v01 = c[mt][nt][1] + b1;
                float v10 = c[mt][nt][2] + b0, v11 = c[mt][nt][3] + b1;
                unsigned short hh, ll;
                __nv_bfloat16* TH = (__nv_bfloat16*)smc;
                __nv_bfloat16* TL = (__nv_bfloat16*)(smc + 34816);
                hilo(v00, hh, ll);
                TH[coll * VT_ST + row0] = __ushort_as_bfloat16(hh);
                TL[coll * VT_ST + row0] = __ushort_as_bfloat16(ll);
                hilo(v01, hh, ll);
                TH[(coll + 1) * VT_ST + row0] = __ushort_as_bfloat16(hh);
                TL[(coll + 1) * VT_ST + row0] = __ushort_as_bfloat16(ll);
                hilo(v10, hh, ll);
                TH[coll * VT_ST + row0 + 8] = __ushort_as_bfloat16(hh);
                TL[coll * VT_ST + row0 + 8] = __ushort_as_bfloat16(ll);
                hilo(v11, hh, ll);
                TH[(coll + 1) * VT_ST + row0 + 8] = __ushort_as_bfloat16(hh);
                TL[(coll + 1) * VT_ST + row0 + 8] = __ushort_as_bfloat16(ll);
            }
        }
        __syncthreads();
        #pragma unroll
        for (int it = 0; it < 8; it++) {
            int ch = tid + it * 256;         // 0..2047
            int drow = ch >> 4;
            int c8 = (ch & 15) * 8;
            if (m0 + c8 + 8 <= SP) {         // guard: last M-block overhangs SP
                uint4 vh = *(uint4*)(smc + (uint32_t)(drow * VT_ST + c8) * 2);
                uint4 vl = *(uint4*)(smc + 34816 + (uint32_t)(drow * VT_ST + c8) * 2);
                *(uint4*)(args.vth + (size_t)(n0 + drow) * SP + m0 + c8) = vh;
                *(uint4*)(args.vtl + (size_t)(n0 + drow) * SP + m0 + c8) = vl;
            }
        }
    } else {
        #pragma unroll
        for (int mt = 0; mt < 4; mt++) {
            #pragma unroll
            for (int nt = 0; nt < 4; nt++) {
                int row = m0 + wm * 64 + mt * 16 + (lane >> 2);
                int col = n0 + wn * 32 + nt * 8 + (lane & 3) * 2;
                float b0 = 0.f, b1 = 0.f;
                if (!splitk) { b0 = bias[col]; b1 = bias[col + 1]; }
                if (row < M)
                    *(float2*)&C[(size_t)row * DIM + col] =
                        make_float2(c[mt][nt][0] + b0, c[mt][nt][1] + b1);
                if (row + 8 < M)
                    *(float2*)&C[(size_t)(row + 8) * DIM + col] =
                        make_float2(c[mt][nt][2] + b0, c[mt][nt][3] + b1);
            }
        }
    }
}

// ================= add split-K partials + bias =================
__global__ __launch_bounds__(256)
void addbias_kernel(const float* __restrict__ p0, const float* __restrict__ p1,
                    const float* __restrict__ bias, float* __restrict__ out) {
    int i = blockIdx.x * 256 + threadIdx.x;
    const int tot4 = S_TOT * DIM / 4;
    if (i >= tot4) return;
    float4 a = ((const float4*)p0)[i];
    float4 b = ((const float4*)p1)[i];
    float4 bb = ((const float4*)bias)[i % (DIM / 4)];
    ((float4*)out)[i] = make_float4(a.x + b.x + bb.x, a.y + b.y + bb.y,
                                    a.z + b.z + bb.z, a.w + b.w + bb.w);
}

// ================= HMMA flash attention (3-way split-KV, double-buffered K/V) ==========
#define F_QST 136
#define F_VST 72
#define F_QH   0
#define F_QL   34816
#define F_STG  69632
#define F_STGB 71680          // KH 17408 | KL 17408 | VTH 18432 | VTL 18432
#define F_SMEM (F_STG + 2 * F_STGB)   // 212992

__global__ __launch_bounds__(256, 1)
void flash_mma(const __nv_bfloat16* __restrict__ Qh, const __nv_bfloat16* __restrict__ Ql,
               const __nv_bfloat16* __restrict__ Kh, const __nv_bfloat16* __restrict__ Kl,
               const __nv_bfloat16* __restrict__ Vh, const __nv_bfloat16* __restrict__ Vl,
               float* __restrict__ O0, float* __restrict__ O1, float* __restrict__ O2,
               float* __restrict__ stat, const int* __restrict__ seq_lens) {
    extern __shared__ char smc[];
    const uint32_t sb = smem_u32(smc);
    const int tid = threadIdx.x;
    const int lane = tid & 31;
    const int wid = tid >> 5;
    const int r0w = wid * 16;
    const int h = blockIdx.y;
    const int q0 = blockIdx.x * 128;
    const int sp = blockIdx.z;                      // 0,1,2
    const int t_begin = (sp == 0) ? 0 : 21 + (sp - 1) * 20;
    const int t_cnt   = (sp == 0) ? 21 : 20;
    const int seqlen = seq_lens[0];
    const float scale2 = 0.08838834764831845f * 1.4426950408889634f;  // /sqrt(128)*log2(e)

    // ---- load Q tile [128 x 128] hi/lo ----
    #pragma unroll
    for (int cix = 0; cix < 8; cix++) {
        int ch = tid + cix * 256;
        int row = ch >> 4, cc = (ch & 15) * 8;
        uint32_t so = (uint32_t)(row * F_QST + cc) * 2;
        uint4 vh = make_uint4(0,0,0,0), vl = make_uint4(0,0,0,0);
        if (q0 + row < S_TOT) {
            size_t gq = (size_t)(q0 + row) * DIM + h * HD + cc;
            vh = *(const uint4*)(Qh + gq);
            vl = *(const uint4*)(Ql + gq);
        }
        *(uint4*)(smc + F_QH + so) = vh;
        *(uint4*)(smc + F_QL + so) = vl;
    }

    auto kv_stage = [&](int gt, int buf) {
        const int k0 = gt * 64;
        const uint32_t base = sb + F_STG + (uint32_t)buf * F_STGB;
        #pragma unroll
        for (int cix = 0; cix < 4; cix++) {
            int ch = tid + cix * 256;            // 0..1023
            {
                int row = ch >> 4, cc = (ch & 15) * 8;
                uint32_t so = (uint32_t)(row * F_QST + cc) * 2;
                int sz = (k0 + row < S_TOT) ? 16 : 0;
                const __nv_bfloat16* gh = Kh + (size_t)(k0 + row) * DIM + h * HD + cc;
                const __nv_bfloat16* gl = Kl + (size_t)(k0 + row) * DIM + h * HD + cc;
                CP16(base + so, gh, sz);
                CP16(base + 17408 + so, gl, sz);
            }
            {
                int row = ch >> 3, cc = (ch & 7) * 8;
                uint32_t so = (uint32_t)(row * F_VST + cc) * 2;
                const __nv_bfloat16* gvh = Vh + (size_t)(h * HD + row) * SP + k0 + cc;
                const __nv_bfloat16* gvl = Vl + (size_t)(h * HD + row) * SP + k0 + cc;
                CP16(base + 34816 + so, gvh, 16);
                CP16(base + 53248 + so, gvl, 16);
            }
        }
        CP_COMMIT();
    };

    kv_stage(t_begin, 0);

    float m0s = -1e30f, m1s = -1e30f, l0s = 0.f, l1s = 0.f;
    float o[16][4];
    #pragma unroll
    for (int i = 0; i < 16; i++)
        #pragma unroll
        for (int j = 0; j < 4; j++) o[i][j] = 0.f;

    const int a_row = (lane & 15);
    const int a_col = ((lane >> 1) & 8);
    const int b_row = (lane & 7) + ((lane & 16) >> 1);
    const int b_col = (lane & 8);

    for (int lt = 0; lt < t_cnt; lt++) {
        const int gt = t_begin + lt;
        const int k0 = gt * 64;
        CP_WAIT0();
        __syncthreads();
        if (lt + 1 < t_cnt) kv_stage(gt + 1, (lt + 1) & 1);

        const uint32_t kb = sb + F_STG + (uint32_t)(lt & 1) * F_STGB;
        const uint32_t kbh = kb, kbl = kb + 17408;
        const uint32_t vbh = kb + 34816, vbl = kb + 53248;

        // ---- S = Q K^T ----
        float c[8][4];
        #pragma unroll
        for (int nt = 0; nt < 8; nt++)
            #pragma unroll
            for (int j = 0; j < 4; j++) c[nt][j] = 0.f;

        #pragma unroll
        for (int kc8 = 0; kc8 < 8; kc8++) {
            const int kc = kc8 * 16;
            uint32_t aq[4], bkh[8][2], bkl[8][2];
            ldsm4(aq[0], aq[1], aq[2], aq[3],
                  sb + F_QH + (uint32_t)((r0w + a_row) * F_QST + kc + a_col) * 2);
            #pragma unroll
            for (int np = 0; np < 4; np++) {
                uint32_t r0, r1, r2, r3;
                ldsm4(r0, r1, r2, r3,
                      kbh + (uint32_t)((np * 16 + b_row) * F_QST + kc + b_col) * 2);
                bkh[np*2][0] = r0; bkh[np*2][1] = r1; bkh[np*2+1][0] = r2; bkh[np*2+1][1] = r3;
                ldsm4(r0, r1, r2, r3,
                      kbl + (uint32_t)((np * 16 + b_row) * F_QST + kc + b_col) * 2);
                bkl[np*2][0] = r0; bkl[np*2][1] = r1; bkl[np*2+1][0] = r2; bkl[np*2+1][1] = r3;
            }
            #pragma unroll
            for (int nt = 0; nt < 8; nt++) {
                mma16816(c[nt], aq, bkh[nt]);
                mma16816(c[nt], aq, bkl[nt]);
            }
            ldsm4(aq[0], aq[1], aq[2], aq[3],
                  sb + F_QL + (uint32_t)((r0w + a_row) * F_QST + kc + a_col) * 2);
            #pragma unroll
            for (int nt = 0; nt < 8; nt++)
                mma16816(c[nt], aq, bkh[nt]);
        }

        // ---- scale (log2 domain) + mask ----
        #pragma unroll
        for (int nt = 0; nt < 8; nt++) {
            int colb = k0 + nt * 8 + (lane & 3) * 2;
            #pragma unroll
            for (int j = 0; j < 4; j++) {
                float v = c[nt][j] * scale2;
                c[nt][j] = (colb + (j & 1) < seqlen) ? v : -1e30f;
            }
        }

        // ---- online softmax (exp2) ----
        float mx0 = -1e30f, mx1 = -1e30f;
        #pragma unroll
        for (int nt = 0; nt < 8; nt++) {
            mx0 = fmaxf(mx0, fmaxf(c[nt][0], c[nt][1]));
            mx1 = fmaxf(mx1, fmaxf(c[nt][2], c[nt][3]));
        }
        mx0 = fmaxf(mx0, __shfl_xor_sync(0xffffffffu, mx0, 1));
        mx0 = fmaxf(mx0, __shfl_xor_sync(0xffffffffu, mx0, 2));
        mx1 = fmaxf(mx1, __shfl_xor_sync(0xffffffffu, mx1, 1));
        mx1 = fmaxf(mx1, __shfl_xor_sync(0xffffffffu, mx1, 2));
        float mn0 = fmaxf(m0s, mx0), mn1 = fmaxf(m1s, mx1);
        float al0 = exp2f(m0s - mn0), al1 = exp2f(m1s - mn1);
        m0s = mn0; m1s = mn1;
        float ls0 = 0.f, ls1 = 0.f;
        #pragma unroll
        for (int nt = 0; nt < 8; nt++) {
            c[nt][0] = exp2f(c[nt][0] - mn0); ls0 += c[nt][0];
            c[nt][1] = exp2f(c[nt][1] - mn0); ls0 += c[nt][1];
            c[nt][2] = exp2f(c[nt][2] - mn1); ls1 += c[nt][2];
            c[nt][3] = exp2f(c[nt][3] - mn1); ls1 += c[nt][3];
        }
        ls0 += __shfl_xor_sync(0xffffffffu, ls0, 1);
        ls0 += __shfl_xor_sync(0xffffffffu, ls0, 2);
        ls1 += __shfl_xor_sync(0xffffffffu, ls1, 1);
        ls1 += __shfl_xor_sync(0xffffffffu, ls1, 2);
        l0s = l0s * al0 + ls0;
        l1s = l1s * al1 + ls1;

        // ---- pack P into A fragments (hi/lo) ----
        uint32_t ph[4][4], pl[4][4];
        #pragma unroll
        for (int kc2 = 0; kc2 < 4; kc2++) {
            split2(c[2*kc2][0],   c[2*kc2][1],   ph[kc2][0], pl[kc2][0]);
            split2(c[2*kc2][2],   c[2*kc2][3],   ph[kc2][1], pl[kc2][1]);
            split2(c[2*kc2+1][0], c[2*kc2+1][1], ph[kc2][2], pl[kc2][2]);
            split2(c[2*kc2+1][2], c[2*kc2+1][3], ph[kc2][3], pl[kc2][3]);
        }

        // ---- rescale O ----
        #pragma unroll
        for (int nt = 0; nt < 16; nt++) {
            o[nt][0] *= al0; o[nt][1] *= al0;
            o[nt][2] *= al1; o[nt][3] *= al1;
        }

        // ---- O += P V ----
        #pragma unroll
        for (int kc2 = 0; kc2 < 4; kc2++) {
            #pragma unroll
            for (int np = 0; np < 8; np++) {
                uint32_t vh0, vh1, vh2, vh3, vl0, vl1, vl2, vl3;
                uint32_t ad = vbh + (uint32_t)((np * 16 + b_row) * F_VST + kc2 * 16 + b_col) * 2;
                ldsm4(vh0, vh1, vh2, vh3, ad);
                ad = vbl + (uint32_t)((np * 16 + b_row) * F_VST + kc2 * 16 + b_col) * 2;
                ldsm4(vl0, vl1, vl2, vl3, ad);
                uint32_t bh0[2] = {vh0, vh1}, bh1[2] = {vh2, vh3};
                uint32_t bl0[2] = {vl0, vl1}, bl1[2] = {vl2, vl3};
                mma16816(o[2*np],   ph[kc2], bh0);
                mma16816(o[2*np+1], ph[kc2], bh1);
                mma16816(o[2*np],   ph[kc2], bl0);
                mma16816(o[2*np+1], ph[kc2], bl1);
                mma16816(o[2*np],   pl[kc2], bh0);
                mma16816(o[2*np+1], pl[kc2], bh1);
            }
        }
    }

    // ---- write UNNORMALIZED partial + stats ----
    float* Op = (sp == 0) ? O0 : ((sp == 1) ? O1 : O2);
    const int rA = q0 + r0w + (lane >> 2);
    const int rB = rA + 8;
    #pragma unroll
    for (int nt = 0; nt < 16; nt++) {
        int col = h * HD + nt * 8 + (lane & 3) * 2;
        if (rA < S_TOT)
            *(float2*)&Op[(size_t)rA * DIM + col] = make_float2(o[nt][0], o[nt][1]);
        if (rB < S_TOT)
            *(float2*)&Op[(size_t)rB * DIM + col] = make_float2(o[nt][2], o[nt][3]);
    }
    if ((lane & 3) == 0) {
        if (rA < S_TOT) {
            stat[STATIDX(sp, h, 0, rA)] = m0s;
            stat[STATIDX(sp, h, 1, rA)] = l0s;
        }
        if (rB < S_TOT) {
            stat[STATIDX(sp, h, 0, rB)] = m1s;
            stat[STATIDX(sp, h, 1, rB)] = l1s;
        }
    }
}

// ================= combine split-KV partials (3-way) =================
__global__ __launch_bounds__(128)
void combine_kernel(const float* __restrict__ O0, const float* __restrict__ O1,
                    const float* __restrict__ O2, const float* __restrict__ stat,
                    __nv_bfloat16* __restrict__ AOh, __nv_bfloat16* __restrict__ AOl) {
    const int s = blockIdx.x;
    const int h = blockIdx.y;
    const int c = threadIdx.x;
    float mA = stat[STATIDX(0, h, 0, s)], lA = stat[STATIDX(0, h, 1, s)];
    float mB = stat[STATIDX(1, h, 0, s)], lB = stat[STATIDX(1, h, 1, s)];
    float mC = stat[STATIDX(2, h, 0, s)], lC = stat[STATIDX(2, h, 1, s)];
    float m = fmaxf(fmaxf(mA, mB), mC);
    float aA = exp2f(mA - m), aB = exp2f(mB - m), aC = exp2f(mC - m);
    float inv = 1.f / (lA * aA + lB * aB + lC * aC);
    size_t idx = (size_t)s * DIM + h * HD + c;
    float o = (O0[idx] * aA + O1[idx] * aB + O2[idx] * aC) * inv;
    unsigned short hh, ll;
    hilo(o, hh, ll);
    AOh[idx] = __ushort_as_bfloat16(hh);
    AOl[idx] = __ushort_as_bfloat16(ll);
}

// ---------------- launch ----------------
extern "C" void kernel_launch(void* const* d_in, const int* in_sizes, int n_in,
                              void* d_out, int out_size) {
    const float* x        = (const float*)d_in[0];
    const int*   seq_lens = (const int*)  d_in[1];
    const int*   grid_sz  = (const int*)  d_in[2];
    const float* freqs    = (const float*)d_in[3];
    const float* Wq       = (const float*)d_in[4];
    const float* bq       = (const float*)d_in[5];
    const float* Wk       = (const float*)d_in[6];
    const float* bk       = (const float*)d_in[7];
    const float* Wv       = (const float*)d_in[8];
    const float* bv       = (const float*)d_in[9];
    const float* Wo       = (const float*)d_in[10];
    const float* bo       = (const float*)d_in[11];
    const float* gq       = (const float*)d_in[12];
    const float* gk       = (const float*)d_in[13];
    float* out = (float*)d_out;

    float *q, *k, *o2, *stat;
    __nv_bfloat16 *xh, *xl, *qh, *ql, *kh, *kl, *aoh, *aol, *vth, *vtl;
    __nv_bfloat16 *wthq, *wtlq, *wthk, *wtlk, *wthv, *wtlv, *wtho, *wtlo;
    cudaGetSymbolAddress((void**)&q, g_q);
    cudaGetSymbolAddress((void**)&k, g_k);
    cudaGetSymbolAddress((void**)&o2, g_o2);
    cudaGetSymbolAddress((void**)&stat, g_stat);
    cudaGetSymbolAddress((void**)&xh, g_xh);   cudaGetSymbolAddress((void**)&xl, g_xl);
    cudaGetSymbolAddress((void**)&qh, g_qh);   cudaGetSymbolAddress((void**)&ql, g_ql);
    cudaGetSymbolAddress((void**)&kh, g_kh);   cudaGetSymbolAddress((void**)&kl, g_kl);
    cudaGetSymbolAddress((void**)&aoh, g_aoh); cudaGetSymbolAddress((void**)&aol, g_aol);
    cudaGetSymbolAddress((void**)&vth, g_vth); cudaGetSymbolAddress((void**)&vtl, g_vtl);
    cudaGetSymbolAddress((void**)&wthq, g_wthq); cudaGetSymbolAddress((void**)&wtlq, g_wtlq);
    cudaGetSymbolAddress((void**)&wthk, g_wthk); cudaGetSymbolAddress((void**)&wtlk, g_wtlk);
    cudaGetSymbolAddress((void**)&wthv, g_wthv); cudaGetSymbolAddress((void**)&wtlv, g_wtlv);
    cudaGetSymbolAddress((void**)&wtho, g_wtho); cudaGetSymbolAddress((void**)&wtlo, g_wtlo);

    cudaFuncSetAttribute(gemm_mma, cudaFuncAttributeMaxDynamicSharedMemorySize, G_SMEM);
    cudaFuncSetAttribute(flash_mma, cudaFuncAttributeMaxDynamicSharedMemorySize, F_SMEM);

    // prep
    convert_x_kernel<<<S_TOT * DIM / 4 / 256, 256>>>(x, xh, xl);
    WPtrs wp;
    wp.w[0] = Wq; wp.th[0] = wthq; wp.tl[0] = wtlq;
    wp.w[1] = Wk; wp.th[1] = wthk; wp.tl[1] = wtlk;
    wp.w[2] = Wv; wp.th[2] = wthv; wp.tl[2] = wtlv;
    wp.w[3] = Wo; wp.th[3] = wtho; wp.tl[3] = wtlo;
    transw_kernel<<<dim3(48, 48, 4), dim3(32, 8)>>>(wp);

    // fused QKV projection; V written directly as transposed bf16 hi/lo
    QKVArgs aqkv;
    aqkv.bh[0] = wthq; aqkv.bl[0] = wtlq; aqkv.bias[0] = bq; aqkv.c[0] = q;
    aqkv.bh[1] = wthk; aqkv.bl[1] = wtlk; aqkv.bias[1] = bk; aqkv.c[1] = k;
    aqkv.bh[2] = wthv; aqkv.bl[2] = wtlv; aqkv.bias[2] = bv; aqkv.c[2] = nullptr;
    aqkv.vth = vth; aqkv.vtl = vtl;
    gemm_mma<<<dim3(36, 31), 256, G_SMEM>>>(xh, xl, aqkv, S_TOT, 0);

    rmsnorm_rope_conv<<<dim3(S_TOT, 2), 256>>>(q, gq, qh, ql, k, gk, kh, kl, freqs, grid_sz);

    // 3-way split-KV flash: partials into g_q, g_k, g_o2 (all free now)
    dim3 fg(31, NH, NSPLIT);
    flash_mma<<<fg, 256, F_SMEM>>>(qh, ql, kh, kl, vth, vtl, q, k, o2, stat, seq_lens);
    combine_kernel<<<dim3(S_TOT, NH), 128>>>(q, k, o2, stat, aoh, aol);

    // O projection: split-K=2 into fp32 partials (g_q, g_k free again), then add+bias
    QKVArgs aop;
    aop.bh[0] = wtho; aop.bl[0] = wtlo; aop.bias[0] = nullptr; aop.c[0] = q;
    aop.bh[1] = wtho; aop.bl[1] = wtlo; aop.bias[1] = nullptr; aop.c[1] = k;
    aop.bh[2] = wtho; aop.bl[2] = wtlo; aop.bias[2] = nullptr; aop.c[2] = nullptr;
    aop.vth = nullptr; aop.vtl = nullptr;
    gemm_mma<<<dim3(12, 31, 2), 256, G_SMEM>>>(aoh, aol, aop, S_TOT, 1);
    addbias_kernel<<<S_TOT * DIM / 4 / 256, 256>>>(q, k, bo, out);
}

// round 11
// speedup vs baseline: 20.0591x; 1.0711x over previous
#include <cuda_runtime.h>
#include <cuda_bf16.h>
#include <cuda_fp16.h>
#include <math.h>
#include <stdint.h>

#define S_TOT 3900
#define SP    3904        // padded seq (61*64)
#define DIM   1536
#define NH    12
#define HD    128
#define CC    64
#define NTILES 61         // SP/64
#define NSPLIT 3          // flash KV splits

// ---------------- scratch ----------------
__device__ float g_q [S_TOT * DIM];   // q fp32 -> flash partial 0 -> O-proj partial 0
__device__ float g_k [S_TOT * DIM];   // k fp32 -> flash partial 1 -> O-proj partial 1
__device__ float g_o2[S_TOT * DIM];   // flash partial 2 -> O-proj partial 2
__device__ float g_stat[NSPLIT * NH * 2 * 4096];

__device__ __nv_bfloat16 g_xh [S_TOT * DIM];
__device__ __nv_bfloat16 g_xl [S_TOT * DIM];
__device__ __nv_bfloat16 g_qh [S_TOT * DIM];
__device__ __nv_bfloat16 g_ql [S_TOT * DIM];
__device__ __nv_bfloat16 g_kh [S_TOT * DIM];
__device__ __nv_bfloat16 g_kl [S_TOT * DIM];
__device__ __nv_bfloat16 g_aoh[S_TOT * DIM];
__device__ __nv_bfloat16 g_aol[S_TOT * DIM];
__device__ __half        g_vth[DIM * SP];     // V transposed, fp16 hi
__device__ __half        g_vtl[DIM * SP];     // V transposed, fp16 lo

__device__ __nv_bfloat16 g_wthq[DIM * DIM];
__device__ __nv_bfloat16 g_wtlq[DIM * DIM];
__device__ __nv_bfloat16 g_wthk[DIM * DIM];
__device__ __nv_bfloat16 g_wtlk[DIM * DIM];
__device__ __nv_bfloat16 g_wthv[DIM * DIM];
__device__ __nv_bfloat16 g_wtlv[DIM * DIM];
__device__ __nv_bfloat16 g_wtho[DIM * DIM];
__device__ __nv_bfloat16 g_wtlo[DIM * DIM];

// ================= helpers =================
__device__ __forceinline__ uint32_t smem_u32(const void* p) {
    uint32_t a;
    asm("{ .reg .u64 t; cvta.to.shared.u64 t, %1; cvt.u32.u64 %0, t; }" : "=r"(a) : "l"(p));
    return a;
}
__device__ __forceinline__ void ldsm4(uint32_t& r0, uint32_t& r1, uint32_t& r2, uint32_t& r3,
                                      uint32_t addr) {
    asm volatile("ldmatrix.sync.aligned.m8n8.x4.shared.b16 {%0,%1,%2,%3}, [%4];"
                 : "=r"(r0), "=r"(r1), "=r"(r2), "=r"(r3) : "r"(addr));
}
__device__ __forceinline__ void mma16816(float* c, const uint32_t* a, const uint32_t* b) {
    asm volatile(
        "mma.sync.aligned.m16n8k16.row.col.f32.bf16.bf16.f32 "
        "{%0,%1,%2,%3}, {%4,%5,%6,%7}, {%8,%9}, {%0,%1,%2,%3};"
        : "+f"(c[0]), "+f"(c[1]), "+f"(c[2]), "+f"(c[3])
        : "r"(a[0]), "r"(a[1]), "r"(a[2]), "r"(a[3]), "r"(b[0]), "r"(b[1]));
}
__device__ __forceinline__ void mma16816h(float* c, const uint32_t* a, const uint32_t* b) {
    asm volatile(
        "mma.sync.aligned.m16n8k16.row.col.f32.f16.f16.f32 "
        "{%0,%1,%2,%3}, {%4,%5,%6,%7}, {%8,%9}, {%0,%1,%2,%3};"
        : "+f"(c[0]), "+f"(c[1]), "+f"(c[2]), "+f"(c[3])
        : "r"(a[0]), "r"(a[1]), "r"(a[2]), "r"(a[3]), "r"(b[0]), "r"(b[1]));
}
#define CP16(dst, src, sz) \
    asm volatile("cp.async.cg.shared.global [%0], [%1], 16, %2;" \
        :: "r"(dst), "l"(src), "r"(sz) : "memory")
#define CP_COMMIT() asm volatile("cp.async.commit_group;" ::: "memory")
#define CP_WAIT0()  asm volatile("cp.async.wait_group 0;" ::: "memory")

__device__ __forceinline__ uint32_t pack_bf(float lo, float hi) {
    __nv_bfloat162 t = __floats2bfloat162_rn(lo, hi);
    return *(uint32_t*)&t;
}
__device__ __forceinline__ void split2(float x, float y, uint32_t& hw, uint32_t& lw) {
    __nv_bfloat16 bx = __float2bfloat16(x), by = __float2bfloat16(y);
    __nv_bfloat162 hp; hp.x = bx; hp.y = by;
    hw = *(uint32_t*)&hp;
    lw = pack_bf(x - __bfloat162float(bx), y - __bfloat162float(by));
}
__device__ __forceinline__ void hilo(float x, unsigned short& h, unsigned short& l) {
    __nv_bfloat16 hb = __float2bfloat16(x);
    h = __bfloat16_as_ushort(hb);
    l = __bfloat16_as_ushort(__float2bfloat16(x - __bfloat162float(hb)));
}
__device__ __forceinline__ void hilo16(float x, unsigned short& h, unsigned short& l) {
    __half hh = __float2half_rn(x);
    h = __half_as_ushort(hh);
    l = __half_as_ushort(__float2half_rn(x - __half2float(hh)));
}
__device__ __forceinline__ uint32_t pack_h2(float x, float y) {
    __half2 t = __floats2half2_rn(x, y);
    return *(uint32_t*)&t;
}
#define STATIDX(sp, hh, ml, s) ((((sp) * NH + (hh)) * 2 + (ml)) * 4096 + (s))

// ================= prep kernels =================
__global__ __launch_bounds__(256)
void convert_x_kernel(const float* __restrict__ x,
                      __nv_bfloat16* __restrict__ xh, __nv_bfloat16* __restrict__ xl) {
    int i = blockIdx.x * 256 + threadIdx.x;
    const int tot4 = S_TOT * DIM / 4;
    if (i >= tot4) return;
    float4 v = ((const float4*)x)[i];
    unsigned short h0,l0,h1,l1,h2,l2,h3,l3;
    hilo(v.x,h0,l0); hilo(v.y,h1,l1); hilo(v.z,h2,l2); hilo(v.w,h3,l3);
    ((uint2*)xh)[i] = make_uint2((uint32_t)h0 | ((uint32_t)h1 << 16), (uint32_t)h2 | ((uint32_t)h3 << 16));
    ((uint2*)xl)[i] = make_uint2((uint32_t)l0 | ((uint32_t)l1 << 16), (uint32_t)l2 | ((uint32_t)l3 << 16));
}

// W[K][N] fp32 -> Wt[N][K] bf16 hi/lo ; 4 weights in one launch (blockIdx.z)
struct WPtrs { const float* w[4]; __nv_bfloat16* th[4]; __nv_bfloat16* tl[4]; };

__global__ __launch_bounds__(256)
void transw_kernel(WPtrs p) {
    __shared__ float t[32][33];
    const float* W = p.w[blockIdx.z];
    __nv_bfloat16* Th = p.th[blockIdx.z];
    __nv_bfloat16* Tl = p.tl[blockIdx.z];
    const int n0 = blockIdx.x * 32, k0 = blockIdx.y * 32;
    const int tx = threadIdx.x, ty = threadIdx.y;
    #pragma unroll
    for (int i = 0; i < 4; i++)
        t[ty + i * 8][tx] = W[(size_t)(k0 + ty + i * 8) * DIM + n0 + tx];
    __syncthreads();
    #pragma unroll
    for (int i = 0; i < 4; i++) {
        float v = t[tx][ty + i * 8];
        unsigned short h, l; hilo(v, h, l);
        size_t o = (size_t)(n0 + ty + i * 8) * DIM + k0 + tx;
        Th[o] = __ushort_as_bfloat16(h);
        Tl[o] = __ushort_as_bfloat16(l);
    }
}

// RMSNorm + RoPE for q and k in one launch (blockIdx.y)
__global__ __launch_bounds__(256)
void rmsnorm_rope_conv(const float* __restrict__ tq, const float* __restrict__ gq,
                       __nv_bfloat16* __restrict__ qoh, __nv_bfloat16* __restrict__ qol,
                       const float* __restrict__ tk, const float* __restrict__ gk,
                       __nv_bfloat16* __restrict__ koh, __nv_bfloat16* __restrict__ kol,
                       const float* __restrict__ freqs, const int* __restrict__ grid_sizes) {
    const int s = blockIdx.x;
    const int tid = threadIdx.x;
    const float* t  = (blockIdx.y == 0) ? tq : tk;
    const float* g  = (blockIdx.y == 0) ? gq : gk;
    __nv_bfloat16* oh = (blockIdx.y == 0) ? qoh : koh;
    __nv_bfloat16* ol = (blockIdx.y == 0) ? qol : kol;
    const float* row = t + (size_t)s * DIM;

    float ss = 0.f;
    for (int i = tid; i < DIM / 4; i += 256) {
        float4 v = ((const float4*)row)[i];
        ss += v.x * v.x + v.y * v.y + v.z * v.z + v.w * v.w;
    }
    #pragma unroll
    for (int off = 16; off; off >>= 1) ss += __shfl_xor_sync(0xffffffffu, ss, off);
    __shared__ float red[8];
    if ((tid & 31) == 0) red[tid >> 5] = ss;
    __syncthreads();
    if (tid == 0) {
        float tot = 0.f;
        #pragma unroll
        for (int i = 0; i < 8; i++) tot += red[i];
        red[0] = tot;
    }
    __syncthreads();
    const float inv = rsqrtf(red[0] * (1.f / DIM) + 1e-6f);

    const int H = grid_sizes[1], W = grid_sizes[2];
    const int fi = s / (H * W);
    const int rem = s % (H * W);
    const int hi = rem / W;
    const int wi = rem % W;
    const int c3 = CC / 3, c0 = CC - 2 * c3;

    for (int p = tid; p < NH * CC; p += 256) {
        int j = p % CC;
        int head = p / CC;
        int idx = head * HD + 2 * j;
        float a = row[idx]     * inv * g[idx];
        float b = row[idx + 1] * inv * g[idx + 1];
        int pos = (j < c0) ? fi : ((j < c0 + c3) ? hi : wi);
        float cs = freqs[(pos * CC + j) * 2 + 0];
        float sn = freqs[(pos * CC + j) * 2 + 1];
        float ra = a * cs - b * sn;
        float rb = a * sn + b * cs;
        uint32_t hw, lw;
        split2(ra, rb, hw, lw);
        *(uint32_t*)(oh + (size_t)s * DIM + idx) = hw;
        *(uint32_t*)(ol + (size_t)s * DIM + idx) = lw;
    }
}

// ================= HMMA GEMM (cp.async double-buffered, multi-weight, opt split-K) ======
#define G_ST   40
#define G_BUFB 10240
#define G_ASH  0
#define G_ASL  20480
#define G_BSH  40960
#define G_BSL  61440
#define G_SMEM 81920
#define VT_ST  136          // transposed V staging stride (elems)

struct QKVArgs {
    const __nv_bfloat16* bh[3];
    const __nv_bfloat16* bl[3];
    const float* bias[3];
    float* c[3];
    __half* vth;            // if non-null: mat==2 writes transposed fp16 hi/lo
    __half* vtl;
};

__global__ __launch_bounds__(256)
void gemm_mma(const __nv_bfloat16* __restrict__ Ah, const __nv_bfloat16* __restrict__ Al,
              QKVArgs args, int M, int splitk) {
    extern __shared__ char smc[];
    const uint32_t sb = smem_u32(smc);
    const int tid = threadIdx.x;
    const int lane = tid & 31;
    const int wid = tid >> 5;
    const int wm = wid & 1;
    const int wn = wid >> 1;
    int mat = blockIdx.x / 12;
    const int n0 = (blockIdx.x % 12) * 128;
    const int m0 = blockIdx.y * 128;
    int kt0 = 0, ktn = 48;
    if (splitk) { kt0 = blockIdx.z * 16; ktn = 16; mat = blockIdx.z; }
    const __nv_bfloat16* Bh = args.bh[splitk ? 0 : mat];
    const __nv_bfloat16* Bl = args.bl[splitk ? 0 : mat];
    const float* bias = args.bias[mat];
    float* C = args.c[mat];

    float c[4][4][4];
    #pragma unroll
    for (int i = 0; i < 4; i++)
        #pragma unroll
        for (int j = 0; j < 4; j++)
            #pragma unroll
            for (int q = 0; q < 4; q++) c[i][j][q] = 0.f;

    auto stage = [&](int kt, int buf) {
        const int k0 = kt * 32;
        #pragma unroll
        for (int cix = 0; cix < 2; cix++) {
            int ch = tid + cix * 256;           // 0..511
            int row = ch >> 2, cc = (ch & 3) * 8;
            uint32_t so = (uint32_t)(row * G_ST + cc) * 2 + (uint32_t)buf * G_BUFB;
            int szA = (m0 + row < M) ? 16 : 0;
            const __nv_bfloat16* pah = Ah + (size_t)(m0 + row) * DIM + k0 + cc;
            const __nv_bfloat16* pal = Al + (size_t)(m0 + row) * DIM + k0 + cc;
            const __nv_bfloat16* pbh = Bh + (size_t)(n0 + row) * DIM + k0 + cc;
            const __nv_bfloat16* pbl = Bl + (size_t)(n0 + row) * DIM + k0 + cc;
            CP16(sb + G_ASH + so, pah, szA);
            CP16(sb + G_ASL + so, pal, szA);
            CP16(sb + G_BSH + so, pbh, 16);
            CP16(sb + G_BSL + so, pbl, 16);
        }
        CP_COMMIT();
    };

    stage(kt0, 0);

    const int a_row = (lane & 15);
    const int a_col = ((lane >> 1) & 8);
    const int b_row = (lane & 7) + ((lane & 16) >> 1);
    const int b_col = (lane & 8);

    for (int kti = 0; kti < ktn; kti++) {
        CP_WAIT0();
        __syncthreads();
        if (kti < ktn - 1) stage(kt0 + kti + 1, (kti + 1) & 1);
        const int bo = (kti & 1) * G_BUFB;
        #pragma unroll
        for (int kc = 0; kc < 32; kc += 16) {
            uint32_t af[4][4], bfh[4][2], bfl[4][2];
            #pragma unroll
            for (int mt = 0; mt < 4; mt++)
                ldsm4(af[mt][0], af[mt][1], af[mt][2], af[mt][3],
                      sb + G_ASH + bo + (uint32_t)((wm * 64 + mt * 16 + a_row) * G_ST + kc + a_col) * 2);
            #pragma unroll
            for (int np = 0; np < 2; np++) {
                uint32_t r0, r1, r2, r3;
                uint32_t ad = sb + G_BSH + bo +
                    (uint32_t)((wn * 32 + np * 16 + b_row) * G_ST + kc + b_col) * 2;
                ldsm4(r0, r1, r2, r3, ad);
                bfh[np*2][0] = r0; bfh[np*2][1] = r1; bfh[np*2+1][0] = r2; bfh[np*2+1][1] = r3;
                ad = sb + G_BSL + bo +
                    (uint32_t)((wn * 32 + np * 16 + b_row) * G_ST + kc + b_col) * 2;
                ldsm4(r0, r1, r2, r3, ad);
                bfl[np*2][0] = r0; bfl[np*2][1] = r1; bfl[np*2+1][0] = r2; bfl[np*2+1][1] = r3;
            }
            #pragma unroll
            for (int mt = 0; mt < 4; mt++)
                #pragma unroll
                for (int nt = 0; nt < 4; nt++) {
                    mma16816(c[mt][nt], af[mt], bfh[nt]);
                    mma16816(c[mt][nt], af[mt], bfl[nt]);
                }
            #pragma unroll
            for (int mt = 0; mt < 4; mt++)
                ldsm4(af[mt][0], af[mt][1], af[mt][2], af[mt][3],
                      sb + G_ASL + bo + (uint32_t)((wm * 64 + mt * 16 + a_row) * G_ST + kc + a_col) * 2);
            #pragma unroll
            for (int mt = 0; mt < 4; mt++)
                #pragma unroll
                for (int nt = 0; nt < 4; nt++)
                    mma16816(c[mt][nt], af[mt], bfh[nt]);
        }
        __syncthreads();
    }

    if (args.vth != nullptr && mat == 2) {
        // ---- V epilogue: transposed fp16 hi/lo via smem staging ----
        #pragma unroll
        for (int mt = 0; mt < 4; mt++) {
            #pragma unroll
            for (int nt = 0; nt < 4; nt++) {
                int row0 = wm * 64 + mt * 16 + (lane >> 2);
                int coll = wn * 32 + nt * 8 + (lane & 3) * 2;
                float b0 = bias[n0 + coll], b1 = bias[n0 + coll + 1];
                float v00 = c[mt][nt][0] + b0, v01 = c[mt][nt][1] + b1;
                float v10 = c[mt][nt][2] + b0, v11 = c[mt][nt][3] + b1;
                unsigned short hh, ll;
                unsigned short* TH = (unsigned short*)smc;
                unsigned short* TL = (unsigned short*)(smc + 34816);
                hilo16(v00, hh, ll);
                TH[coll * VT_ST + row0] = hh;
                TL[coll * VT_ST + row0] = ll;
                hilo16(v01, hh, ll);
                TH[(coll + 1) * VT_ST + row0] = hh;
                TL[(coll + 1) * VT_ST + row0] = ll;
                hilo16(v10, hh, ll);
                TH[coll * VT_ST + row0 + 8] = hh;
                TL[coll * VT_ST + row0 + 8] = ll;
                hilo16(v11, hh, ll);
                TH[(coll + 1) * VT_ST + row0 + 8] = hh;
                TL[(coll + 1) * VT_ST + row0 + 8] = ll;
            }
        }
        __syncthreads();
        #pragma unroll
        for (int it = 0; it < 8; it++) {
            int ch = tid + it * 256;         // 0..2047
            int drow = ch >> 4;
            int c8 = (ch & 15) * 8;
            if (m0 + c8 + 8 <= SP) {         // guard: last M-block overhangs SP
                uint4 vh = *(uint4*)(smc + (uint32_t)(drow * VT_ST + c8) * 2);
                uint4 vl = *(uint4*)(smc + 34816 + (uint32_t)(drow * VT_ST + c8) * 2);
                *(uint4*)(args.vth + (size_t)(n0 + drow) * SP + m0 + c8) = vh;
                *(uint4*)(args.vtl + (size_t)(n0 + drow) * SP + m0 + c8) = vl;
            }
        }
    } else {
        #pragma unroll
        for (int mt = 0; mt < 4; mt++) {
            #pragma unroll
            for (int nt = 0; nt < 4; nt++) {
                int row = m0 + wm * 64 + mt * 16 + (lane >> 2);
                int col = n0 + wn * 32 + nt * 8 + (lane & 3) * 2;
                float b0 = 0.f, b1 = 0.f;
                if (!splitk) { b0 = bias[col]; b1 = bias[col + 1]; }
                if (row < M)
                    *(float2*)&C[(size_t)row * DIM + col] =
                        make_float2(c[mt][nt][0] + b0, c[mt][nt][1] + b1);
                if (row + 8 < M)
                    *(float2*)&C[(size_t)(row + 8) * DIM + col] =
                        make_float2(c[mt][nt][2] + b0, c[mt][nt][3] + b1);
            }
        }
    }
}

// ================= add split-K partials + bias (3-way) =================
__global__ __launch_bounds__(256)
void addbias_kernel(const float* __restrict__ p0, const float* __restrict__ p1,
                    const float* __restrict__ p2, const float* __restrict__ bias,
                    float* __restrict__ out) {
    int i = blockIdx.x * 256 + threadIdx.x;
    const int tot4 = S_TOT * DIM / 4;
    if (i >= tot4) return;
    float4 a = ((const float4*)p0)[i];
    float4 b = ((const float4*)p1)[i];
    float4 d = ((const float4*)p2)[i];
    float4 bb = ((const float4*)bias)[i % (DIM / 4)];
    ((float4*)out)[i] = make_float4(a.x + b.x + d.x + bb.x, a.y + b.y + d.y + bb.y,
                                    a.z + b.z + d.z + bb.z, a.w + b.w + d.w + bb.w);
}

// ================= HMMA flash attention (3-way split-KV, double-buffered K/V) ==========
#define F_QST 136
#define F_VST 72
#define F_QH   0
#define F_QL   34816
#define F_STG  69632
#define F_STGB 71680          // KH 17408 | KL 17408 | VTH 18432 | VTL 18432
#define F_SMEM (F_STG + 2 * F_STGB)   // 212992

__global__ __launch_bounds__(256, 1)
void flash_mma(const __nv_bfloat16* __restrict__ Qh, const __nv_bfloat16* __restrict__ Ql,
               const __nv_bfloat16* __restrict__ Kh, const __nv_bfloat16* __restrict__ Kl,
               const __half* __restrict__ Vh, const __half* __restrict__ Vl,
               float* __restrict__ O0, float* __restrict__ O1, float* __restrict__ O2,
               float* __restrict__ stat, const int* __restrict__ seq_lens) {
    extern __shared__ char smc[];
    const uint32_t sb = smem_u32(smc);
    const int tid = threadIdx.x;
    const int lane = tid & 31;
    const int wid = tid >> 5;
    const int r0w = wid * 16;
    const int h = blockIdx.y;
    const int q0 = blockIdx.x * 128;
    const int sp = blockIdx.z;                      // 0,1,2
    const int t_begin = (sp == 0) ? 0 : 21 + (sp - 1) * 20;
    const int t_cnt   = (sp == 0) ? 21 : 20;
    const int seqlen = seq_lens[0];
    const float scale2 = 0.08838834764831845f * 1.4426950408889634f;  // /sqrt(128)*log2(e)

    // ---- load Q tile [128 x 128] hi/lo ----
    #pragma unroll
    for (int cix = 0; cix < 8; cix++) {
        int ch = tid + cix * 256;
        int row = ch >> 4, cc = (ch & 15) * 8;
        uint32_t so = (uint32_t)(row * F_QST + cc) * 2;
        uint4 vh = make_uint4(0,0,0,0), vl = make_uint4(0,0,0,0);
        if (q0 + row < S_TOT) {
            size_t gq = (size_t)(q0 + row) * DIM + h * HD + cc;
            vh = *(const uint4*)(Qh + gq);
            vl = *(const uint4*)(Ql + gq);
        }
        *(uint4*)(smc + F_QH + so) = vh;
        *(uint4*)(smc + F_QL + so) = vl;
    }

    auto kv_stage = [&](int gt, int buf) {
        const int k0 = gt * 64;
        const uint32_t base = sb + F_STG + (uint32_t)buf * F_STGB;
        #pragma unroll
        for (int cix = 0; cix < 4; cix++) {
            int ch = tid + cix * 256;            // 0..1023
            {
                int row = ch >> 4, cc = (ch & 15) * 8;
                uint32_t so = (uint32_t)(row * F_QST + cc) * 2;
                int sz = (k0 + row < S_TOT) ? 16 : 0;
                const __nv_bfloat16* gh = Kh + (size_t)(k0 + row) * DIM + h * HD + cc;
                const __nv_bfloat16* gl = Kl + (size_t)(k0 + row) * DIM + h * HD + cc;
                CP16(base + so, gh, sz);
                CP16(base + 17408 + so, gl, sz);
            }
            {
                int row = ch >> 3, cc = (ch & 7) * 8;
                uint32_t so = (uint32_t)(row * F_VST + cc) * 2;
                const __half* gvh = Vh + (size_t)(h * HD + row) * SP + k0 + cc;
                const __half* gvl = Vl + (size_t)(h * HD + row) * SP + k0 + cc;
                CP16(base + 34816 + so, gvh, 16);
                CP16(base + 53248 + so, gvl, 16);
            }
        }
        CP_COMMIT();
    };

    kv_stage(t_begin, 0);

    float m0s = -1e30f, m1s = -1e30f, l0s = 0.f, l1s = 0.f;
    float o[16][4];
    #pragma unroll
    for (int i = 0; i < 16; i++)
        #pragma unroll
        for (int j = 0; j < 4; j++) o[i][j] = 0.f;

    const int a_row = (lane & 15);
    const int a_col = ((lane >> 1) & 8);
    const int b_row = (lane & 7) + ((lane & 16) >> 1);
    const int b_col = (lane & 8);

    for (int lt = 0; lt < t_cnt; lt++) {
        const int gt = t_begin + lt;
        const int k0 = gt * 64;
        CP_WAIT0();
        __syncthreads();
        if (lt + 1 < t_cnt) kv_stage(gt + 1, (lt + 1) & 1);

        const uint32_t kb = sb + F_STG + (uint32_t)(lt & 1) * F_STGB;
        const uint32_t kbh = kb, kbl = kb + 17408;
        const uint32_t vbh = kb + 34816, vbl = kb + 53248;

        // ---- S = Q K^T (bf16 3-pass) ----
        float c[8][4];
        #pragma unroll
        for (int nt = 0; nt < 8; nt++)
            #pragma unroll
            for (int j = 0; j < 4; j++) c[nt][j] = 0.f;

        #pragma unroll
        for (int kc8 = 0; kc8 < 8; kc8++) {
            const int kc = kc8 * 16;
            uint32_t aq[4], bkh[8][2], bkl[8][2];
            ldsm4(aq[0], aq[1], aq[2], aq[3],
                  sb + F_QH + (uint32_t)((r0w + a_row) * F_QST + kc + a_col) * 2);
            #pragma unroll
            for (int np = 0; np < 4; np++) {
                uint32_t r0, r1, r2, r3;
                ldsm4(r0, r1, r2, r3,
                      kbh + (uint32_t)((np * 16 + b_row) * F_QST + kc + b_col) * 2);
                bkh[np*2][0] = r0; bkh[np*2][1] = r1; bkh[np*2+1][0] = r2; bkh[np*2+1][1] = r3;
                ldsm4(r0, r1, r2, r3,
                      kbl + (uint32_t)((np * 16 + b_row) * F_QST + kc + b_col) * 2);
                bkl[np*2][0] = r0; bkl[np*2][1] = r1; bkl[np*2+1][0] = r2; bkl[np*2+1][1] = r3;
            }
            #pragma unroll
            for (int nt = 0; nt < 8; nt++) {
                mma16816(c[nt], aq, bkh[nt]);
                mma16816(c[nt], aq, bkl[nt]);
            }
            ldsm4(aq[0], aq[1], aq[2], aq[3],
                  sb + F_QL + (uint32_t)((r0w + a_row) * F_QST + kc + a_col) * 2);
            #pragma unroll
            for (int nt = 0; nt < 8; nt++)
                mma16816(c[nt], aq, bkh[nt]);
        }

        // ---- scale (log2 domain) + mask ----
        #pragma unroll
        for (int nt = 0; nt < 8; nt++) {
            int colb = k0 + nt * 8 + (lane & 3) * 2;
            #pragma unroll
            for (int j = 0; j < 4; j++) {
                float v = c[nt][j] * scale2;
                c[nt][j] = (colb + (j & 1) < seqlen) ? v : -1e30f;
            }
        }

        // ---- online softmax (exp2) ----
        float mx0 = -1e30f, mx1 = -1e30f;
        #pragma unroll
        for (int nt = 0; nt < 8; nt++) {
            mx0 = fmaxf(mx0, fmaxf(c[nt][0], c[nt][1]));
            mx1 = fmaxf(mx1, fmaxf(c[nt][2], c[nt][3]));
        }
        mx0 = fmaxf(mx0, __shfl_xor_sync(0xffffffffu, mx0, 1));
        mx0 = fmaxf(mx0, __shfl_xor_sync(0xffffffffu, mx0, 2));
        mx1 = fmaxf(mx1, __shfl_xor_sync(0xffffffffu, mx1, 1));
        mx1 = fmaxf(mx1, __shfl_xor_sync(0xffffffffu, mx1, 2));
        float mn0 = fmaxf(m0s, mx0), mn1 = fmaxf(m1s, mx1);
        float al0 = exp2f(m0s - mn0), al1 = exp2f(m1s - mn1);
        m0s = mn0; m1s = mn1;
        float ls0 = 0.f, ls1 = 0.f;
        #pragma unroll
        for (int nt = 0; nt < 8; nt++) {
            c[nt][0] = exp2f(c[nt][0] - mn0); ls0 += c[nt][0];
            c[nt][1] = exp2f(c[nt][1] - mn0); ls0 += c[nt][1];
            c[nt][2] = exp2f(c[nt][2] - mn1); ls1 += c[nt][2];
            c[nt][3] = exp2f(c[nt][3] - mn1); ls1 += c[nt][3];
        }
        ls0 += __shfl_xor_sync(0xffffffffu, ls0, 1);
        ls0 += __shfl_xor_sync(0xffffffffu, ls0, 2);
        ls1 += __shfl_xor_sync(0xffffffffu, ls1, 1);
        ls1 += __shfl_xor_sync(0xffffffffu, ls1, 2);
        l0s = l0s * al0 + ls0;
        l1s = l1s * al1 + ls1;

        // ---- pack P into fp16 A fragments (single precision level) ----
        uint32_t ph[4][4];
        #pragma unroll
        for (int kc2 = 0; kc2 < 4; kc2++) {
            ph[kc2][0] = pack_h2(c[2*kc2][0],   c[2*kc2][1]);
            ph[kc2][1] = pack_h2(c[2*kc2][2],   c[2*kc2][3]);
            ph[kc2][2] = pack_h2(c[2*kc2+1][0], c[2*kc2+1][1]);
            ph[kc2][3] = pack_h2(c[2*kc2+1][2], c[2*kc2+1][3]);
        }

        // ---- rescale O ----
        #pragma unroll
        for (int nt = 0; nt < 16; nt++) {
            o[nt][0] *= al0; o[nt][1] *= al0;
            o[nt][2] *= al1; o[nt][3] *= al1;
        }

        // ---- O += P V (fp16, 2 passes: Ph*Vh + Ph*Vl) ----
        #pragma unroll
        for (int kc2 = 0; kc2 < 4; kc2++) {
            #pragma unroll
            for (int np = 0; np < 8; np++) {
                uint32_t vh0, vh1, vh2, vh3, vl0, vl1, vl2, vl3;
                uint32_t ad = vbh + (uint32_t)((np * 16 + b_row) * F_VST + kc2 * 16 + b_col) * 2;
                ldsm4(vh0, vh1, vh2, vh3, ad);
                ad = vbl + (uint32_t)((np * 16 + b_row) * F_VST + kc2 * 16 + b_col) * 2;
                ldsm4(vl0, vl1, vl2, vl3, ad);
                uint32_t bh0[2] = {vh0, vh1}, bh1[2] = {vh2, vh3};
                uint32_t bl0[2] = {vl0, vl1}, bl1[2] = {vl2, vl3};
                mma16816h(o[2*np],   ph[kc2], bh0);
                mma16816h(o[2*np+1], ph[kc2], bh1);
                mma16816h(o[2*np],   ph[kc2], bl0);
                mma16816h(o[2*np+1], ph[kc2], bl1);
            }
        }
    }

    // ---- write UNNORMALIZED partial + stats ----
    float* Op = (sp == 0) ? O0 : ((sp == 1) ? O1 : O2);
    const int rA = q0 + r0w + (lane >> 2);
    const int rB = rA + 8;
    #pragma unroll
    for (int nt = 0; nt < 16; nt++) {
        int col = h * HD + nt * 8 + (lane & 3) * 2;
        if (rA < S_TOT)
            *(float2*)&Op[(size_t)rA * DIM + col] = make_float2(o[nt][0], o[nt][1]);
        if (rB < S_TOT)
            *(float2*)&Op[(size_t)rB * DIM + col] = make_float2(o[nt][2], o[nt][3]);
    }
    if ((lane & 3) == 0) {
        if (rA < S_TOT) {
            stat[STATIDX(sp, h, 0, rA)] = m0s;
            stat[STATIDX(sp, h, 1, rA)] = l0s;
        }
        if (rB < S_TOT) {
            stat[STATIDX(sp, h, 0, rB)] = m1s;
            stat[STATIDX(sp, h, 1, rB)] = l1s;
        }
    }
}

// ================= combine split-KV partials (3-way) =================
__global__ __launch_bounds__(128)
void combine_kernel(const float* __restrict__ O0, const float* __restrict__ O1,
                    const float* __restrict__ O2, const float* __restrict__ stat,
                    __nv_bfloat16* __restrict__ AOh, __nv_bfloat16* __restrict__ AOl) {
    const int s = blockIdx.x;
    const int h = blockIdx.y;
    const int c = threadIdx.x;
    float mA = stat[STATIDX(0, h, 0, s)], lA = stat[STATIDX(0, h, 1, s)];
    float mB = stat[STATIDX(1, h, 0, s)], lB = stat[STATIDX(1, h, 1, s)];
    float mC = stat[STATIDX(2, h, 0, s)], lC = stat[STATIDX(2, h, 1, s)];
    float m = fmaxf(fmaxf(mA, mB), mC);
    float aA = exp2f(mA - m), aB = exp2f(mB - m), aC = exp2f(mC - m);
    float inv = 1.f / (lA * aA + lB * aB + lC * aC);
    size_t idx = (size_t)s * DIM + h * HD + c;
    float o = (O0[idx] * aA + O1[idx] * aB + O2[idx] * aC) * inv;
    unsigned short hh, ll;
    hilo(o, hh, ll);
    AOh[idx] = __ushort_as_bfloat16(hh);
    AOl[idx] = __ushort_as_bfloat16(ll);
}

// ---------------- launch ----------------
extern "C" void kernel_launch(void* const* d_in, const int* in_sizes, int n_in,
                              void* d_out, int out_size) {
    const float* x        = (const float*)d_in[0];
    const int*   seq_lens = (const int*)  d_in[1];
    const int*   grid_sz  = (const int*)  d_in[2];
    const float* freqs    = (const float*)d_in[3];
    const float* Wq       = (const float*)d_in[4];
    const float* bq       = (const float*)d_in[5];
    const float* Wk       = (const float*)d_in[6];
    const float* bk       = (const float*)d_in[7];
    const float* Wv       = (const float*)d_in[8];
    const float* bv       = (const float*)d_in[9];
    const float* Wo       = (const float*)d_in[10];
    const float* bo       = (const float*)d_in[11];
    const float* gq       = (const float*)d_in[12];
    const float* gk       = (const float*)d_in[13];
    float* out = (float*)d_out;

    float *q, *k, *o2, *stat;
    __nv_bfloat16 *xh, *xl, *qh, *ql, *kh, *kl, *aoh, *aol;
    __half *vth, *vtl;
    __nv_bfloat16 *wthq, *wtlq, *wthk, *wtlk, *wthv, *wtlv, *wtho, *wtlo;
    cudaGetSymbolAddress((void**)&q, g_q);
    cudaGetSymbolAddress((void**)&k, g_k);
    cudaGetSymbolAddress((void**)&o2, g_o2);
    cudaGetSymbolAddress((void**)&stat, g_stat);
    cudaGetSymbolAddress((void**)&xh, g_xh);   cudaGetSymbolAddress((void**)&xl, g_xl);
    cudaGetSymbolAddress((void**)&qh, g_qh);   cudaGetSymbolAddress((void**)&ql, g_ql);
    cudaGetSymbolAddress((void**)&kh, g_kh);   cudaGetSymbolAddress((void**)&kl, g_kl);
    cudaGetSymbolAddress((void**)&aoh, g_aoh); cudaGetSymbolAddress((void**)&aol, g_aol);
    cudaGetSymbolAddress((void**)&vth, g_vth); cudaGetSymbolAddress((void**)&vtl, g_vtl);
    cudaGetSymbolAddress((void**)&wthq, g_wthq); cudaGetSymbolAddress((void**)&wtlq, g_wtlq);
    cudaGetSymbolAddress((void**)&wthk, g_wthk); cudaGetSymbolAddress((void**)&wtlk, g_wtlk);
    cudaGetSymbolAddress((void**)&wthv, g_wthv); cudaGetSymbolAddress((void**)&wtlv, g_wtlv);
    cudaGetSymbolAddress((void**)&wtho, g_wtho); cudaGetSymbolAddress((void**)&wtlo, g_wtlo);

    cudaFuncSetAttribute(gemm_mma, cudaFuncAttributeMaxDynamicSharedMemorySize, G_SMEM);
    cudaFuncSetAttribute(flash_mma, cudaFuncAttributeMaxDynamicSharedMemorySize, F_SMEM);

    // prep
    convert_x_kernel<<<S_TOT * DIM / 4 / 256, 256>>>(x, xh, xl);
    WPtrs wp;
    wp.w[0] = Wq; wp.th[0] = wthq; wp.tl[0] = wtlq;
    wp.w[1] = Wk; wp.th[1] = wthk; wp.tl[1] = wtlk;
    wp.w[2] = Wv; wp.th[2] = wthv; wp.tl[2] = wtlv;
    wp.w[3] = Wo; wp.th[3] = wtho; wp.tl[3] = wtlo;
    transw_kernel<<<dim3(48, 48, 4), dim3(32, 8)>>>(wp);

    // fused QKV projection; V written directly as transposed fp16 hi/lo
    QKVArgs aqkv;
    aqkv.bh[0] = wthq; aqkv.bl[0] = wtlq; aqkv.bias[0] = bq; aqkv.c[0] = q;
    aqkv.bh[1] = wthk; aqkv.bl[1] = wtlk; aqkv.bias[1] = bk; aqkv.c[1] = k;
    aqkv.bh[2] = wthv; aqkv.bl[2] = wtlv; aqkv.bias[2] = bv; aqkv.c[2] = nullptr;
    aqkv.vth = vth; aqkv.vtl = vtl;
    gemm_mma<<<dim3(36, 31), 256, G_SMEM>>>(xh, xl, aqkv, S_TOT, 0);

    rmsnorm_rope_conv<<<dim3(S_TOT, 2), 256>>>(q, gq, qh, ql, k, gk, kh, kl, freqs, grid_sz);

    // 3-way split-KV flash: partials into g_q, g_k, g_o2 (all free now)
    dim3 fg(31, NH, NSPLIT);
    flash_mma<<<fg, 256, F_SMEM>>>(qh, ql, kh, kl, vth, vtl, q, k, o2, stat, seq_lens);
    combine_kernel<<<dim3(S_TOT, NH), 128>>>(q, k, o2, stat, aoh, aol);

    // O projection: split-K=3 into fp32 partials (g_q, g_k, g_o2 free again), then add+bias
    QKVArgs aop;
    aop.bh[0] = wtho; aop.bl[0] = wtlo; aop.bias[0] = nullptr; aop.c[0] = q;
    aop.bh[1] = wtho; aop.bl[1] = wtlo; aop.bias[1] = nullptr; aop.c[1] = k;
    aop.bh[2] = wtho; aop.bl[2] = wtlo; aop.bias[2] = nullptr; aop.c[2] = o2;
    aop.vth = nullptr; aop.vtl = nullptr;
    gemm_mma<<<dim3(12, 31, 3), 256, G_SMEM>>>(aoh, aol, aop, S_TOT, 1);
    addbias_kernel<<<S_TOT * DIM / 4 / 256, 256>>>(q, k, o2, bo, out);
}

// round 12
// speedup vs baseline: 24.3835x; 1.2156x over previous
#include <cuda_runtime.h>
#include <cuda_bf16.h>
#include <cuda_fp16.h>
#include <math.h>
#include <stdint.h>

#define S_TOT 3900
#define SP    3904        // padded seq (61*64)
#define DIM   1536
#define NH    12
#define HD    128
#define CC    64
#define NTILES 61         // SP/64
#define NSPLIT 3          // flash KV splits

// ---------------- scratch ----------------
__device__ float g_q [S_TOT * DIM];   // q fp32 -> flash partial 0 -> O-proj partial 0
__device__ float g_k [S_TOT * DIM];   // k fp32 -> flash partial 1 -> O-proj partial 1
__device__ float g_o2[S_TOT * DIM];   // v fp32 unused; flash partial 2 -> O-proj partial 2
__device__ float g_stat[NSPLIT * NH * 2 * 4096];

__device__ __half g_x16 [S_TOT * DIM];    // x fp16 single
__device__ __half g_q16 [S_TOT * DIM];    // Q fp16 single (post rmsnorm+rope)
__device__ __half g_kh16[S_TOT * DIM];    // K fp16 hi
__device__ __half g_kl16[S_TOT * DIM];    // K fp16 lo
__device__ __half g_ao16[S_TOT * DIM];    // attention out fp16 single
__device__ __half g_vth [DIM * SP];       // V transposed fp16 hi
__device__ __half g_vtl [DIM * SP];       // V transposed fp16 lo

__device__ __half g_wthq[DIM * DIM];
__device__ __half g_wtlq[DIM * DIM];
__device__ __half g_wthk[DIM * DIM];
__device__ __half g_wtlk[DIM * DIM];
__device__ __half g_wthv[DIM * DIM];
__device__ __half g_wtlv[DIM * DIM];
__device__ __half g_wtho[DIM * DIM];
__device__ __half g_wtlo[DIM * DIM];

// ================= helpers =================
__device__ __forceinline__ uint32_t smem_u32(const void* p) {
    uint32_t a;
    asm("{ .reg .u64 t; cvta.to.shared.u64 t, %1; cvt.u32.u64 %0, t; }" : "=r"(a) : "l"(p));
    return a;
}
__device__ __forceinline__ void ldsm4(uint32_t& r0, uint32_t& r1, uint32_t& r2, uint32_t& r3,
                                      uint32_t addr) {
    asm volatile("ldmatrix.sync.aligned.m8n8.x4.shared.b16 {%0,%1,%2,%3}, [%4];"
                 : "=r"(r0), "=r"(r1), "=r"(r2), "=r"(r3) : "r"(addr));
}
__device__ __forceinline__ void mma16816h(float* c, const uint32_t* a, const uint32_t* b) {
    asm volatile(
        "mma.sync.aligned.m16n8k16.row.col.f32.f16.f16.f32 "
        "{%0,%1,%2,%3}, {%4,%5,%6,%7}, {%8,%9}, {%0,%1,%2,%3};"
        : "+f"(c[0]), "+f"(c[1]), "+f"(c[2]), "+f"(c[3])
        : "r"(a[0]), "r"(a[1]), "r"(a[2]), "r"(a[3]), "r"(b[0]), "r"(b[1]));
}
#define CP16(dst, src, sz) \
    asm volatile("cp.async.cg.shared.global [%0], [%1], 16, %2;" \
        :: "r"(dst), "l"(src), "r"(sz) : "memory")
#define CP_COMMIT() asm volatile("cp.async.commit_group;" ::: "memory")
#define CP_WAIT0()  asm volatile("cp.async.wait_group 0;" ::: "memory")

__device__ __forceinline__ void hilo16(float x, unsigned short& h, unsigned short& l) {
    __half hh = __float2half_rn(x);
    h = __half_as_ushort(hh);
    l = __half_as_ushort(__float2half_rn(x - __half2float(hh)));
}
__device__ __forceinline__ uint32_t pack_h2(float x, float y) {
    __half2 t = __floats2half2_rn(x, y);
    return *(uint32_t*)&t;
}
#define STATIDX(sp, hh, ml, s) ((((sp) * NH + (hh)) * 2 + (ml)) * 4096 + (s))

// ================= prep kernels =================
__global__ __launch_bounds__(256)
void convert_x_kernel(const float* __restrict__ x, __half* __restrict__ x16) {
    int i = blockIdx.x * 256 + threadIdx.x;
    const int tot4 = S_TOT * DIM / 4;
    if (i >= tot4) return;
    float4 v = ((const float4*)x)[i];
    ((uint2*)x16)[i] = make_uint2(pack_h2(v.x, v.y), pack_h2(v.z, v.w));
}

// W[K][N] fp32 -> Wt[N][K] fp16 hi/lo ; 4 weights in one launch (blockIdx.z)
struct WPtrs { const float* w[4]; __half* th[4]; __half* tl[4]; };

__global__ __launch_bounds__(256)
void transw_kernel(WPtrs p) {
    __shared__ float t[32][33];
    const float* W = p.w[blockIdx.z];
    __half* Th = p.th[blockIdx.z];
    __half* Tl = p.tl[blockIdx.z];
    const int n0 = blockIdx.x * 32, k0 = blockIdx.y * 32;
    const int tx = threadIdx.x, ty = threadIdx.y;
    #pragma unroll
    for (int i = 0; i < 4; i++)
        t[ty + i * 8][tx] = W[(size_t)(k0 + ty + i * 8) * DIM + n0 + tx];
    __syncthreads();
    #pragma unroll
    for (int i = 0; i < 4; i++) {
        float v = t[tx][ty + i * 8];
        unsigned short h, l; hilo16(v, h, l);
        size_t o = (size_t)(n0 + ty + i * 8) * DIM + k0 + tx;
        Th[o] = __ushort_as_half(h);
        Tl[o] = __ushort_as_half(l);
    }
}

// RMSNorm + RoPE: y==0 -> Q fp16 single; y==1 -> K fp16 hi/lo
__global__ __launch_bounds__(256)
void rmsnorm_rope_conv(const float* __restrict__ tq, const float* __restrict__ gq,
                       __half* __restrict__ qo16,
                       const float* __restrict__ tk, const float* __restrict__ gk,
                       __half* __restrict__ koh, __half* __restrict__ kol,
                       const float* __restrict__ freqs, const int* __restrict__ grid_sizes) {
    const int s = blockIdx.x;
    const int tid = threadIdx.x;
    const int isq = (blockIdx.y == 0);
    const float* t  = isq ? tq : tk;
    const float* g  = isq ? gq : gk;
    const float* row = t + (size_t)s * DIM;

    float ss = 0.f;
    for (int i = tid; i < DIM / 4; i += 256) {
        float4 v = ((const float4*)row)[i];
        ss += v.x * v.x + v.y * v.y + v.z * v.z + v.w * v.w;
    }
    #pragma unroll
    for (int off = 16; off; off >>= 1) ss += __shfl_xor_sync(0xffffffffu, ss, off);
    __shared__ float red[8];
    if ((tid & 31) == 0) red[tid >> 5] = ss;
    __syncthreads();
    if (tid == 0) {
        float tot = 0.f;
        #pragma unroll
        for (int i = 0; i < 8; i++) tot += red[i];
        red[0] = tot;
    }
    __syncthreads();
    const float inv = rsqrtf(red[0] * (1.f / DIM) + 1e-6f);

    const int H = grid_sizes[1], W = grid_sizes[2];
    const int fi = s / (H * W);
    const int rem = s % (H * W);
    const int hi = rem / W;
    const int wi = rem % W;
    const int c3 = CC / 3, c0 = CC - 2 * c3;

    for (int p = tid; p < NH * CC; p += 256) {
        int j = p % CC;
        int head = p / CC;
        int idx = head * HD + 2 * j;
        float a = row[idx]     * inv * g[idx];
        float b = row[idx + 1] * inv * g[idx + 1];
        int pos = (j < c0) ? fi : ((j < c0 + c3) ? hi : wi);
        float cs = freqs[(pos * CC + j) * 2 + 0];
        float sn = freqs[(pos * CC + j) * 2 + 1];
        float ra = a * cs - b * sn;
        float rb = a * sn + b * cs;
        if (isq) {
            *(uint32_t*)(qo16 + (size_t)s * DIM + idx) = pack_h2(ra, rb);
        } else {
            unsigned short ha, la, hb, lb;
            hilo16(ra, ha, la); hilo16(rb, hb, lb);
            *(uint32_t*)(koh + (size_t)s * DIM + idx) = (uint32_t)ha | ((uint32_t)hb << 16);
            *(uint32_t*)(kol + (size_t)s * DIM + idx) = (uint32_t)la | ((uint32_t)lb << 16);
        }
    }
}

// ================= HMMA GEMM: fp16 single-A x fp16 hi/lo-B, 2 passes =================
#define G_ST   40
#define G_BUFB 10240
#define G_AS   0               // 2 bufs: 0..20480
#define G_BSH  20480
#define G_BSL  40960
#define G_SMEM 69632           // covers main path (61440) + V staging (2x34816)
#define VT_ST  136             // transposed V staging stride (elems)

struct QKVArgs {
    const __half* bh[3];
    const __half* bl[3];
    const float* bias[3];
    float* c[3];
    __half* vth;               // if non-null: mat==2 writes transposed fp16 hi/lo
    __half* vtl;
};

__global__ __launch_bounds__(256)
void gemm_mma(const __half* __restrict__ A, QKVArgs args, int M, int splitk) {
    extern __shared__ char smc[];
    const uint32_t sb = smem_u32(smc);
    const int tid = threadIdx.x;
    const int lane = tid & 31;
    const int wid = tid >> 5;
    const int wm = wid & 1;
    const int wn = wid >> 1;
    int mat = blockIdx.x / 12;
    const int n0 = (blockIdx.x % 12) * 128;
    const int m0 = blockIdx.y * 128;
    int kt0 = 0, ktn = 48;
    if (splitk) { kt0 = blockIdx.z * 16; ktn = 16; mat = blockIdx.z; }
    const __half* Bh = args.bh[splitk ? 0 : mat];
    const __half* Bl = args.bl[splitk ? 0 : mat];
    const float* bias = args.bias[mat];
    float* C = args.c[mat];

    float c[4][4][4];
    #pragma unroll
    for (int i = 0; i < 4; i++)
        #pragma unroll
        for (int j = 0; j < 4; j++)
            #pragma unroll
            for (int q = 0; q < 4; q++) c[i][j][q] = 0.f;

    auto stage = [&](int kt, int buf) {
        const int k0 = kt * 32;
        #pragma unroll
        for (int cix = 0; cix < 2; cix++) {
            int ch = tid + cix * 256;           // 0..511
            int row = ch >> 2, cc = (ch & 3) * 8;
            uint32_t so = (uint32_t)(row * G_ST + cc) * 2 + (uint32_t)buf * G_BUFB;
            int szA = (m0 + row < M) ? 16 : 0;
            const __half* pa  = A  + (size_t)(m0 + row) * DIM + k0 + cc;
            const __half* pbh = Bh + (size_t)(n0 + row) * DIM + k0 + cc;
            const __half* pbl = Bl + (size_t)(n0 + row) * DIM + k0 + cc;
            CP16(sb + G_AS  + so, pa,  szA);
            CP16(sb + G_BSH + so, pbh, 16);
            CP16(sb + G_BSL + so, pbl, 16);
        }
        CP_COMMIT();
    };

    stage(kt0, 0);

    const int a_row = (lane & 15);
    const int a_col = ((lane >> 1) & 8);
    const int b_row = (lane & 7) + ((lane & 16) >> 1);
    const int b_col = (lane & 8);

    for (int kti = 0; kti < ktn; kti++) {
        CP_WAIT0();
        __syncthreads();
        if (kti < ktn - 1) stage(kt0 + kti + 1, (kti + 1) & 1);
        const int bo = (kti & 1) * G_BUFB;
        #pragma unroll
        for (int kc = 0; kc < 32; kc += 16) {
            uint32_t af[4][4], bfh[4][2], bfl[4][2];
            #pragma unroll
            for (int mt = 0; mt < 4; mt++)
                ldsm4(af[mt][0], af[mt][1], af[mt][2], af[mt][3],
                      sb + G_AS + bo + (uint32_t)((wm * 64 + mt * 16 + a_row) * G_ST + kc + a_col) * 2);
            #pragma unroll
            for (int np = 0; np < 2; np++) {
                uint32_t r0, r1, r2, r3;
                uint32_t ad = sb + G_BSH + bo +
                    (uint32_t)((wn * 32 + np * 16 + b_row) * G_ST + kc + b_col) * 2;
                ldsm4(r0, r1, r2, r3, ad);
                bfh[np*2][0] = r0; bfh[np*2][1] = r1; bfh[np*2+1][0] = r2; bfh[np*2+1][1] = r3;
                ad = sb + G_BSL + bo +
                    (uint32_t)((wn * 32 + np * 16 + b_row) * G_ST + kc + b_col) * 2;
                ldsm4(r0, r1, r2, r3, ad);
                bfl[np*2][0] = r0; bfl[np*2][1] = r1; bfl[np*2+1][0] = r2; bfl[np*2+1][1] = r3;
            }
            #pragma unroll
            for (int mt = 0; mt < 4; mt++)
                #pragma unroll
                for (int nt = 0; nt < 4; nt++) {
                    mma16816h(c[mt][nt], af[mt], bfh[nt]);
                    mma16816h(c[mt][nt], af[mt], bfl[nt]);
                }
        }
        __syncthreads();
    }

    if (args.vth != nullptr && mat == 2) {
        // ---- V epilogue: transposed fp16 hi/lo via smem staging ----
        #pragma unroll
        for (int mt = 0; mt < 4; mt++) {
            #pragma unroll
            for (int nt = 0; nt < 4; nt++) {
                int row0 = wm * 64 + mt * 16 + (lane >> 2);
                int coll = wn * 32 + nt * 8 + (lane & 3) * 2;
                float b0 = bias[n0 + coll], b1 = bias[n0 + coll + 1];
                float v00 = c[mt][nt][0] + b0, v01 = c[mt][nt][1] + b1;
                float v10 = c[mt][nt][2] + b0, v11 = c[mt][nt][3] + b1;
                unsigned short hh, ll;
                unsigned short* TH = (unsigned short*)smc;
                unsigned short* TL = (unsigned short*)(smc + 34816);
                hilo16(v00, hh, ll);
                TH[coll * VT_ST + row0] = hh;
                TL[coll * VT_ST + row0] = ll;
                hilo16(v01, hh, ll);
                TH[(coll + 1) * VT_ST + row0] = hh;
                TL[(coll + 1) * VT_ST + row0] = ll;
                hilo16(v10, hh, ll);
                TH[coll * VT_ST + row0 + 8] = hh;
                TL[coll * VT_ST + row0 + 8] = ll;
                hilo16(v11, hh, ll);
                TH[(coll + 1) * VT_ST + row0 + 8] = hh;
                TL[(coll + 1) * VT_ST + row0 + 8] = ll;
            }
        }
        __syncthreads();
        #pragma unroll
        for (int it = 0; it < 8; it++) {
            int ch = tid + it * 256;         // 0..2047
            int drow = ch >> 4;
            int c8 = (ch & 15) * 8;
            if (m0 + c8 + 8 <= SP) {         // guard: last M-block overhangs SP
                uint4 vh = *(uint4*)(smc + (uint32_t)(drow * VT_ST + c8) * 2);
                uint4 vl = *(uint4*)(smc + 34816 + (uint32_t)(drow * VT_ST + c8) * 2);
                *(uint4*)(args.vth + (size_t)(n0 + drow) * SP + m0 + c8) = vh;
                *(uint4*)(args.vtl + (size_t)(n0 + drow) * SP + m0 + c8) = vl;
            }
        }
    } else {
        #pragma unroll
        for (int mt = 0; mt < 4; mt++) {
            #pragma unroll
            for (int nt = 0; nt < 4; nt++) {
                int row = m0 + wm * 64 + mt * 16 + (lane >> 2);
                int col = n0 + wn * 32 + nt * 8 + (lane & 3) * 2;
                float b0 = 0.f, b1 = 0.f;
                if (!splitk) { b0 = bias[col]; b1 = bias[col + 1]; }
                if (row < M)
                    *(float2*)&C[(size_t)row * DIM + col] =
                        make_float2(c[mt][nt][0] + b0, c[mt][nt][1] + b1);
                if (row + 8 < M)
                    *(float2*)&C[(size_t)(row + 8) * DIM + col] =
                        make_float2(c[mt][nt][2] + b0, c[mt][nt][3] + b1);
            }
        }
    }
}

// ================= add split-K partials + bias (3-way) =================
__global__ __launch_bounds__(256)
void addbias_kernel(const float* __restrict__ p0, const float* __restrict__ p1,
                    const float* __restrict__ p2, const float* __restrict__ bias,
                    float* __restrict__ out) {
    int i = blockIdx.x * 256 + threadIdx.x;
    const int tot4 = S_TOT * DIM / 4;
    if (i >= tot4) return;
    float4 a = ((const float4*)p0)[i];
    float4 b = ((const float4*)p1)[i];
    float4 d = ((const float4*)p2)[i];
    float4 bb = ((const float4*)bias)[i % (DIM / 4)];
    ((float4*)out)[i] = make_float4(a.x + b.x + d.x + bb.x, a.y + b.y + d.y + bb.y,
                                    a.z + b.z + d.z + bb.z, a.w + b.w + d.w + bb.w);
}

// ================= HMMA flash attention: fp16, QK 2-pass, PV 2-pass =================
#define F_QST 136
#define F_VST 72
#define F_Q    0               // Q fp16 single: 128*136*2 = 34816
#define F_STG  34816
#define F_STGB 71680           // KH 17408 | KL 17408 | VTH 18432 | VTL 18432
#define F_SMEM (F_STG + 2 * F_STGB)   // 178176

__global__ __launch_bounds__(256, 1)
void flash_mma(const __half* __restrict__ Q16,
               const __half* __restrict__ Kh, const __half* __restrict__ Kl,
               const __half* __restrict__ Vh, const __half* __restrict__ Vl,
               float* __restrict__ O0, float* __restrict__ O1, float* __restrict__ O2,
               float* __restrict__ stat, const int* __restrict__ seq_lens) {
    extern __shared__ char smc[];
    const uint32_t sb = smem_u32(smc);
    const int tid = threadIdx.x;
    const int lane = tid & 31;
    const int wid = tid >> 5;
    const int r0w = wid * 16;
    const int h = blockIdx.y;
    const int q0 = blockIdx.x * 128;
    const int sp = blockIdx.z;                      // 0,1,2
    const int t_begin = (sp == 0) ? 0 : 21 + (sp - 1) * 20;
    const int t_cnt   = (sp == 0) ? 21 : 20;
    const int seqlen = seq_lens[0];
    const float scale2 = 0.08838834764831845f * 1.4426950408889634f;  // /sqrt(128)*log2(e)

    // ---- load Q tile [128 x 128] fp16 single ----
    #pragma unroll
    for (int cix = 0; cix < 4; cix++) {
        int ch = tid + cix * 256;                   // 0..1023 wait: 2048 chunks? no: 32768B/16 = 2048
        // handled below with 8 iterations of 256 over 2048 chunks
        (void)ch;
    }
    #pragma unroll
    for (int cix = 0; cix < 8; cix++) {
        int ch = tid + cix * 256;                   // 0..2047
        int row = ch >> 4, cc = (ch & 15) * 8;
        if ((ch & 15) < 16) {
            // 128 cols fp16 = 256 B per row = 16 chunks; row = ch>>4 valid 0..127
        }
        if (cix < 8) {
            // Q chunk: 16 chunks/row x 128 rows = 2048; but 128 cols*2B=256B → 16 chunks ✓
        }
        uint4 v = make_uint4(0, 0, 0, 0);
        if (q0 + row < S_TOT)
            v = *(const uint4*)(Q16 + (size_t)(q0 + row) * DIM + h * HD + cc);
        *(uint4*)(smc + F_Q + (uint32_t)(row * F_QST + cc) * 2) = v;
    }

    auto kv_stage = [&](int gt, int buf) {
        const int k0 = gt * 64;
        const uint32_t base = sb + F_STG + (uint32_t)buf * F_STGB;
        #pragma unroll
        for (int cix = 0; cix < 4; cix++) {
            int ch = tid + cix * 256;            // 0..1023
            {
                int row = ch >> 4, cc = (ch & 15) * 8;
                uint32_t so = (uint32_t)(row * F_QST + cc) * 2;
                int sz = (k0 + row < S_TOT) ? 16 : 0;
                const __half* gh = Kh + (size_t)(k0 + row) * DIM + h * HD + cc;
                const __half* gl = Kl + (size_t)(k0 + row) * DIM + h * HD + cc;
                CP16(base + so, gh, sz);
                CP16(base + 17408 + so, gl, sz);
            }
            {
                int row = ch >> 3, cc = (ch & 7) * 8;
                uint32_t so = (uint32_t)(row * F_VST + cc) * 2;
                const __half* gvh = Vh + (size_t)(h * HD + row) * SP + k0 + cc;
                const __half* gvl = Vl + (size_t)(h * HD + row) * SP + k0 + cc;
                CP16(base + 34816 + so, gvh, 16);
                CP16(base + 53248 + so, gvl, 16);
            }
        }
        CP_COMMIT();
    };

    kv_stage(t_begin, 0);

    float m0s = -1e30f, m1s = -1e30f, l0s = 0.f, l1s = 0.f;
    float o[16][4];
    #pragma unroll
    for (int i = 0; i < 16; i++)
        #pragma unroll
        for (int j = 0; j < 4; j++) o[i][j] = 0.f;

    const int a_row = (lane & 15);
    const int a_col = ((lane >> 1) & 8);
    const int b_row = (lane & 7) + ((lane & 16) >> 1);
    const int b_col = (lane & 8);

    for (int lt = 0; lt < t_cnt; lt++) {
        const int gt = t_begin + lt;
        const int k0 = gt * 64;
        CP_WAIT0();
        __syncthreads();
        if (lt + 1 < t_cnt) kv_stage(gt + 1, (lt + 1) & 1);

        const uint32_t kb = sb + F_STG + (uint32_t)(lt & 1) * F_STGB;
        const uint32_t kbh = kb, kbl = kb + 17408;
        const uint32_t vbh = kb + 34816, vbl = kb + 53248;

        // ---- S = Q K^T (fp16, 2 passes: Q*Kh + Q*Kl) ----
        float c[8][4];
        #pragma unroll
        for (int nt = 0; nt < 8; nt++)
            #pragma unroll
            for (int j = 0; j < 4; j++) c[nt][j] = 0.f;

        #pragma unroll
        for (int kc8 = 0; kc8 < 8; kc8++) {
            const int kc = kc8 * 16;
            uint32_t aq[4], bkh[8][2], bkl[8][2];
            ldsm4(aq[0], aq[1], aq[2], aq[3],
                  sb + F_Q + (uint32_t)((r0w + a_row) * F_QST + kc + a_col) * 2);
            #pragma unroll
            for (int np = 0; np < 4; np++) {
                uint32_t r0, r1, r2, r3;
                ldsm4(r0, r1, r2, r3,
                      kbh + (uint32_t)((np * 16 + b_row) * F_QST + kc + b_col) * 2);
                bkh[np*2][0] = r0; bkh[np*2][1] = r1; bkh[np*2+1][0] = r2; bkh[np*2+1][1] = r3;
                ldsm4(r0, r1, r2, r3,
                      kbl + (uint32_t)((np * 16 + b_row) * F_QST + kc + b_col) * 2);
                bkl[np*2][0] = r0; bkl[np*2][1] = r1; bkl[np*2+1][0] = r2; bkl[np*2+1][1] = r3;
            }
            #pragma unroll
            for (int nt = 0; nt < 8; nt++) {
                mma16816h(c[nt], aq, bkh[nt]);
                mma16816h(c[nt], aq, bkl[nt]);
            }
        }

        // ---- scale (log2 domain) + mask ----
        #pragma unroll
        for (int nt = 0; nt < 8; nt++) {
            int colb = k0 + nt * 8 + (lane & 3) * 2;
            #pragma unroll
            for (int j = 0; j < 4; j++) {
                float v = c[nt][j] * scale2;
                c[nt][j] = (colb + (j & 1) < seqlen) ? v : -1e30f;
            }
        }

        // ---- online softmax (exp2) ----
        float mx0 = -1e30f, mx1 = -1e30f;
        #pragma unroll
        for (int nt = 0; nt < 8; nt++) {
            mx0 = fmaxf(mx0, fmaxf(c[nt][0], c[nt][1]));
            mx1 = fmaxf(mx1, fmaxf(c[nt][2], c[nt][3]));
        }
        mx0 = fmaxf(mx0, __shfl_xor_sync(0xffffffffu, mx0, 1));
        mx0 = fmaxf(mx0, __shfl_xor_sync(0xffffffffu, mx0, 2));
        mx1 = fmaxf(mx1, __shfl_xor_sync(0xffffffffu, mx1, 1));
        mx1 = fmaxf(mx1, __shfl_xor_sync(0xffffffffu, mx1, 2));
        float mn0 = fmaxf(m0s, mx0), mn1 = fmaxf(m1s, mx1);
        float al0 = exp2f(m0s - mn0), al1 = exp2f(m1s - mn1);
        m0s = mn0; m1s = mn1;
        float ls0 = 0.f, ls1 = 0.f;
        #pragma unroll
        for (int nt = 0; nt < 8; nt++) {
            c[nt][0] = exp2f(c[nt][0] - mn0); ls0 += c[nt][0];
            c[nt][1] = exp2f(c[nt][1] - mn0); ls0 += c[nt][1];
            c[nt][2] = exp2f(c[nt][2] - mn1); ls1 += c[nt][2];
            c[nt][3] = exp2f(c[nt][3] - mn1); ls1 += c[nt][3];
        }
        ls0 += __shfl_xor_sync(0xffffffffu, ls0, 1);
        ls0 += __shfl_xor_sync(0xffffffffu, ls0, 2);
        ls1 += __shfl_xor_sync(0xffffffffu, ls1, 1);
        ls1 += __shfl_xor_sync(0xffffffffu, ls1, 2);
        l0s = l0s * al0 + ls0;
        l1s = l1s * al1 + ls1;

        // ---- pack P into fp16 A fragments ----
        uint32_t ph[4][4];
        #pragma unroll
        for (int kc2 = 0; kc2 < 4; kc2++) {
            ph[kc2][0] = pack_h2(c[2*kc2][0],   c[2*kc2][1]);
            ph[kc2][1] = pack_h2(c[2*kc2][2],   c[2*kc2][3]);
            ph[kc2][2] = pack_h2(c[2*kc2+1][0], c[2*kc2+1][1]);
            ph[kc2][3] = pack_h2(c[2*kc2+1][2], c[2*kc2+1][3]);
        }

        // ---- rescale O ----
        #pragma unroll
        for (int nt = 0; nt < 16; nt++) {
            o[nt][0] *= al0; o[nt][1] *= al0;
            o[nt][2] *= al1; o[nt][3] *= al1;
        }

        // ---- O += P V (fp16, 2 passes: P*Vh + P*Vl) ----
        #pragma unroll
        for (int kc2 = 0; kc2 < 4; kc2++) {
            #pragma unroll
            for (int np = 0; np < 8; np++) {
                uint32_t vh0, vh1, vh2, vh3, vl0, vl1, vl2, vl3;
                uint32_t ad = vbh + (uint32_t)((np * 16 + b_row) * F_VST + kc2 * 16 + b_col) * 2;
                ldsm4(vh0, vh1, vh2, vh3, ad);
                ad = vbl + (uint32_t)((np * 16 + b_row) * F_VST + kc2 * 16 + b_col) * 2;
                ldsm4(vl0, vl1, vl2, vl3, ad);
                uint32_t bh0[2] = {vh0, vh1}, bh1[2] = {vh2, vh3};
                uint32_t bl0[2] = {vl0, vl1}, bl1[2] = {vl2, vl3};
                mma16816h(o[2*np],   ph[kc2], bh0);
                mma16816h(o[2*np+1], ph[kc2], bh1);
                mma16816h(o[2*np],   ph[kc2], bl0);
                mma16816h(o[2*np+1], ph[kc2], bl1);
            }
        }
    }

    // ---- write UNNORMALIZED partial + stats ----
    float* Op = (sp == 0) ? O0 : ((sp == 1) ? O1 : O2);
    const int rA = q0 + r0w + (lane >> 2);
    const int rB = rA + 8;
    #pragma unroll
    for (int nt = 0; nt < 16; nt++) {
        int col = h * HD + nt * 8 + (lane & 3) * 2;
        if (rA < S_TOT)
            *(float2*)&Op[(size_t)rA * DIM + col] = make_float2(o[nt][0], o[nt][1]);
        if (rB < S_TOT)
            *(float2*)&Op[(size_t)rB * DIM + col] = make_float2(o[nt][2], o[nt][3]);
    }
    if ((lane & 3) == 0) {
        if (rA < S_TOT) {
            stat[STATIDX(sp, h, 0, rA)] = m0s;
            stat[STATIDX(sp, h, 1, rA)] = l0s;
        }
        if (rB < S_TOT) {
            stat[STATIDX(sp, h, 0, rB)] = m1s;
            stat[STATIDX(sp, h, 1, rB)] = l1s;
        }
    }
}

// ================= combine split-KV partials (3-way) -> fp16 single =================
__global__ __launch_bounds__(128)
void combine_kernel(const float* __restrict__ O0, const float* __restrict__ O1,
                    const float* __restrict__ O2, const float* __restrict__ stat,
                    __half* __restrict__ AO16) {
    const int s = blockIdx.x;
    const int h = blockIdx.y;
    const int c = threadIdx.x;
    float mA = stat[STATIDX(0, h, 0, s)], lA = stat[STATIDX(0, h, 1, s)];
    float mB = stat[STATIDX(1, h, 0, s)], lB = stat[STATIDX(1, h, 1, s)];
    float mC = stat[STATIDX(2, h, 0, s)], lC = stat[STATIDX(2, h, 1, s)];
    float m = fmaxf(fmaxf(mA, mB), mC);
    float aA = exp2f(mA - m), aB = exp2f(mB - m), aC = exp2f(mC - m);
    float inv = 1.f / (lA * aA + lB * aB + lC * aC);
    size_t idx = (size_t)s * DIM + h * HD + c;
    float o = (O0[idx] * aA + O1[idx] * aB + O2[idx] * aC) * inv;
    AO16[idx] = __float2half_rn(o);
}

// ---------------- launch ----------------
extern "C" void kernel_launch(void* const* d_in, const int* in_sizes, int n_in,
                              void* d_out, int out_size) {
    const float* x        = (const float*)d_in[0];
    const int*   seq_lens = (const int*)  d_in[1];
    const int*   grid_sz  = (const int*)  d_in[2];
    const float* freqs    = (const float*)d_in[3];
    const float* Wq       = (const float*)d_in[4];
    const float* bq       = (const float*)d_in[5];
    const float* Wk       = (const float*)d_in[6];
    const float* bk       = (const float*)d_in[7];
    const float* Wv       = (const float*)d_in[8];
    const float* bv       = (const float*)d_in[9];
    const float* Wo       = (const float*)d_in[10];
    const float* bo       = (const float*)d_in[11];
    const float* gq       = (const float*)d_in[12];
    const float* gk       = (const float*)d_in[13];
    float* out = (float*)d_out;

    float *q, *k, *o2, *stat;
    __half *x16, *q16, *kh16, *kl16, *ao16, *vth, *vtl;
    __half *wthq, *wtlq, *wthk, *wtlk, *wthv, *wtlv, *wtho, *wtlo;
    cudaGetSymbolAddress((void**)&q, g_q);
    cudaGetSymbolAddress((void**)&k, g_k);
    cudaGetSymbolAddress((void**)&o2, g_o2);
    cudaGetSymbolAddress((void**)&stat, g_stat);
    cudaGetSymbolAddress((void**)&x16, g_x16);
    cudaGetSymbolAddress((void**)&q16, g_q16);
    cudaGetSymbolAddress((void**)&kh16, g_kh16);
    cudaGetSymbolAddress((void**)&kl16, g_kl16);
    cudaGetSymbolAddress((void**)&ao16, g_ao16);
    cudaGetSymbolAddress((void**)&vth, g_vth);
    cudaGetSymbolAddress((void**)&vtl, g_vtl);
    cudaGetSymbolAddress((void**)&wthq, g_wthq); cudaGetSymbolAddress((void**)&wtlq, g_wtlq);
    cudaGetSymbolAddress((void**)&wthk, g_wthk); cudaGetSymbolAddress((void**)&wtlk, g_wtlk);
    cudaGetSymbolAddress((void**)&wthv, g_wthv); cudaGetSymbolAddress((void**)&wtlv, g_wtlv);
    cudaGetSymbolAddress((void**)&wtho, g_wtho); cudaGetSymbolAddress((void**)&wtlo, g_wtlo);

    cudaFuncSetAttribute(gemm_mma, cudaFuncAttributeMaxDynamicSharedMemorySize, G_SMEM);
    cudaFuncSetAttribute(flash_mma, cudaFuncAttributeMaxDynamicSharedMemorySize, F_SMEM);

    // prep
    convert_x_kernel<<<S_TOT * DIM / 4 / 256, 256>>>(x, x16);
    WPtrs wp;
    wp.w[0] = Wq; wp.th[0] = wthq; wp.tl[0] = wtlq;
    wp.w[1] = Wk; wp.th[1] = wthk; wp.tl[1] = wtlk;
    wp.w[2] = Wv; wp.th[2] = wthv; wp.tl[2] = wtlv;
    wp.w[3] = Wo; wp.th[3] = wtho; wp.tl[3] = wtlo;
    transw_kernel<<<dim3(48, 48, 4), dim3(32, 8)>>>(wp);

    // fused QKV projection; V written directly as transposed fp16 hi/lo
    QKVArgs aqkv;
    aqkv.bh[0] = wthq; aqkv.bl[0] = wtlq; aqkv.bias[0] = bq; aqkv.c[0] = q;
    aqkv.bh[1] = wthk; aqkv.bl[1] = wtlk; aqkv.bias[1] = bk; aqkv.c[1] = k;
    aqkv.bh[2] = wthv; aqkv.bl[2] = wtlv; aqkv.bias[2] = bv; aqkv.c[2] = nullptr;
    aqkv.vth = vth; aqkv.vtl = vtl;
    gemm_mma<<<dim3(36, 31), 256, G_SMEM>>>(x16, aqkv, S_TOT, 0);

    rmsnorm_rope_conv<<<dim3(S_TOT, 2), 256>>>(q, gq, q16, k, gk, kh16, kl16, freqs, grid_sz);

    // 3-way split-KV flash: partials into g_q, g_k, g_o2 (all free now)
    dim3 fg(31, NH, NSPLIT);
    flash_mma<<<fg, 256, F_SMEM>>>(q16, kh16, kl16, vth, vtl, q, k, o2, stat, seq_lens);
    combine_kernel<<<dim3(S_TOT, NH), 128>>>(q, k, o2, stat, ao16);

    // O projection: split-K=3 into fp32 partials (g_q, g_k, g_o2 free again), then add+bias
    QKVArgs aop;
    aop.bh[0] = wtho; aop.bl[0] = wtlo; aop.bias[0] = nullptr; aop.c[0] = q;
    aop.bh[1] = wtho; aop.bl[1] = wtlo; aop.bias[1] = nullptr; aop.c[1] = k;
    aop.bh[2] = wtho; aop.bl[2] = wtlo; aop.bias[2] = nullptr; aop.c[2] = o2;
    aop.vth = nullptr; aop.vtl = nullptr;
    gemm_mma<<<dim3(12, 31, 3), 256, G_SMEM>>>(ao16, aop, S_TOT, 1);
    addbias_kernel<<<S_TOT * DIM / 4 / 256, 256>>>(q, k, o2, bo, out);
}

// round 13
// speedup vs baseline: 40.6982x; 1.6691x over previous
#include <cuda_runtime.h>
#include <cuda_bf16.h>
#include <cuda_fp16.h>
#include <math.h>
#include <stdint.h>

#define S_TOT 3900
#define SP    3904        // padded seq (61*64)
#define DIM   1536
#define NH    12
#define HD    128
#define CC    64
#define NTILES 61         // SP/64
#define NSPLIT 3          // flash KV splits

// ---------------- scratch ----------------
__device__ float g_q [S_TOT * DIM];   // q fp32 -> flash partial 0 -> O-proj partial 0
__device__ float g_k [S_TOT * DIM];   // k fp32 -> flash partial 1 -> O-proj partial 1
__device__ float g_o2[S_TOT * DIM];   // flash partial 2 -> O-proj partial 2
__device__ float g_stat[NSPLIT * NH * 2 * 4096];

__device__ __half g_x16 [S_TOT * DIM];    // x fp16
__device__ __half g_q16 [S_TOT * DIM];    // Q fp16 (post rmsnorm+rope)
__device__ __half g_k16 [S_TOT * DIM];    // K fp16
__device__ __half g_ao16[S_TOT * DIM];    // attention out fp16
__device__ __half g_vt16[DIM * SP];       // V transposed fp16

__device__ __half g_w16q[DIM * DIM];
__device__ __half g_w16k[DIM * DIM];
__device__ __half g_w16v[DIM * DIM];
__device__ __half g_w16o[DIM * DIM];

// ================= helpers =================
__device__ __forceinline__ uint32_t smem_u32(const void* p) {
    uint32_t a;
    asm("{ .reg .u64 t; cvta.to.shared.u64 t, %1; cvt.u32.u64 %0, t; }" : "=r"(a) : "l"(p));
    return a;
}
__device__ __forceinline__ void ldsm4(uint32_t& r0, uint32_t& r1, uint32_t& r2, uint32_t& r3,
                                      uint32_t addr) {
    asm volatile("ldmatrix.sync.aligned.m8n8.x4.shared.b16 {%0,%1,%2,%3}, [%4];"
                 : "=r"(r0), "=r"(r1), "=r"(r2), "=r"(r3) : "r"(addr));
}
__device__ __forceinline__ void mma16816h(float* c, const uint32_t* a, const uint32_t* b) {
    asm volatile(
        "mma.sync.aligned.m16n8k16.row.col.f32.f16.f16.f32 "
        "{%0,%1,%2,%3}, {%4,%5,%6,%7}, {%8,%9}, {%0,%1,%2,%3};"
        : "+f"(c[0]), "+f"(c[1]), "+f"(c[2]), "+f"(c[3])
        : "r"(a[0]), "r"(a[1]), "r"(a[2]), "r"(a[3]), "r"(b[0]), "r"(b[1]));
}
#define CP16(dst, src, sz) \
    asm volatile("cp.async.cg.shared.global [%0], [%1], 16, %2;" \
        :: "r"(dst), "l"(src), "r"(sz) : "memory")
#define CP_COMMIT() asm volatile("cp.async.commit_group;" ::: "memory")
#define CP_WAIT0()  asm volatile("cp.async.wait_group 0;" ::: "memory")

__device__ __forceinline__ uint32_t pack_h2(float x, float y) {
    __half2 t = __floats2half2_rn(x, y);
    return *(uint32_t*)&t;
}
#define STATIDX(sp, hh, ml, s) ((((sp) * NH + (hh)) * 2 + (ml)) * 4096 + (s))

// ================= prep kernels =================
__global__ __launch_bounds__(256)
void convert_x_kernel(const float* __restrict__ x, __half* __restrict__ x16) {
    int i = blockIdx.x * 256 + threadIdx.x;
    const int tot4 = S_TOT * DIM / 4;
    if (i >= tot4) return;
    float4 v = ((const float4*)x)[i];
    ((uint2*)x16)[i] = make_uint2(pack_h2(v.x, v.y), pack_h2(v.z, v.w));
}

// W[K][N] fp32 -> Wt[N][K] fp16 ; 4 weights in one launch (blockIdx.z)
struct WPtrs { const float* w[4]; __half* t16[4]; };

__global__ __launch_bounds__(256)
void transw_kernel(WPtrs p) {
    __shared__ float t[32][33];
    const float* W = p.w[blockIdx.z];
    __half* T = p.t16[blockIdx.z];
    const int n0 = blockIdx.x * 32, k0 = blockIdx.y * 32;
    const int tx = threadIdx.x, ty = threadIdx.y;
    #pragma unroll
    for (int i = 0; i < 4; i++)
        t[ty + i * 8][tx] = W[(size_t)(k0 + ty + i * 8) * DIM + n0 + tx];
    __syncthreads();
    #pragma unroll
    for (int i = 0; i < 4; i++) {
        float v = t[tx][ty + i * 8];
        T[(size_t)(n0 + ty + i * 8) * DIM + k0 + tx] = __float2half_rn(v);
    }
}

// RMSNorm + RoPE -> fp16 (y==0 Q, y==1 K)
__global__ __launch_bounds__(256)
void rmsnorm_rope_conv(const float* __restrict__ tq, const float* __restrict__ gq,
                       __half* __restrict__ qo16,
                       const float* __restrict__ tk, const float* __restrict__ gk,
                       __half* __restrict__ ko16,
                       const float* __restrict__ freqs, const int* __restrict__ grid_sizes) {
    const int s = blockIdx.x;
    const int tid = threadIdx.x;
    const int isq = (blockIdx.y == 0);
    const float* t  = isq ? tq : tk;
    const float* g  = isq ? gq : gk;
    __half* o16 = isq ? qo16 : ko16;
    const float* row = t + (size_t)s * DIM;

    float ss = 0.f;
    for (int i = tid; i < DIM / 4; i += 256) {
        float4 v = ((const float4*)row)[i];
        ss += v.x * v.x + v.y * v.y + v.z * v.z + v.w * v.w;
    }
    #pragma unroll
    for (int off = 16; off; off >>= 1) ss += __shfl_xor_sync(0xffffffffu, ss, off);
    __shared__ float red[8];
    if ((tid & 31) == 0) red[tid >> 5] = ss;
    __syncthreads();
    if (tid == 0) {
        float tot = 0.f;
        #pragma unroll
        for (int i = 0; i < 8; i++) tot += red[i];
        red[0] = tot;
    }
    __syncthreads();
    const float inv = rsqrtf(red[0] * (1.f / DIM) + 1e-6f);

    const int H = grid_sizes[1], W = grid_sizes[2];
    const int fi = s / (H * W);
    const int rem = s % (H * W);
    const int hi = rem / W;
    const int wi = rem % W;
    const int c3 = CC / 3, c0 = CC - 2 * c3;

    for (int p = tid; p < NH * CC; p += 256) {
        int j = p % CC;
        int head = p / CC;
        int idx = head * HD + 2 * j;
        float a = row[idx]     * inv * g[idx];
        float b = row[idx + 1] * inv * g[idx + 1];
        int pos = (j < c0) ? fi : ((j < c0 + c3) ? hi : wi);
        float cs = freqs[(pos * CC + j) * 2 + 0];
        float sn = freqs[(pos * CC + j) * 2 + 1];
        float ra = a * cs - b * sn;
        float rb = a * sn + b * cs;
        *(uint32_t*)(o16 + (size_t)s * DIM + idx) = pack_h2(ra, rb);
    }
}

// ================= HMMA GEMM: fp16 x fp16, single pass =================
#define G_ST   40
#define G_BUFB 10240
#define G_AS   0               // 2 bufs: 0..20480
#define G_BS   20480           // 2 bufs: 20480..40960
#define G_SMEM 40960           // V staging (34816) fits inside
#define VT_ST  136

struct QKVArgs {
    const __half* b16[3];
    const float* bias[3];
    float* c[3];
    __half* vt16;              // if non-null: mat==2 writes transposed fp16
};

__global__ __launch_bounds__(256)
void gemm_mma(const __half* __restrict__ A, QKVArgs args, int M, int splitk) {
    extern __shared__ char smc[];
    const uint32_t sb = smem_u32(smc);
    const int tid = threadIdx.x;
    const int lane = tid & 31;
    const int wid = tid >> 5;
    const int wm = wid & 1;
    const int wn = wid >> 1;
    int mat = blockIdx.x / 12;
    const int n0 = (blockIdx.x % 12) * 128;
    const int m0 = blockIdx.y * 128;
    int kt0 = 0, ktn = 48;
    if (splitk) { kt0 = blockIdx.z * 16; ktn = 16; mat = blockIdx.z; }
    const __half* B = args.b16[splitk ? 0 : mat];
    const float* bias = args.bias[mat];
    float* C = args.c[mat];

    float c[4][4][4];
    #pragma unroll
    for (int i = 0; i < 4; i++)
        #pragma unroll
        for (int j = 0; j < 4; j++)
            #pragma unroll
            for (int q = 0; q < 4; q++) c[i][j][q] = 0.f;

    auto stage = [&](int kt, int buf) {
        const int k0 = kt * 32;
        #pragma unroll
        for (int cix = 0; cix < 2; cix++) {
            int ch = tid + cix * 256;           // 0..511
            int row = ch >> 2, cc = (ch & 3) * 8;
            uint32_t so = (uint32_t)(row * G_ST + cc) * 2 + (uint32_t)buf * G_BUFB;
            int szA = (m0 + row < M) ? 16 : 0;
            const __half* pa = A + (size_t)(m0 + row) * DIM + k0 + cc;
            const __half* pb = B + (size_t)(n0 + row) * DIM + k0 + cc;
            CP16(sb + G_AS + so, pa, szA);
            CP16(sb + G_BS + so, pb, 16);
        }
        CP_COMMIT();
    };

    stage(kt0, 0);

    const int a_row = (lane & 15);
    const int a_col = ((lane >> 1) & 8);
    const int b_row = (lane & 7) + ((lane & 16) >> 1);
    const int b_col = (lane & 8);

    for (int kti = 0; kti < ktn; kti++) {
        CP_WAIT0();
        __syncthreads();
        if (kti < ktn - 1) stage(kt0 + kti + 1, (kti + 1) & 1);
        const int bo = (kti & 1) * G_BUFB;
        #pragma unroll
        for (int kc = 0; kc < 32; kc += 16) {
            uint32_t af[4][4], bf[4][2];
            #pragma unroll
            for (int mt = 0; mt < 4; mt++)
                ldsm4(af[mt][0], af[mt][1], af[mt][2], af[mt][3],
                      sb + G_AS + bo + (uint32_t)((wm * 64 + mt * 16 + a_row) * G_ST + kc + a_col) * 2);
            #pragma unroll
            for (int np = 0; np < 2; np++) {
                uint32_t r0, r1, r2, r3;
                ldsm4(r0, r1, r2, r3,
                      sb + G_BS + bo + (uint32_t)((wn * 32 + np * 16 + b_row) * G_ST + kc + b_col) * 2);
                bf[np*2][0] = r0; bf[np*2][1] = r1; bf[np*2+1][0] = r2; bf[np*2+1][1] = r3;
            }
            #pragma unroll
            for (int mt = 0; mt < 4; mt++)
                #pragma unroll
                for (int nt = 0; nt < 4; nt++)
                    mma16816h(c[mt][nt], af[mt], bf[nt]);
        }
        __syncthreads();
    }

    if (args.vt16 != nullptr && mat == 2) {
        // ---- V epilogue: transposed fp16 via smem staging ----
        unsigned short* TH = (unsigned short*)smc;
        #pragma unroll
        for (int mt = 0; mt < 4; mt++) {
            #pragma unroll
            for (int nt = 0; nt < 4; nt++) {
                int row0 = wm * 64 + mt * 16 + (lane >> 2);
                int coll = wn * 32 + nt * 8 + (lane & 3) * 2;
                float b0 = bias[n0 + coll], b1 = bias[n0 + coll + 1];
                TH[coll * VT_ST + row0] =
                    __half_as_ushort(__float2half_rn(c[mt][nt][0] + b0));
                TH[(coll + 1) * VT_ST + row0] =
                    __half_as_ushort(__float2half_rn(c[mt][nt][1] + b1));
                TH[coll * VT_ST + row0 + 8] =
                    __half_as_ushort(__float2half_rn(c[mt][nt][2] + b0));
                TH[(coll + 1) * VT_ST + row0 + 8] =
                    __half_as_ushort(__float2half_rn(c[mt][nt][3] + b1));
            }
        }
        __syncthreads();
        #pragma unroll
        for (int it = 0; it < 8; it++) {
            int ch = tid + it * 256;         // 0..2047
            int drow = ch >> 4;
            int c8 = (ch & 15) * 8;
            if (m0 + c8 + 8 <= SP) {         // guard: last M-block overhangs SP
                uint4 v = *(uint4*)(smc + (uint32_t)(drow * VT_ST + c8) * 2);
                *(uint4*)(args.vt16 + (size_t)(n0 + drow) * SP + m0 + c8) = v;
            }
        }
    } else {
        #pragma unroll
        for (int mt = 0; mt < 4; mt++) {
            #pragma unroll
            for (int nt = 0; nt < 4; nt++) {
                int row = m0 + wm * 64 + mt * 16 + (lane >> 2);
                int col = n0 + wn * 32 + nt * 8 + (lane & 3) * 2;
                float b0 = 0.f, b1 = 0.f;
                if (!splitk) { b0 = bias[col]; b1 = bias[col + 1]; }
                if (row < M)
                    *(float2*)&C[(size_t)row * DIM + col] =
                        make_float2(c[mt][nt][0] + b0, c[mt][nt][1] + b1);
                if (row + 8 < M)
                    *(float2*)&C[(size_t)(row + 8) * DIM + col] =
                        make_float2(c[mt][nt][2] + b0, c[mt][nt][3] + b1);
            }
        }
    }
}

// ================= add split-K partials + bias (3-way) =================
__global__ __launch_bounds__(256)
void addbias_kernel(const float* __restrict__ p0, const float* __restrict__ p1,
                    const float* __restrict__ p2, const float* __restrict__ bias,
                    float* __restrict__ out) {
    int i = blockIdx.x * 256 + threadIdx.x;
    const int tot4 = S_TOT * DIM / 4;
    if (i >= tot4) return;
    float4 a = ((const float4*)p0)[i];
    float4 b = ((const float4*)p1)[i];
    float4 d = ((const float4*)p2)[i];
    float4 bb = ((const float4*)bias)[i % (DIM / 4)];
    ((float4*)out)[i] = make_float4(a.x + b.x + d.x + bb.x, a.y + b.y + d.y + bb.y,
                                    a.z + b.z + d.z + bb.z, a.w + b.w + d.w + bb.w);
}

// ================= HMMA flash attention: fp16 single, QK 1-pass, PV 1-pass ==========
#define F_QST 136
#define F_VST 72
#define F_Q    0               // Q fp16: 128*136*2 = 34816
#define F_STG  34816
#define F_STGB 35840           // K 17408 | V 18432
#define F_SMEM (F_STG + 2 * F_STGB)   // 106496 -> 2 CTAs/SM

__global__ __launch_bounds__(256)
void flash_mma(const __half* __restrict__ Q16, const __half* __restrict__ K16,
               const __half* __restrict__ V16,
               float* __restrict__ O0, float* __restrict__ O1, float* __restrict__ O2,
               float* __restrict__ stat, const int* __restrict__ seq_lens) {
    extern __shared__ char smc[];
    const uint32_t sb = smem_u32(smc);
    const int tid = threadIdx.x;
    const int lane = tid & 31;
    const int wid = tid >> 5;
    const int r0w = wid * 16;
    const int h = blockIdx.y;
    const int q0 = blockIdx.x * 128;
    const int sp = blockIdx.z;                      // 0,1,2
    const int t_begin = (sp == 0) ? 0 : 21 + (sp - 1) * 20;
    const int t_cnt   = (sp == 0) ? 21 : 20;
    const int seqlen = seq_lens[0];
    const float scale2 = 0.08838834764831845f * 1.4426950408889634f;  // /sqrt(128)*log2(e)

    // ---- load Q tile [128 x 128] fp16 ----
    #pragma unroll
    for (int cix = 0; cix < 8; cix++) {
        int ch = tid + cix * 256;                   // 0..2047
        int row = ch >> 4, cc = (ch & 15) * 8;
        uint4 v = make_uint4(0, 0, 0, 0);
        if (q0 + row < S_TOT)
            v = *(const uint4*)(Q16 + (size_t)(q0 + row) * DIM + h * HD + cc);
        *(uint4*)(smc + F_Q + (uint32_t)(row * F_QST + cc) * 2) = v;
    }

    auto kv_stage = [&](int gt, int buf) {
        const int k0 = gt * 64;
        const uint32_t base = sb + F_STG + (uint32_t)buf * F_STGB;
        #pragma unroll
        for (int cix = 0; cix < 4; cix++) {
            int ch = tid + cix * 256;            // 0..1023
            {
                int row = ch >> 4, cc = (ch & 15) * 8;
                int sz = (k0 + row < S_TOT) ? 16 : 0;
                const __half* gk = K16 + (size_t)(k0 + row) * DIM + h * HD + cc;
                CP16(base + (uint32_t)(row * F_QST + cc) * 2, gk, sz);
            }
            {
                int row = ch >> 3, cc = (ch & 7) * 8;
                const __half* gv = V16 + (size_t)(h * HD + row) * SP + k0 + cc;
                CP16(base + 17408 + (uint32_t)(row * F_VST + cc) * 2, gv, 16);
            }
        }
        CP_COMMIT();
    };

    kv_stage(t_begin, 0);

    float m0s = -1e30f, m1s = -1e30f, l0s = 0.f, l1s = 0.f;
    float o[16][4];
    #pragma unroll
    for (int i = 0; i < 16; i++)
        #pragma unroll
        for (int j = 0; j < 4; j++) o[i][j] = 0.f;

    const int a_row = (lane & 15);
    const int a_col = ((lane >> 1) & 8);
    const int b_row = (lane & 7) + ((lane & 16) >> 1);
    const int b_col = (lane & 8);

    for (int lt = 0; lt < t_cnt; lt++) {
        const int gt = t_begin + lt;
        const int k0 = gt * 64;
        CP_WAIT0();
        __syncthreads();
        if (lt + 1 < t_cnt) kv_stage(gt + 1, (lt + 1) & 1);

        const uint32_t kb = sb + F_STG + (uint32_t)(lt & 1) * F_STGB;
        const uint32_t vb = kb + 17408;

        // ---- S = Q K^T (fp16, 1 pass) ----
        float c[8][4];
        #pragma unroll
        for (int nt = 0; nt < 8; nt++)
            #pragma unroll
            for (int j = 0; j < 4; j++) c[nt][j] = 0.f;

        #pragma unroll
        for (int kc8 = 0; kc8 < 8; kc8++) {
            const int kc = kc8 * 16;
            uint32_t aq[4], bk[8][2];
            ldsm4(aq[0], aq[1], aq[2], aq[3],
                  sb + F_Q + (uint32_t)((r0w + a_row) * F_QST + kc + a_col) * 2);
            #pragma unroll
            for (int np = 0; np < 4; np++) {
                uint32_t r0, r1, r2, r3;
                ldsm4(r0, r1, r2, r3,
                      kb + (uint32_t)((np * 16 + b_row) * F_QST + kc + b_col) * 2);
                bk[np*2][0] = r0; bk[np*2][1] = r1; bk[np*2+1][0] = r2; bk[np*2+1][1] = r3;
            }
            #pragma unroll
            for (int nt = 0; nt < 8; nt++)
                mma16816h(c[nt], aq, bk[nt]);
        }

        // ---- scale (log2 domain) + mask ----
        #pragma unroll
        for (int nt = 0; nt < 8; nt++) {
            int colb = k0 + nt * 8 + (lane & 3) * 2;
            #pragma unroll
            for (int j = 0; j < 4; j++) {
                float v = c[nt][j] * scale2;
                c[nt][j] = (colb + (j & 1) < seqlen) ? v : -1e30f;
            }
        }

        // ---- online softmax (exp2) ----
        float mx0 = -1e30f, mx1 = -1e30f;
        #pragma unroll
        for (int nt = 0; nt < 8; nt++) {
            mx0 = fmaxf(mx0, fmaxf(c[nt][0], c[nt][1]));
            mx1 = fmaxf(mx1, fmaxf(c[nt][2], c[nt][3]));
        }
        mx0 = fmaxf(mx0, __shfl_xor_sync(0xffffffffu, mx0, 1));
        mx0 = fmaxf(mx0, __shfl_xor_sync(0xffffffffu, mx0, 2));
        mx1 = fmaxf(mx1, __shfl_xor_sync(0xffffffffu, mx1, 1));
        mx1 = fmaxf(mx1, __shfl_xor_sync(0xffffffffu, mx1, 2));
        float mn0 = fmaxf(m0s, mx0), mn1 = fmaxf(m1s, mx1);
        float al0 = exp2f(m0s - mn0), al1 = exp2f(m1s - mn1);
        m0s = mn0; m1s = mn1;
        float ls0 = 0.f, ls1 = 0.f;
        #pragma unroll
        for (int nt = 0; nt < 8; nt++) {
            c[nt][0] = exp2f(c[nt][0] - mn0); ls0 += c[nt][0];
            c[nt][1] = exp2f(c[nt][1] - mn0); ls0 += c[nt][1];
            c[nt][2] = exp2f(c[nt][2] - mn1); ls1 += c[nt][2];
            c[nt][3] = exp2f(c[nt][3] - mn1); ls1 += c[nt][3];
        }
        ls0 += __shfl_xor_sync(0xffffffffu, ls0, 1);
        ls0 += __shfl_xor_sync(0xffffffffu, ls0, 2);
        ls1 += __shfl_xor_sync(0xffffffffu, ls1, 1);
        ls1 += __shfl_xor_sync(0xffffffffu, ls1, 2);
        l0s = l0s * al0 + ls0;
        l1s = l1s * al1 + ls1;

        // ---- pack P into fp16 A fragments ----
        uint32_t ph[4][4];
        #pragma unroll
        for (int kc2 = 0; kc2 < 4; kc2++) {
            ph[kc2][0] = pack_h2(c[2*kc2][0],   c[2*kc2][1]);
            ph[kc2][1] = pack_h2(c[2*kc2][2],   c[2*kc2][3]);
            ph[kc2][2] = pack_h2(c[2*kc2+1][0], c[2*kc2+1][1]);
            ph[kc2][3] = pack_h2(c[2*kc2+1][2], c[2*kc2+1][3]);
        }

        // ---- rescale O ----
        #pragma unroll
        for (int nt = 0; nt < 16; nt++) {
            o[nt][0] *= al0; o[nt][1] *= al0;
            o[nt][2] *= al1; o[nt][3] *= al1;
        }

        // ---- O += P V (fp16, 1 pass) ----
        #pragma unroll
        for (int kc2 = 0; kc2 < 4; kc2++) {
            #pragma unroll
            for (int np = 0; np < 8; np++) {
                uint32_t v0, v1, v2, v3;
                ldsm4(v0, v1, v2, v3,
                      vb + (uint32_t)((np * 16 + b_row) * F_VST + kc2 * 16 + b_col) * 2);
                uint32_t b0[2] = {v0, v1}, b1[2] = {v2, v3};
                mma16816h(o[2*np],   ph[kc2], b0);
                mma16816h(o[2*np+1], ph[kc2], b1);
            }
        }
    }

    // ---- write UNNORMALIZED partial + stats ----
    float* Op = (sp == 0) ? O0 : ((sp == 1) ? O1 : O2);
    const int rA = q0 + r0w + (lane >> 2);
    const int rB = rA + 8;
    #pragma unroll
    for (int nt = 0; nt < 16; nt++) {
        int col = h * HD + nt * 8 + (lane & 3) * 2;
        if (rA < S_TOT)
            *(float2*)&Op[(size_t)rA * DIM + col] = make_float2(o[nt][0], o[nt][1]);
        if (rB < S_TOT)
            *(float2*)&Op[(size_t)rB * DIM + col] = make_float2(o[nt][2], o[nt][3]);
    }
    if ((lane & 3) == 0) {
        if (rA < S_TOT) {
            stat[STATIDX(sp, h, 0, rA)] = m0s;
            stat[STATIDX(sp, h, 1, rA)] = l0s;
        }
        if (rB < S_TOT) {
            stat[STATIDX(sp, h, 0, rB)] = m1s;
            stat[STATIDX(sp, h, 1, rB)] = l1s;
        }
    }
}

// ================= combine split-KV partials (3-way) -> fp16 =================
__global__ __launch_bounds__(128)
void combine_kernel(const float* __restrict__ O0, const float* __restrict__ O1,
                    const float* __restrict__ O2, const float* __restrict__ stat,
                    __half* __restrict__ AO16) {
    const int s = blockIdx.x;
    const int h = blockIdx.y;
    const int c = threadIdx.x;
    float mA = stat[STATIDX(0, h, 0, s)], lA = stat[STATIDX(0, h, 1, s)];
    float mB = stat[STATIDX(1, h, 0, s)], lB = stat[STATIDX(1, h, 1, s)];
    float mC = stat[STATIDX(2, h, 0, s)], lC = stat[STATIDX(2, h, 1, s)];
    float m = fmaxf(fmaxf(mA, mB), mC);
    float aA = exp2f(mA - m), aB = exp2f(mB - m), aC = exp2f(mC - m);
    float inv = 1.f / (lA * aA + lB * aB + lC * aC);
    size_t idx = (size_t)s * DIM + h * HD + c;
    float o = (O0[idx] * aA + O1[idx] * aB + O2[idx] * aC) * inv;
    AO16[idx] = __float2half_rn(o);
}

// ---------------- launch ----------------
extern "C" void kernel_launch(void* const* d_in, const int* in_sizes, int n_in,
                              void* d_out, int out_size) {
    const float* x        = (const float*)d_in[0];
    const int*   seq_lens = (const int*)  d_in[1];
    const int*   grid_sz  = (const int*)  d_in[2];
    const float* freqs    = (const float*)d_in[3];
    const float* Wq       = (const float*)d_in[4];
    const float* bq       = (const float*)d_in[5];
    const float* Wk       = (const float*)d_in[6];
    const float* bk       = (const float*)d_in[7];
    const float* Wv       = (const float*)d_in[8];
    const float* bv       = (const float*)d_in[9];
    const float* Wo       = (const float*)d_in[10];
    const float* bo       = (const float*)d_in[11];
    const float* gq       = (const float*)d_in[12];
    const float* gk       = (const float*)d_in[13];
    float* out = (float*)d_out;

    float *q, *k, *o2, *stat;
    __half *x16, *q16, *k16, *ao16, *vt16;
    __half *w16q, *w16k, *w16v, *w16o;
    cudaGetSymbolAddress((void**)&q, g_q);
    cudaGetSymbolAddress((void**)&k, g_k);
    cudaGetSymbolAddress((void**)&o2, g_o2);
    cudaGetSymbolAddress((void**)&stat, g_stat);
    cudaGetSymbolAddress((void**)&x16, g_x16);
    cudaGetSymbolAddress((void**)&q16, g_q16);
    cudaGetSymbolAddress((void**)&k16, g_k16);
    cudaGetSymbolAddress((void**)&ao16, g_ao16);
    cudaGetSymbolAddress((void**)&vt16, g_vt16);
    cudaGetSymbolAddress((void**)&w16q, g_w16q);
    cudaGetSymbolAddress((void**)&w16k, g_w16k);
    cudaGetSymbolAddress((void**)&w16v, g_w16v);
    cudaGetSymbolAddress((void**)&w16o, g_w16o);

    cudaFuncSetAttribute(gemm_mma, cudaFuncAttributeMaxDynamicSharedMemorySize, G_SMEM);
    cudaFuncSetAttribute(flash_mma, cudaFuncAttributeMaxDynamicSharedMemorySize, F_SMEM);

    // prep
    convert_x_kernel<<<S_TOT * DIM / 4 / 256, 256>>>(x, x16);
    WPtrs wp;
    wp.w[0] = Wq; wp.t16[0] = w16q;
    wp.w[1] = Wk; wp.t16[1] = w16k;
    wp.w[2] = Wv; wp.t16[2] = w16v;
    wp.w[3] = Wo; wp.t16[3] = w16o;
    transw_kernel<<<dim3(48, 48, 4), dim3(32, 8)>>>(wp);

    // fused QKV projection; V written directly as transposed fp16
    QKVArgs aqkv;
    aqkv.b16[0] = w16q; aqkv.bias[0] = bq; aqkv.c[0] = q;
    aqkv.b16[1] = w16k; aqkv.bias[1] = bk; aqkv.c[1] = k;
    aqkv.b16[2] = w16v; aqkv.bias[2] = bv; aqkv.c[2] = nullptr;
    aqkv.vt16 = vt16;
    gemm_mma<<<dim3(36, 31), 256, G_SMEM>>>(x16, aqkv, S_TOT, 0);

    rmsnorm_rope_conv<<<dim3(S_TOT, 2), 256>>>(q, gq, q16, k, gk, k16, freqs, grid_sz);

    // 3-way split-KV flash: partials into g_q, g_k, g_o2 (all free now)
    dim3 fg(31, NH, NSPLIT);
    flash_mma<<<fg, 256, F_SMEM>>>(q16, k16, vt16, q, k, o2, stat, seq_lens);
    combine_kernel<<<dim3(S_TOT, NH), 128>>>(q, k, o2, stat, ao16);

    // O projection: split-K=3 into fp32 partials, then add+bias
    QKVArgs aop;
    aop.b16[0] = w16o; aop.bias[0] = nullptr; aop.c[0] = q;
    aop.b16[1] = w16o; aop.bias[1] = nullptr; aop.c[1] = k;
    aop.b16[2] = w16o; aop.bias[2] = nullptr; aop.c[2] = o2;
    aop.vt16 = nullptr;
    gemm_mma<<<dim3(12, 31, 3), 256, G_SMEM>>>(ao16, aop, S_TOT, 1);
    addbias_kernel<<<S_TOT * DIM / 4 / 256, 256>>>(q, k, o2, bo, out);
}